// round 1
// baseline (speedup 1.0000x reference)
#include <cuda_runtime.h>
#include <math.h>

#define Nn 512
#define Dd 128
#define Df 256
#define Hh 8
#define Dh 16
#define ROWS (Nn*Nn)

// ---------------- device scratch (no allocs allowed) ----------------
__device__ float sc_mem[(size_t)ROWS * Dd];   // memory [i,j,c]      (134 MB)
__device__ float sc_K[(size_t)ROWS * Dd];     // K transposed [j,i,c]
__device__ float sc_V[(size_t)ROWS * Dd];     // V transposed [j,i,c]
__device__ float sc_S[Nn * Dd];               // node[j] @ W_mem[128:256]
__device__ float sc_T[Nn * Dd];               // node[i] @ W_mem[256:384]
__device__ float sc_q[Nn * Dd];               // node @ Wq + bq
__device__ float sc_o[Nn * Dd];               // attention output (pre out-proj)

// ---------------- helpers ----------------
__device__ __forceinline__ float red16(float v) {
    v += __shfl_xor_sync(0xffffffffu, v, 1);
    v += __shfl_xor_sync(0xffffffffu, v, 2);
    v += __shfl_xor_sync(0xffffffffu, v, 4);
    v += __shfl_xor_sync(0xffffffffu, v, 8);
    return v;
}

// 64-row x 128-col tile GEMM, K=128 chunked by 32. 256 threads, 4x8 micro-tile.
// thread (tx,ty), tx=tid&15, ty=tid>>4. cols: tx*4+{0..3} and 64+tx*4+{0..3}.
__device__ __forceinline__ void gemm_tile(const float* __restrict__ A,
                                          const float* __restrict__ W,
                                          float acc[4][8]) {
    __shared__ float As[64 * 33];
    __shared__ float Ws[32 * 128];
    const int tid = threadIdx.x;
    const int tx = tid & 15, ty = tid >> 4;
    const size_t r0 = (size_t)blockIdx.x * 64;

#pragma unroll
    for (int r = 0; r < 4; ++r)
#pragma unroll
        for (int j = 0; j < 8; ++j) acc[r][j] = 0.f;

#pragma unroll
    for (int kk = 0; kk < 4; ++kk) {
        // A chunk: 64 rows x 32 cols
#pragma unroll
        for (int it = 0; it < 2; ++it) {
            int idx = it * 256 + tid;           // 512 float4s
            int row = idx >> 3;
            int c4 = (idx & 7) << 2;
            float4 v = *reinterpret_cast<const float4*>(&A[(r0 + row) * Dd + kk * 32 + c4]);
            float* d = &As[row * 33 + c4];
            d[0] = v.x; d[1] = v.y; d[2] = v.z; d[3] = v.w;
        }
        // W chunk: 32 rows x 128 cols
#pragma unroll
        for (int it = 0; it < 4; ++it) {
            int idx = it * 256 + tid;           // 1024 float4s
            int kr = idx >> 5;
            int c4 = (idx & 31) << 2;
            *reinterpret_cast<float4*>(&Ws[kr * 128 + c4]) =
                *reinterpret_cast<const float4*>(&W[(size_t)(kk * 32 + kr) * Dd + c4]);
        }
        __syncthreads();
#pragma unroll
        for (int k = 0; k < 32; ++k) {
            float aa[4];
            aa[0] = As[(ty * 4 + 0) * 33 + k];
            aa[1] = As[(ty * 4 + 1) * 33 + k];
            aa[2] = As[(ty * 4 + 2) * 33 + k];
            aa[3] = As[(ty * 4 + 3) * 33 + k];
            float4 b0 = *reinterpret_cast<const float4*>(&Ws[k * 128 + tx * 4]);
            float4 b1 = *reinterpret_cast<const float4*>(&Ws[k * 128 + 64 + tx * 4]);
            float bb[8] = {b0.x, b0.y, b0.z, b0.w, b1.x, b1.y, b1.z, b1.w};
#pragma unroll
            for (int r = 0; r < 4; ++r)
#pragma unroll
                for (int j = 0; j < 8; ++j)
                    acc[r][j] = fmaf(aa[r], bb[j], acc[r][j]);
        }
        __syncthreads();
    }
}

// ---------------- K1: S, T, q precompute ----------------
__global__ void k_small(const float* __restrict__ node,
                        const float* __restrict__ Wmem,
                        const float* __restrict__ Wq,
                        const float* __restrict__ bq) {
    int n = blockIdx.x;
    int c = threadIdx.x;
    __shared__ float ns[Dd];
    ns[c] = node[n * Dd + c];
    __syncthreads();
    float s = 0.f, t = 0.f, q = 0.f;
#pragma unroll 8
    for (int k = 0; k < Dd; ++k) {
        float nv = ns[k];
        s = fmaf(nv, Wmem[(Dd + k) * Dd + c], s);
        t = fmaf(nv, Wmem[(2 * Dd + k) * Dd + c], t);
        q = fmaf(nv, Wq[k * Dd + c], q);
    }
    sc_S[n * Dd + c] = s;
    sc_T[n * Dd + c] = t;
    sc_q[n * Dd + c] = q + bq[c];
}

// ---------------- K2: memory = relu(LN(edge@Wm_e + S[j] + T[i] + b)) ----------------
__global__ void k_mem(const float* __restrict__ edge,
                      const float* __restrict__ Wmem,   // rows 0..127 = edge part
                      const float* __restrict__ bmem,
                      const float* __restrict__ gm,
                      const float* __restrict__ bem) {
    float acc[4][8];
    gemm_tile(edge, Wmem, acc);

    const int tid = threadIdx.x;
    const int tx = tid & 15, ty = tid >> 4;
    const size_t r0 = (size_t)blockIdx.x * 64;

    int cols[8];
#pragma unroll
    for (int j = 0; j < 4; ++j) { cols[j] = tx * 4 + j; cols[4 + j] = 64 + tx * 4 + j; }
    float bj[8], gj[8], bej[8];
#pragma unroll
    for (int j = 0; j < 8; ++j) { bj[j] = bmem[cols[j]]; gj[j] = gm[cols[j]]; bej[j] = bem[cols[j]]; }

#pragma unroll
    for (int rr = 0; rr < 4; ++rr) {
        size_t gr = r0 + ty * 4 + rr;
        int i = (int)(gr >> 9);
        int jn = (int)(gr & 511);
        float v[8];
#pragma unroll
        for (int j = 0; j < 8; ++j)
            v[j] = acc[rr][j] + bj[j] + sc_S[jn * Dd + cols[j]] + sc_T[i * Dd + cols[j]];
        float s = 0.f;
#pragma unroll
        for (int j = 0; j < 8; ++j) s += v[j];
        s = red16(s);
        float mean = s * (1.f / 128.f);
        float s2 = 0.f;
#pragma unroll
        for (int j = 0; j < 8; ++j) { float d = v[j] - mean; s2 = fmaf(d, d, s2); }
        s2 = red16(s2);
        float rstd = rsqrtf(s2 * (1.f / 128.f) + 1e-5f);
#pragma unroll
        for (int j = 0; j < 8; ++j) {
            float x = (v[j] - mean) * rstd * gj[j] + bej[j];
            sc_mem[gr * Dd + cols[j]] = fmaxf(x, 0.f);
        }
    }
}

// ---------------- K3: edge_out = LN(edge + relu(LN(memory@W_e + b_e))) ----------------
__global__ void k_edge(const float* __restrict__ edge,
                       const float* __restrict__ We,
                       const float* __restrict__ be_b,
                       const float* __restrict__ g1,
                       const float* __restrict__ be1,
                       const float* __restrict__ g2,
                       const float* __restrict__ be2,
                       float* __restrict__ out_edge) {
    float acc[4][8];
    gemm_tile(sc_mem, We, acc);

    const int tid = threadIdx.x;
    const int tx = tid & 15, ty = tid >> 4;
    const size_t r0 = (size_t)blockIdx.x * 64;

    int cols[8];
#pragma unroll
    for (int j = 0; j < 4; ++j) { cols[j] = tx * 4 + j; cols[4 + j] = 64 + tx * 4 + j; }
    float bj[8], g1j[8], be1j[8], g2j[8], be2j[8];
#pragma unroll
    for (int j = 0; j < 8; ++j) {
        bj[j] = be_b[cols[j]];
        g1j[j] = g1[cols[j]]; be1j[j] = be1[cols[j]];
        g2j[j] = g2[cols[j]]; be2j[j] = be2[cols[j]];
    }

#pragma unroll
    for (int rr = 0; rr < 4; ++rr) {
        size_t gr = r0 + ty * 4 + rr;
        float v[8];
#pragma unroll
        for (int j = 0; j < 8; ++j) v[j] = acc[rr][j] + bj[j];
        // LN1
        float s = 0.f;
#pragma unroll
        for (int j = 0; j < 8; ++j) s += v[j];
        s = red16(s);
        float mean = s * (1.f / 128.f);
        float s2 = 0.f;
#pragma unroll
        for (int j = 0; j < 8; ++j) { float d = v[j] - mean; s2 = fmaf(d, d, s2); }
        s2 = red16(s2);
        float rstd = rsqrtf(s2 * (1.f / 128.f) + 1e-5f);
        float w[8];
#pragma unroll
        for (int j = 0; j < 8; ++j) {
            float u = (v[j] - mean) * rstd * g1j[j] + be1j[j];
            u = fmaxf(u, 0.f);
            w[j] = edge[gr * Dd + cols[j]] + u;
        }
        // LN2
        s = 0.f;
#pragma unroll
        for (int j = 0; j < 8; ++j) s += w[j];
        s = red16(s);
        mean = s * (1.f / 128.f);
        s2 = 0.f;
#pragma unroll
        for (int j = 0; j < 8; ++j) { float d = w[j] - mean; s2 = fmaf(d, d, s2); }
        s2 = red16(s2);
        rstd = rsqrtf(s2 * (1.f / 128.f) + 1e-5f);
#pragma unroll
        for (int j = 0; j < 8; ++j)
            out_edge[gr * Dd + cols[j]] = (w[j] - mean) * rstd * g2j[j] + be2j[j];
    }
}

// ---------------- K4/K5: K = memory@Wk+bk, V = memory@Wv+bv (batch-major transposed) ----------------
__global__ void k_kv(const float* __restrict__ W,
                     const float* __restrict__ bias,
                     int toV) {
    float acc[4][8];
    gemm_tile(sc_mem, W, acc);

    const int tid = threadIdx.x;
    const int tx = tid & 15, ty = tid >> 4;
    const size_t r0 = (size_t)blockIdx.x * 64;
    float* outp = toV ? sc_V : sc_K;

    int cols[8];
#pragma unroll
    for (int j = 0; j < 4; ++j) { cols[j] = tx * 4 + j; cols[4 + j] = 64 + tx * 4 + j; }
    float bj[8];
#pragma unroll
    for (int j = 0; j < 8; ++j) bj[j] = bias[cols[j]];

#pragma unroll
    for (int rr = 0; rr < 4; ++rr) {
        size_t gr = r0 + ty * 4 + rr;
        int i = (int)(gr >> 9);
        int jn = (int)(gr & 511);
        size_t ob = ((size_t)jn * Nn + i) * Dd;   // [batch jn][m=i][c]
#pragma unroll
        for (int j = 0; j < 8; ++j)
            outp[ob + cols[j]] = acc[rr][j] + bj[j];
    }
}

// ---------------- K6: attention per batch n ----------------
__global__ void k_attn(const unsigned char* __restrict__ mask) {
    const int n = blockIdx.x;
    const int tid = threadIdx.x;
    const int w = tid >> 5, lane = tid & 31;

    __shared__ float q_s[Dd];
    __shared__ float sc[Hh * Nn];      // scores [h][m]  (16 KB)
    __shared__ float red2[256];

    if (tid < Dd) q_s[tid] = sc_q[n * Dd + tid];
    __syncthreads();

    // Phase 1: scores
    float4 qv = *reinterpret_cast<const float4*>(&q_s[lane * 4]);
    for (int m = w; m < Nn; m += 8) {
        const float* kp = &sc_K[((size_t)n * Nn + m) * Dd];
        float4 kd = *reinterpret_cast<const float4*>(&kp[lane * 4]);
        float p = qv.x * kd.x + qv.y * kd.y + qv.z * kd.z + qv.w * kd.w;
        p += __shfl_xor_sync(0xffffffffu, p, 1);
        p += __shfl_xor_sync(0xffffffffu, p, 2);
        if ((lane & 3) == 0) {
            int h = lane >> 2;
            sc[h * Nn + m] = mask[n * Nn + m] ? -INFINITY : p * 0.25f;
        }
    }
    __syncthreads();

    // Phase 2: softmax per head (warp w handles head w)
    {
        int h = w;
        float mx = -INFINITY;
#pragma unroll
        for (int t = 0; t < 16; ++t) mx = fmaxf(mx, sc[h * Nn + lane + t * 32]);
#pragma unroll
        for (int off = 16; off >= 1; off >>= 1)
            mx = fmaxf(mx, __shfl_xor_sync(0xffffffffu, mx, off));
        float sum = 0.f;
#pragma unroll
        for (int t = 0; t < 16; ++t) {
            float e = __expf(sc[h * Nn + lane + t * 32] - mx);
            sc[h * Nn + lane + t * 32] = e;
            sum += e;
        }
#pragma unroll
        for (int off = 16; off >= 1; off >>= 1)
            sum += __shfl_xor_sync(0xffffffffu, sum, off);
        float inv = 1.f / sum;
#pragma unroll
        for (int t = 0; t < 16; ++t) sc[h * Nn + lane + t * 32] *= inv;
    }
    __syncthreads();

    // Phase 3: o[c] = sum_m attn[h(c)][m] * V[n][m][c], split m-range over 2 halves
    {
        int c = tid & 127;
        int half = tid >> 7;
        int h = c >> 4;
        const float* vb = &sc_V[((size_t)n * Nn + half * 256) * Dd + c];
        const float* ap = &sc[h * Nn + half * 256];
        float acc = 0.f;
#pragma unroll 4
        for (int m = 0; m < 256; ++m)
            acc = fmaf(ap[m], vb[(size_t)m * Dd], acc);
        red2[tid] = acc;
        __syncthreads();
        if (tid < 128)
            sc_o[n * Dd + tid] = red2[tid] + red2[tid + 128];
    }
}

// ---------------- K7: out-proj + LN + FFN + LN ----------------
__device__ __forceinline__ float bsum128(float v, float* tmp) {
    int lane = threadIdx.x & 31, wid = threadIdx.x >> 5;
#pragma unroll
    for (int off = 16; off >= 1; off >>= 1)
        v += __shfl_xor_sync(0xffffffffu, v, off);
    if (lane == 0) tmp[wid] = v;
    __syncthreads();
    float s = tmp[0] + tmp[1] + tmp[2] + tmp[3];
    __syncthreads();
    return s;
}

__global__ void k_final(const float* __restrict__ node,
                        const float* __restrict__ Wo, const float* __restrict__ bo,
                        const float* __restrict__ g2, const float* __restrict__ be2,
                        const float* __restrict__ W1, const float* __restrict__ b1,
                        const float* __restrict__ W2, const float* __restrict__ b2,
                        const float* __restrict__ g3, const float* __restrict__ be3,
                        float* __restrict__ out_x) {
    const int n = blockIdx.x;
    const int c = threadIdx.x;   // 128 threads
    __shared__ float os[Dd], xs[Dd], hs[Df], tmp[4];

    os[c] = sc_o[n * Dd + c];
    __syncthreads();

    float t = bo[c];
#pragma unroll 8
    for (int k = 0; k < Dd; ++k) t = fmaf(os[k], Wo[k * Dd + c], t);
    float x = node[n * Dd + c] + t;

    float mean = bsum128(x, tmp) * (1.f / 128.f);
    float d = x - mean;
    float var = bsum128(d * d, tmp) * (1.f / 128.f);
    float xn = d * rsqrtf(var + 1e-5f) * g2[c] + be2[c];
    xs[c] = xn;
    __syncthreads();

    float h0 = b1[c], h1 = b1[c + 128];
#pragma unroll 8
    for (int k = 0; k < Dd; ++k) {
        float xv = xs[k];
        h0 = fmaf(xv, W1[k * Df + c], h0);
        h1 = fmaf(xv, W1[k * Df + c + 128], h1);
    }
    hs[c] = fmaxf(h0, 0.f);
    hs[c + 128] = fmaxf(h1, 0.f);
    __syncthreads();

    float y = b2[c];
#pragma unroll 8
    for (int f = 0; f < Df; ++f) y = fmaf(hs[f], W2[f * Dd + c], y);
    float z = xn + y;

    mean = bsum128(z, tmp) * (1.f / 128.f);
    d = z - mean;
    var = bsum128(d * d, tmp) * (1.f / 128.f);
    out_x[n * Dd + c] = d * rsqrtf(var + 1e-5f) * g3[c] + be3[c];
}

// ---------------- host launcher ----------------
extern "C" void kernel_launch(void* const* d_in, const int* in_sizes, int n_in,
                              void* d_out, int out_size) {
    const float* node   = (const float*)d_in[0];
    const float* edge   = (const float*)d_in[1];
    const unsigned char* mask = (const unsigned char*)d_in[2];
    const float* W_mem  = (const float*)d_in[3];
    const float* b_mem  = (const float*)d_in[4];
    const float* g_mem  = (const float*)d_in[5];
    const float* be_mem = (const float*)d_in[6];
    const float* W_e    = (const float*)d_in[7];
    const float* b_e    = (const float*)d_in[8];
    const float* g_e1   = (const float*)d_in[9];
    const float* be_e1  = (const float*)d_in[10];
    const float* g_e2   = (const float*)d_in[11];
    const float* be_e2  = (const float*)d_in[12];
    const float* Wq     = (const float*)d_in[13];
    const float* bq     = (const float*)d_in[14];
    const float* Wk     = (const float*)d_in[15];
    const float* bk     = (const float*)d_in[16];
    const float* Wv     = (const float*)d_in[17];
    const float* bv     = (const float*)d_in[18];
    const float* Wo     = (const float*)d_in[19];
    const float* bo     = (const float*)d_in[20];
    const float* W1     = (const float*)d_in[21];
    const float* b1     = (const float*)d_in[22];
    const float* W2     = (const float*)d_in[23];
    const float* b2     = (const float*)d_in[24];
    const float* g2     = (const float*)d_in[25];
    const float* be2    = (const float*)d_in[26];
    const float* g3     = (const float*)d_in[27];
    const float* be3    = (const float*)d_in[28];

    float* out = (float*)d_out;
    float* out_x = out;                    // [512,128]
    float* out_edge = out + Nn * Dd;       // [512,512,128]

    k_small<<<Nn, Dd>>>(node, W_mem, Wq, bq);
    k_mem<<<ROWS / 64, 256>>>(edge, W_mem, b_mem, g_mem, be_mem);
    k_edge<<<ROWS / 64, 256>>>(edge, W_e, b_e, g_e1, be_e1, g_e2, be_e2, out_edge);
    k_kv<<<ROWS / 64, 256>>>(Wk, bk, 0);
    k_kv<<<ROWS / 64, 256>>>(Wv, bv, 1);
    k_attn<<<Nn, 256>>>(mask);
    k_final<<<Nn, 128>>>(node, Wo, bo, g2, be2, W1, b1, W2, b2, g3, be3, out_x);
}

// round 2
// speedup vs baseline: 1.0067x; 1.0067x over previous
#include <cuda_runtime.h>
#include <math.h>

#define Nn 512
#define Dd 128
#define Df 256
#define Hh 8
#define Dh 16
#define ROWS (Nn*Nn)

// ---------------- device scratch (no allocs allowed) ----------------
__device__ float sc_mem[(size_t)ROWS * Dd];   // memory [i,j,c]      (134 MB)
__device__ float sc_K[(size_t)ROWS * Dd];     // K transposed [j,i,c]
__device__ float sc_V[(size_t)ROWS * Dd];     // V transposed [j,i,c]
__device__ float sc_S[Nn * Dd];               // node[j] @ W_mem[128:256]
__device__ float sc_T[Nn * Dd];               // node[i] @ W_mem[256:384]
__device__ float sc_q[Nn * Dd];               // node @ Wq + bq
__device__ float sc_o[Nn * Dd];               // attention output (pre out-proj)

// ---------------- helpers ----------------
__device__ __forceinline__ float red16(float v) {
    v += __shfl_xor_sync(0xffffffffu, v, 1);
    v += __shfl_xor_sync(0xffffffffu, v, 2);
    v += __shfl_xor_sync(0xffffffffu, v, 4);
    v += __shfl_xor_sync(0xffffffffu, v, 8);
    return v;
}

// 64-row x 128-col tile GEMM, K=128 chunked by 32. 256 threads, 4x8 micro-tile.
// thread (tx,ty), tx=tid&15, ty=tid>>4. cols: tx*4+{0..3} and 64+tx*4+{0..3}.
__device__ __forceinline__ void gemm_tile(const float* __restrict__ A,
                                          const float* __restrict__ W,
                                          float acc[4][8]) {
    __shared__ float As[64 * 33];
    __shared__ float Ws[32 * 128];
    const int tid = threadIdx.x;
    const int tx = tid & 15, ty = tid >> 4;
    const size_t r0 = (size_t)blockIdx.x * 64;

#pragma unroll
    for (int r = 0; r < 4; ++r)
#pragma unroll
        for (int j = 0; j < 8; ++j) acc[r][j] = 0.f;

#pragma unroll
    for (int kk = 0; kk < 4; ++kk) {
        // A chunk: 64 rows x 32 cols
#pragma unroll
        for (int it = 0; it < 2; ++it) {
            int idx = it * 256 + tid;           // 512 float4s
            int row = idx >> 3;
            int c4 = (idx & 7) << 2;
            float4 v = *reinterpret_cast<const float4*>(&A[(r0 + row) * Dd + kk * 32 + c4]);
            float* d = &As[row * 33 + c4];
            d[0] = v.x; d[1] = v.y; d[2] = v.z; d[3] = v.w;
        }
        // W chunk: 32 rows x 128 cols
#pragma unroll
        for (int it = 0; it < 4; ++it) {
            int idx = it * 256 + tid;           // 1024 float4s
            int kr = idx >> 5;
            int c4 = (idx & 31) << 2;
            *reinterpret_cast<float4*>(&Ws[kr * 128 + c4]) =
                *reinterpret_cast<const float4*>(&W[(size_t)(kk * 32 + kr) * Dd + c4]);
        }
        __syncthreads();
#pragma unroll
        for (int k = 0; k < 32; ++k) {
            float aa[4];
            aa[0] = As[(ty * 4 + 0) * 33 + k];
            aa[1] = As[(ty * 4 + 1) * 33 + k];
            aa[2] = As[(ty * 4 + 2) * 33 + k];
            aa[3] = As[(ty * 4 + 3) * 33 + k];
            float4 b0 = *reinterpret_cast<const float4*>(&Ws[k * 128 + tx * 4]);
            float4 b1 = *reinterpret_cast<const float4*>(&Ws[k * 128 + 64 + tx * 4]);
            float bb[8] = {b0.x, b0.y, b0.z, b0.w, b1.x, b1.y, b1.z, b1.w};
#pragma unroll
            for (int r = 0; r < 4; ++r)
#pragma unroll
                for (int j = 0; j < 8; ++j)
                    acc[r][j] = fmaf(aa[r], bb[j], acc[r][j]);
        }
        __syncthreads();
    }
}

// ---------------- K1: S, T, q precompute ----------------
__global__ void k_small(const float* __restrict__ node,
                        const float* __restrict__ Wmem,
                        const float* __restrict__ Wq,
                        const float* __restrict__ bq) {
    int n = blockIdx.x;
    int c = threadIdx.x;
    __shared__ float ns[Dd];
    ns[c] = node[n * Dd + c];
    __syncthreads();
    float s = 0.f, t = 0.f, q = 0.f;
#pragma unroll 8
    for (int k = 0; k < Dd; ++k) {
        float nv = ns[k];
        s = fmaf(nv, Wmem[(Dd + k) * Dd + c], s);
        t = fmaf(nv, Wmem[(2 * Dd + k) * Dd + c], t);
        q = fmaf(nv, Wq[k * Dd + c], q);
    }
    sc_S[n * Dd + c] = s;
    sc_T[n * Dd + c] = t;
    sc_q[n * Dd + c] = q + bq[c];
}

// ---------------- K2: memory = relu(LN(edge@Wm_e + S[j] + T[i] + b)) ----------------
__global__ void k_mem(const float* __restrict__ edge,
                      const float* __restrict__ Wmem,   // rows 0..127 = edge part
                      const float* __restrict__ bmem,
                      const float* __restrict__ gm,
                      const float* __restrict__ bem) {
    float acc[4][8];
    gemm_tile(edge, Wmem, acc);

    const int tid = threadIdx.x;
    const int tx = tid & 15, ty = tid >> 4;
    const size_t r0 = (size_t)blockIdx.x * 64;

    int cols[8];
#pragma unroll
    for (int j = 0; j < 4; ++j) { cols[j] = tx * 4 + j; cols[4 + j] = 64 + tx * 4 + j; }
    float bj[8], gj[8], bej[8];
#pragma unroll
    for (int j = 0; j < 8; ++j) { bj[j] = bmem[cols[j]]; gj[j] = gm[cols[j]]; bej[j] = bem[cols[j]]; }

#pragma unroll
    for (int rr = 0; rr < 4; ++rr) {
        size_t gr = r0 + ty * 4 + rr;
        int i = (int)(gr >> 9);
        int jn = (int)(gr & 511);
        float v[8];
#pragma unroll
        for (int j = 0; j < 8; ++j)
            v[j] = acc[rr][j] + bj[j] + sc_S[jn * Dd + cols[j]] + sc_T[i * Dd + cols[j]];
        float s = 0.f;
#pragma unroll
        for (int j = 0; j < 8; ++j) s += v[j];
        s = red16(s);
        float mean = s * (1.f / 128.f);
        float s2 = 0.f;
#pragma unroll
        for (int j = 0; j < 8; ++j) { float d = v[j] - mean; s2 = fmaf(d, d, s2); }
        s2 = red16(s2);
        float rstd = rsqrtf(s2 * (1.f / 128.f) + 1e-5f);
#pragma unroll
        for (int j = 0; j < 8; ++j) {
            float x = (v[j] - mean) * rstd * gj[j] + bej[j];
            sc_mem[gr * Dd + cols[j]] = fmaxf(x, 0.f);
        }
    }
}

// ---------------- K3: edge_out = LN(edge + relu(LN(memory@W_e + b_e))) ----------------
__global__ void k_edge(const float* __restrict__ edge,
                       const float* __restrict__ We,
                       const float* __restrict__ be_b,
                       const float* __restrict__ g1,
                       const float* __restrict__ be1,
                       const float* __restrict__ g2,
                       const float* __restrict__ be2,
                       float* __restrict__ out_edge) {
    float acc[4][8];
    gemm_tile(sc_mem, We, acc);

    const int tid = threadIdx.x;
    const int tx = tid & 15, ty = tid >> 4;
    const size_t r0 = (size_t)blockIdx.x * 64;

    int cols[8];
#pragma unroll
    for (int j = 0; j < 4; ++j) { cols[j] = tx * 4 + j; cols[4 + j] = 64 + tx * 4 + j; }
    float bj[8], g1j[8], be1j[8], g2j[8], be2j[8];
#pragma unroll
    for (int j = 0; j < 8; ++j) {
        bj[j] = be_b[cols[j]];
        g1j[j] = g1[cols[j]]; be1j[j] = be1[cols[j]];
        g2j[j] = g2[cols[j]]; be2j[j] = be2[cols[j]];
    }

#pragma unroll
    for (int rr = 0; rr < 4; ++rr) {
        size_t gr = r0 + ty * 4 + rr;
        float v[8];
#pragma unroll
        for (int j = 0; j < 8; ++j) v[j] = acc[rr][j] + bj[j];
        // LN1
        float s = 0.f;
#pragma unroll
        for (int j = 0; j < 8; ++j) s += v[j];
        s = red16(s);
        float mean = s * (1.f / 128.f);
        float s2 = 0.f;
#pragma unroll
        for (int j = 0; j < 8; ++j) { float d = v[j] - mean; s2 = fmaf(d, d, s2); }
        s2 = red16(s2);
        float rstd = rsqrtf(s2 * (1.f / 128.f) + 1e-5f);
        float w[8];
#pragma unroll
        for (int j = 0; j < 8; ++j) {
            float u = (v[j] - mean) * rstd * g1j[j] + be1j[j];
            u = fmaxf(u, 0.f);
            w[j] = edge[gr * Dd + cols[j]] + u;
        }
        // LN2
        s = 0.f;
#pragma unroll
        for (int j = 0; j < 8; ++j) s += w[j];
        s = red16(s);
        mean = s * (1.f / 128.f);
        s2 = 0.f;
#pragma unroll
        for (int j = 0; j < 8; ++j) { float d = w[j] - mean; s2 = fmaf(d, d, s2); }
        s2 = red16(s2);
        rstd = rsqrtf(s2 * (1.f / 128.f) + 1e-5f);
#pragma unroll
        for (int j = 0; j < 8; ++j)
            out_edge[gr * Dd + cols[j]] = (w[j] - mean) * rstd * g2j[j] + be2j[j];
    }
}

// ---------------- K4/K5: K = memory@Wk+bk, V = memory@Wv+bv (batch-major transposed) ----------------
__global__ void k_kv(const float* __restrict__ W,
                     const float* __restrict__ bias,
                     int toV) {
    float acc[4][8];
    gemm_tile(sc_mem, W, acc);

    const int tid = threadIdx.x;
    const int tx = tid & 15, ty = tid >> 4;
    const size_t r0 = (size_t)blockIdx.x * 64;
    float* outp = toV ? sc_V : sc_K;

    int cols[8];
#pragma unroll
    for (int j = 0; j < 4; ++j) { cols[j] = tx * 4 + j; cols[4 + j] = 64 + tx * 4 + j; }
    float bj[8];
#pragma unroll
    for (int j = 0; j < 8; ++j) bj[j] = bias[cols[j]];

#pragma unroll
    for (int rr = 0; rr < 4; ++rr) {
        size_t gr = r0 + ty * 4 + rr;
        int i = (int)(gr >> 9);
        int jn = (int)(gr & 511);
        size_t ob = ((size_t)jn * Nn + i) * Dd;   // [batch jn][m=i][c]
#pragma unroll
        for (int j = 0; j < 8; ++j)
            outp[ob + cols[j]] = acc[rr][j] + bj[j];
    }
}

// ---------------- K6: attention per batch n ----------------
__global__ void k_attn(const unsigned char* __restrict__ mask) {
    const int n = blockIdx.x;
    const int tid = threadIdx.x;
    const int w = tid >> 5, lane = tid & 31;

    __shared__ float q_s[Dd];
    __shared__ float sc[Hh * Nn];      // scores [h][m]  (16 KB)
    __shared__ float red2[256];

    if (tid < Dd) q_s[tid] = sc_q[n * Dd + tid];
    __syncthreads();

    // Phase 1: scores
    float4 qv = *reinterpret_cast<const float4*>(&q_s[lane * 4]);
    for (int m = w; m < Nn; m += 8) {
        const float* kp = &sc_K[((size_t)n * Nn + m) * Dd];
        float4 kd = *reinterpret_cast<const float4*>(&kp[lane * 4]);
        float p = qv.x * kd.x + qv.y * kd.y + qv.z * kd.z + qv.w * kd.w;
        p += __shfl_xor_sync(0xffffffffu, p, 1);
        p += __shfl_xor_sync(0xffffffffu, p, 2);
        if ((lane & 3) == 0) {
            int h = lane >> 2;
            sc[h * Nn + m] = mask[n * Nn + m] ? -INFINITY : p * 0.25f;
        }
    }
    __syncthreads();

    // Phase 2: softmax per head (warp w handles head w)
    {
        int h = w;
        float mx = -INFINITY;
#pragma unroll
        for (int t = 0; t < 16; ++t) mx = fmaxf(mx, sc[h * Nn + lane + t * 32]);
#pragma unroll
        for (int off = 16; off >= 1; off >>= 1)
            mx = fmaxf(mx, __shfl_xor_sync(0xffffffffu, mx, off));
        float sum = 0.f;
#pragma unroll
        for (int t = 0; t < 16; ++t) {
            float e = __expf(sc[h * Nn + lane + t * 32] - mx);
            sc[h * Nn + lane + t * 32] = e;
            sum += e;
        }
#pragma unroll
        for (int off = 16; off >= 1; off >>= 1)
            sum += __shfl_xor_sync(0xffffffffu, sum, off);
        float inv = 1.f / sum;
#pragma unroll
        for (int t = 0; t < 16; ++t) sc[h * Nn + lane + t * 32] *= inv;
    }
    __syncthreads();

    // Phase 3: o[c] = sum_m attn[h(c)][m] * V[n][m][c], split m-range over 2 halves
    {
        int c = tid & 127;
        int half = tid >> 7;
        int h = c >> 4;
        const float* vb = &sc_V[((size_t)n * Nn + half * 256) * Dd + c];
        const float* ap = &sc[h * Nn + half * 256];
        float acc = 0.f;
#pragma unroll 4
        for (int m = 0; m < 256; ++m)
            acc = fmaf(ap[m], vb[(size_t)m * Dd], acc);
        red2[tid] = acc;
        __syncthreads();
        if (tid < 128)
            sc_o[n * Dd + tid] = red2[tid] + red2[tid + 128];
    }
}

// ---------------- K7: out-proj + LN + FFN + LN ----------------
__device__ __forceinline__ float bsum128(float v, float* tmp) {
    int lane = threadIdx.x & 31, wid = threadIdx.x >> 5;
#pragma unroll
    for (int off = 16; off >= 1; off >>= 1)
        v += __shfl_xor_sync(0xffffffffu, v, off);
    if (lane == 0) tmp[wid] = v;
    __syncthreads();
    float s = tmp[0] + tmp[1] + tmp[2] + tmp[3];
    __syncthreads();
    return s;
}

__global__ void k_final(const float* __restrict__ node,
                        const float* __restrict__ Wo, const float* __restrict__ bo,
                        const float* __restrict__ g2, const float* __restrict__ be2,
                        const float* __restrict__ W1, const float* __restrict__ b1,
                        const float* __restrict__ W2, const float* __restrict__ b2,
                        const float* __restrict__ g3, const float* __restrict__ be3,
                        float* __restrict__ out_x) {
    const int n = blockIdx.x;
    const int c = threadIdx.x;   // 128 threads
    __shared__ float os[Dd], xs[Dd], hs[Df], tmp[4];

    os[c] = sc_o[n * Dd + c];
    __syncthreads();

    float t = bo[c];
#pragma unroll 8
    for (int k = 0; k < Dd; ++k) t = fmaf(os[k], Wo[k * Dd + c], t);
    float x = node[n * Dd + c] + t;

    float mean = bsum128(x, tmp) * (1.f / 128.f);
    float d = x - mean;
    float var = bsum128(d * d, tmp) * (1.f / 128.f);
    float xn = d * rsqrtf(var + 1e-5f) * g2[c] + be2[c];
    xs[c] = xn;
    __syncthreads();

    float h0 = b1[c], h1 = b1[c + 128];
#pragma unroll 8
    for (int k = 0; k < Dd; ++k) {
        float xv = xs[k];
        h0 = fmaf(xv, W1[k * Df + c], h0);
        h1 = fmaf(xv, W1[k * Df + c + 128], h1);
    }
    hs[c] = fmaxf(h0, 0.f);
    hs[c + 128] = fmaxf(h1, 0.f);
    __syncthreads();

    float y = b2[c];
#pragma unroll 8
    for (int f = 0; f < Df; ++f) y = fmaf(hs[f], W2[f * Dd + c], y);
    float z = xn + y;

    mean = bsum128(z, tmp) * (1.f / 128.f);
    d = z - mean;
    var = bsum128(d * d, tmp) * (1.f / 128.f);
    out_x[n * Dd + c] = d * rsqrtf(var + 1e-5f) * g3[c] + be3[c];
}

// ---------------- host launcher ----------------
extern "C" void kernel_launch(void* const* d_in, const int* in_sizes, int n_in,
                              void* d_out, int out_size) {
    const float* node   = (const float*)d_in[0];
    const float* edge   = (const float*)d_in[1];
    const unsigned char* mask = (const unsigned char*)d_in[2];
    const float* W_mem  = (const float*)d_in[3];
    const float* b_mem  = (const float*)d_in[4];
    const float* g_mem  = (const float*)d_in[5];
    const float* be_mem = (const float*)d_in[6];
    const float* W_e    = (const float*)d_in[7];
    const float* b_e    = (const float*)d_in[8];
    const float* g_e1   = (const float*)d_in[9];
    const float* be_e1  = (const float*)d_in[10];
    const float* g_e2   = (const float*)d_in[11];
    const float* be_e2  = (const float*)d_in[12];
    const float* Wq     = (const float*)d_in[13];
    const float* bq     = (const float*)d_in[14];
    const float* Wk     = (const float*)d_in[15];
    const float* bk     = (const float*)d_in[16];
    const float* Wv     = (const float*)d_in[17];
    const float* bv     = (const float*)d_in[18];
    const float* Wo     = (const float*)d_in[19];
    const float* bo     = (const float*)d_in[20];
    const float* W1     = (const float*)d_in[21];
    const float* b1     = (const float*)d_in[22];
    const float* W2     = (const float*)d_in[23];
    const float* b2     = (const float*)d_in[24];
    const float* g2     = (const float*)d_in[25];
    const float* be2    = (const float*)d_in[26];
    const float* g3     = (const float*)d_in[27];
    const float* be3    = (const float*)d_in[28];

    float* out = (float*)d_out;
    float* out_x = out;                    // [512,128]
    float* out_edge = out + Nn * Dd;       // [512,512,128]

    k_small<<<Nn, Dd>>>(node, W_mem, Wq, bq);
    k_mem<<<ROWS / 64, 256>>>(edge, W_mem, b_mem, g_mem, be_mem);
    k_edge<<<ROWS / 64, 256>>>(edge, W_e, b_e, g_e1, be_e1, g_e2, be_e2, out_edge);
    k_kv<<<ROWS / 64, 256>>>(Wk, bk, 0);
    k_kv<<<ROWS / 64, 256>>>(Wv, bv, 1);
    k_attn<<<Nn, 256>>>(mask);
    k_final<<<Nn, 128>>>(node, Wo, bo, g2, be2, W1, b1, W2, b2, g3, be3, out_x);
}

// round 4
// speedup vs baseline: 1.4243x; 1.4147x over previous
#include <cuda_runtime.h>
#include <math.h>
#include <stdint.h>

#define Nn 512
#define Dd 128
#define Df 256
#define Hh 8
#define ROWS (Nn*Nn)
#define NT 2048
#define SSTR 130

__device__ float sc_K[(size_t)ROWS * Dd];
__device__ float sc_V[(size_t)ROWS * Dd];
__device__ float sc_S[Nn * Dd];
__device__ float sc_T[Nn * Dd];
__device__ float sc_q[Nn * Dd];
__device__ float sc_o[Nn * Dd];
__device__ float wfrag[4][16384];                 // weight tiles, tf32 frag layout
__device__ float memfrag[(size_t)NT * 16384];     // memory, tf32 frag layout (134MB)

// dynamic smem float offsets
#define O_A 0            // 16384 floats: A fragments
#define O_B 16384        // 16384 floats: B fragments
#define O_S 32768        // 16640 floats: epilogue stage [128][130]
#define O_R 49408        // 256 floats: LN reduce
#define O_T 49664        // 128 floats: T row
#define SMF 49792
#define DYN (SMF * 4)

__device__ __forceinline__ uint32_t tf32c(float x) {
    uint32_t y;
    asm("cvt.rna.tf32.f32 %0, %1;" : "=r"(y) : "f"(x));
    return y;
}
__device__ __forceinline__ float tf32f(float x) { return __uint_as_float(tf32c(x)); }

__device__ __forceinline__ void mma8(float* c, const uint32_t* a, const uint32_t* b) {
    asm volatile(
        "mma.sync.aligned.m16n8k8.row.col.f32.tf32.tf32.f32 "
        "{%0,%1,%2,%3},{%4,%5,%6,%7},{%8,%9},{%0,%1,%2,%3};"
        : "+f"(c[0]), "+f"(c[1]), "+f"(c[2]), "+f"(c[3])
        : "r"(a[0]), "r"(a[1]), "r"(a[2]), "r"(a[3]), "r"(b[0]), "r"(b[1]));
}

// 128x128x128 tile: 8 warps, warp tile 32x64 (2 m-frags x 8 n-frags), 16 k-chunks
__device__ __forceinline__ void mma_tile(const float* sA, const float* sB, float c[2][8][4]) {
    int tid = threadIdx.x, w = tid >> 5, lane = tid & 31;
    int wm = w >> 1, wn = w & 1;
#pragma unroll
    for (int mt = 0; mt < 2; ++mt)
#pragma unroll
        for (int nt = 0; nt < 8; ++nt)
#pragma unroll
            for (int i = 0; i < 4; ++i) c[mt][nt][i] = 0.f;
#pragma unroll
    for (int kc = 0; kc < 16; ++kc) {
        uint32_t a[2][4];
#pragma unroll
        for (int mt = 0; mt < 2; ++mt) {
            float4 v = *(const float4*)&sA[(((wm * 2 + mt) * 16 + kc) * 32 + lane) * 4];
            a[mt][0] = __float_as_uint(v.x); a[mt][1] = __float_as_uint(v.y);
            a[mt][2] = __float_as_uint(v.z); a[mt][3] = __float_as_uint(v.w);
        }
#pragma unroll
        for (int nt = 0; nt < 8; ++nt) {
            float2 bv = *(const float2*)&sB[(((wn * 8 + nt) * 16 + kc) * 32 + lane) * 2];
            uint32_t b[2] = {__float_as_uint(bv.x), __float_as_uint(bv.y)};
            mma8(c[0][nt], a[0], b);
            mma8(c[1][nt], a[1], b);
        }
    }
}

__device__ __forceinline__ void frag_to_stg(float* stg, float c[2][8][4]) {
    int tid = threadIdx.x, w = tid >> 5, lane = tid & 31;
    int wm = w >> 1, wn = w & 1, g = lane >> 2, t2 = (lane & 3) * 2;
#pragma unroll
    for (int mt = 0; mt < 2; ++mt)
#pragma unroll
        for (int nt = 0; nt < 8; ++nt) {
            int row = wm * 32 + mt * 16 + g, col = wn * 64 + nt * 8 + t2;
            *(float2*)&stg[row * SSTR + col] = make_float2(c[mt][nt][0], c[mt][nt][1]);
            *(float2*)&stg[(row + 8) * SSTR + col] = make_float2(c[mt][nt][2], c[mt][nt][3]);
        }
}

__device__ __forceinline__ float ln_red(float part, float* red, int row, int ch) {
    red[row * 2 + ch] = part;
    __syncthreads();
    float s = red[row * 2] + red[row * 2 + 1];
    __syncthreads();
    return s;
}

// ---------- weight prep: transpose + tf32 + fragment layout ----------
__global__ void k_prep(const float* __restrict__ Wm, const float* __restrict__ We,
                       const float* __restrict__ Wk, const float* __restrict__ Wv) {
    extern __shared__ float ws[];   // [128][129]
    const float* W = blockIdx.x == 0 ? Wm : blockIdx.x == 1 ? We : blockIdx.x == 2 ? Wk : Wv;
    int tid = threadIdx.x;
    for (int t = 0; t < 16; ++t) {
        int id = tid + t * 256;
        int k = id >> 5, n4 = (id & 31) << 2;
        float4 v = *(const float4*)&W[k * Dd + n4];
        ws[k * 129 + n4] = v.x; ws[k * 129 + n4 + 1] = v.y;
        ws[k * 129 + n4 + 2] = v.z; ws[k * 129 + n4 + 3] = v.w;
    }
    __syncthreads();
    float* out = wfrag[blockIdx.x];
    for (int t = 0; t < 32; ++t) {           // 8192 float2
        int id = tid + t * 256;
        int lane = id & 31, kb = (id >> 5) & 15, nb = id >> 9;
        int n = nb * 8 + (lane >> 2), k = kb * 8 + (lane & 3);
        float2 o;
        o.x = tf32f(ws[k * 129 + n]);
        o.y = tf32f(ws[(k + 4) * 129 + n]);
        *(float2*)&out[id * 2] = o;
    }
}

// ---------- S, T, q ----------
__global__ void k_small(const float* __restrict__ node, const float* __restrict__ Wmem,
                        const float* __restrict__ Wq, const float* __restrict__ bq) {
    int n = blockIdx.x, c = threadIdx.x;
    __shared__ float ns[Dd];
    ns[c] = node[n * Dd + c];
    __syncthreads();
    float s = 0.f, t = 0.f, q = 0.f;
#pragma unroll 8
    for (int k = 0; k < Dd; ++k) {
        float nv = ns[k];
        s = fmaf(nv, Wmem[(Dd + k) * Dd + c], s);
        t = fmaf(nv, Wmem[(2 * Dd + k) * Dd + c], t);
        q = fmaf(nv, Wq[k * Dd + c], q);
    }
    sc_S[n * Dd + c] = s; sc_T[n * Dd + c] = t; sc_q[n * Dd + c] = q + bq[c];
}

// ---------- memory = relu(LN(edge@Wm + S[j] + T[i] + b)) -> memfrag ----------
__global__ __launch_bounds__(256, 1) void k_mem(const float* __restrict__ edge,
        const float* __restrict__ bm, const float* __restrict__ gm, const float* __restrict__ bem) {
    extern __shared__ float sm[];
    int tid = threadIdx.x;
    int ib = blockIdx.x >> 2, jn0 = (blockIdx.x & 3) << 7;
    size_t r0 = (size_t)blockIdx.x * 128;

    // A: edge -> frag layout (+tf32)
    for (int t = 0; t < 16; ++t) {
        int id = tid + t * 256;
        int r = id >> 5, c4 = (id & 31) << 2;
        float4 v = *(const float4*)&edge[(r0 + r) * Dd + c4];
        int mb = r >> 4, mr = r & 15, kb = c4 >> 3;
        int reg = (mr >> 3) + (((c4 & 7) >> 2) << 1);
        int base = ((mb * 16 + kb) * 32) * 4 + ((mr & 7) << 2) * 4 + reg;
        sm[O_A + base + 0 * 4] = tf32f(v.x);
        sm[O_A + base + 1 * 4] = tf32f(v.y);
        sm[O_A + base + 2 * 4] = tf32f(v.z);
        sm[O_A + base + 3 * 4] = tf32f(v.w);
    }
    for (int t = 0; t < 16; ++t) {
        int id = tid + t * 256;
        *(float4*)&sm[O_B + id * 4] = *(const float4*)&wfrag[0][id * 4];
    }
    if (tid < Dd) sm[O_T + tid] = sc_T[ib * Dd + tid];
    __syncthreads();

    float c[2][8][4];
    mma_tile(sm + O_A, sm + O_B, c);
    frag_to_stg(sm + O_S, c);
    __syncthreads();

    int row = tid >> 1, ch = tid & 1, c0 = ch << 6;
    int jn = jn0 + row;
    float v[64];
    {
        const float4* Sp = (const float4*)&sc_S[jn * Dd + c0];
        const float4* Bp = (const float4*)&bm[c0];
        const float4* Tp = (const float4*)&sm[O_T + c0];
        const float* sp = &sm[O_S + row * SSTR + c0];
#pragma unroll
        for (int q = 0; q < 16; ++q) {
            float4 s4 = Sp[q], b4 = Bp[q], t4 = Tp[q];
            v[q*4+0] = sp[q*4+0] + b4.x + s4.x + t4.x;
            v[q*4+1] = sp[q*4+1] + b4.y + s4.y + t4.y;
            v[q*4+2] = sp[q*4+2] + b4.z + s4.z + t4.z;
            v[q*4+3] = sp[q*4+3] + b4.w + s4.w + t4.w;
        }
    }
    float* red = &sm[O_R];
    float s = 0.f;
#pragma unroll
    for (int j = 0; j < 64; ++j) s += v[j];
    float mean = ln_red(s, red, row, ch) * (1.f / 128.f);
    float s2 = 0.f;
#pragma unroll
    for (int j = 0; j < 64; ++j) { float d = v[j] - mean; s2 = fmaf(d, d, s2); }
    float rstd = rsqrtf(ln_red(s2, red, row, ch) * (1.f / 128.f) + 1e-5f);
#pragma unroll
    for (int j = 0; j < 64; ++j) {
        int cc = c0 + j;
        float x = (v[j] - mean) * rstd * gm[cc] + bem[cc];
        sm[O_S + row * SSTR + cc] = tf32f(fmaxf(x, 0.f));
    }
    __syncthreads();

    float* mo = &memfrag[(size_t)blockIdx.x * 16384];
    for (int t = 0; t < 16; ++t) {
        int id = tid + t * 256;                 // float4 index = (mb*16+kb)*32+lane
        int lane = id & 31, kb = (id >> 5) & 15, mb = id >> 9;
        int R = mb * 16 + (lane >> 2), K = kb * 8 + (lane & 3);
        float4 o;
        o.x = sm[O_S + R * SSTR + K];
        o.y = sm[O_S + (R + 8) * SSTR + K];
        o.z = sm[O_S + R * SSTR + K + 4];
        o.w = sm[O_S + (R + 8) * SSTR + K + 4];
        *(float4*)&mo[id * 4] = o;
    }
}

// ---------- edge_out = LN(edge + relu(LN(mem@We + be))) ----------
__global__ __launch_bounds__(256, 1) void k_edge(const float* __restrict__ edge,
        const float* __restrict__ beb, const float* __restrict__ g1, const float* __restrict__ be1,
        const float* __restrict__ g2, const float* __restrict__ be2, float* __restrict__ oe) {
    extern __shared__ float sm[];
    int tid = threadIdx.x;
    size_t r0 = (size_t)blockIdx.x * 128;
    const float* mf = &memfrag[(size_t)blockIdx.x * 16384];

    for (int t = 0; t < 16; ++t) {
        int id = tid + t * 256;
        *(float4*)&sm[O_A + id * 4] = *(const float4*)&mf[id * 4];
        *(float4*)&sm[O_B + id * 4] = *(const float4*)&wfrag[1][id * 4];
    }
    __syncthreads();
    float c[2][8][4];
    mma_tile(sm + O_A, sm + O_B, c);
    __syncthreads();                          // all warps done reading A
    // residual -> A region (16B-swizzled rows)
    for (int t = 0; t < 16; ++t) {
        int id = tid + t * 256;
        int r = id >> 5, c4 = (id & 31) << 2;
        int cs = c4 ^ ((r & 7) << 2);
        *(float4*)&sm[O_A + r * 128 + cs] = *(const float4*)&edge[(r0 + r) * Dd + c4];
    }
    frag_to_stg(sm + O_S, c);
    __syncthreads();

    int row = tid >> 1, ch = tid & 1, c0 = ch << 6;
    float v[64];
#pragma unroll
    for (int j = 0; j < 64; ++j) v[j] = sm[O_S + row * SSTR + c0 + j] + beb[c0 + j];

    float* red = &sm[O_R];
    float s = 0.f;
#pragma unroll
    for (int j = 0; j < 64; ++j) s += v[j];
    float mean = ln_red(s, red, row, ch) * (1.f / 128.f);
    float s2 = 0.f;
#pragma unroll
    for (int j = 0; j < 64; ++j) { float d = v[j] - mean; s2 = fmaf(d, d, s2); }
    float rstd = rsqrtf(ln_red(s2, red, row, ch) * (1.f / 128.f) + 1e-5f);
#pragma unroll
    for (int j = 0; j < 64; ++j) {
        int cc = c0 + j;
        float u = fmaxf((v[j] - mean) * rstd * g1[cc] + be1[cc], 0.f);
        int cs = cc ^ ((row & 7) << 2);
        v[j] = sm[O_A + row * 128 + cs] + u;
    }
    s = 0.f;
#pragma unroll
    for (int j = 0; j < 64; ++j) s += v[j];
    mean = ln_red(s, red, row, ch) * (1.f / 128.f);
    s2 = 0.f;
#pragma unroll
    for (int j = 0; j < 64; ++j) { float d = v[j] - mean; s2 = fmaf(d, d, s2); }
    rstd = rsqrtf(ln_red(s2, red, row, ch) * (1.f / 128.f) + 1e-5f);
#pragma unroll
    for (int j = 0; j < 64; ++j) {
        int cc = c0 + j;
        sm[O_S + row * SSTR + cc] = (v[j] - mean) * rstd * g2[cc] + be2[cc];
    }
    __syncthreads();
    for (int t = 0; t < 16; ++t) {
        int id = tid + t * 256;
        int r = id >> 5, c4 = (id & 31) << 2;
        const float* sp = &sm[O_S + r * SSTR + c4];
        float4 o; o.x = sp[0]; o.y = sp[1]; o.z = sp[2]; o.w = sp[3];
        *(float4*)&oe[(r0 + r) * Dd + c4] = o;
    }
}

// ---------- K and V fused (transposed outputs) ----------
__global__ __launch_bounds__(256, 1) void k_kv(const float* __restrict__ bk,
                                               const float* __restrict__ bv) {
    extern __shared__ float sm[];
    int tid = threadIdx.x;
    int ib = blockIdx.x >> 2, jn0 = (blockIdx.x & 3) << 7;
    const float* mf = &memfrag[(size_t)blockIdx.x * 16384];

    for (int t = 0; t < 16; ++t) {
        int id = tid + t * 256;
        *(float4*)&sm[O_A + id * 4] = *(const float4*)&mf[id * 4];
        *(float4*)&sm[O_B + id * 4] = *(const float4*)&wfrag[2][id * 4];
    }
    __syncthreads();
    float c[2][8][4];
    mma_tile(sm + O_A, sm + O_B, c);
    frag_to_stg(sm + O_S, c);
    __syncthreads();
    // write K (+bias) and swap B to Wv
    for (int t = 0; t < 16; ++t) {
        int id = tid + t * 256;
        int r = id >> 5, c4 = (id & 31) << 2;
        const float* sp = &sm[O_S + r * SSTR + c4];
        float4 b4 = *(const float4*)&bk[c4];
        float4 o; o.x = sp[0] + b4.x; o.y = sp[1] + b4.y; o.z = sp[2] + b4.z; o.w = sp[3] + b4.w;
        *(float4*)&sc_K[((size_t)(jn0 + r) * Nn + ib) * Dd + c4] = o;
        *(float4*)&sm[O_B + id * 4] = *(const float4*)&wfrag[3][id * 4];
    }
    __syncthreads();
    mma_tile(sm + O_A, sm + O_B, c);
    __syncthreads();
    frag_to_stg(sm + O_S, c);
    __syncthreads();
    for (int t = 0; t < 16; ++t) {
        int id = tid + t * 256;
        int r = id >> 5, c4 = (id & 31) << 2;
        const float* sp = &sm[O_S + r * SSTR + c4];
        float4 b4 = *(const float4*)&bv[c4];
        float4 o; o.x = sp[0] + b4.x; o.y = sp[1] + b4.y; o.z = sp[2] + b4.z; o.w = sp[3] + b4.w;
        *(float4*)&sc_V[((size_t)(jn0 + r) * Nn + ib) * Dd + c4] = o;
    }
}

// ---------- attention per batch ----------
__global__ void k_attn(const unsigned char* __restrict__ mask) {
    const int n = blockIdx.x;
    const int tid = threadIdx.x;
    const int w = tid >> 5, lane = tid & 31;
    __shared__ float q_s[Dd];
    __shared__ float sc[Hh * Nn];
    __shared__ float red2[256];

    if (tid < Dd) q_s[tid] = sc_q[n * Dd + tid];
    __syncthreads();
    float4 qv = *(const float4*)&q_s[lane * 4];
    for (int m = w; m < Nn; m += 8) {
        const float* kp = &sc_K[((size_t)n * Nn + m) * Dd];
        float4 kd = *(const float4*)&kp[lane * 4];
        float p = qv.x * kd.x + qv.y * kd.y + qv.z * kd.z + qv.w * kd.w;
        p += __shfl_xor_sync(0xffffffffu, p, 1);
        p += __shfl_xor_sync(0xffffffffu, p, 2);
        if ((lane & 3) == 0) {
            int h = lane >> 2;
            sc[h * Nn + m] = mask[n * Nn + m] ? -INFINITY : p * 0.25f;
        }
    }
    __syncthreads();
    {
        int h = w;
        float mx = -INFINITY;
#pragma unroll
        for (int t = 0; t < 16; ++t) mx = fmaxf(mx, sc[h * Nn + lane + t * 32]);
#pragma unroll
        for (int off = 16; off >= 1; off >>= 1) mx = fmaxf(mx, __shfl_xor_sync(0xffffffffu, mx, off));
        float sum = 0.f;
#pragma unroll
        for (int t = 0; t < 16; ++t) {
            float e = __expf(sc[h * Nn + lane + t * 32] - mx);
            sc[h * Nn + lane + t * 32] = e; sum += e;
        }
#pragma unroll
        for (int off = 16; off >= 1; off >>= 1) sum += __shfl_xor_sync(0xffffffffu, sum, off);
        float inv = 1.f / sum;
#pragma unroll
        for (int t = 0; t < 16; ++t) sc[h * Nn + lane + t * 32] *= inv;
    }
    __syncthreads();
    {
        int c = tid & 127, half = tid >> 7, h = c >> 4;
        const float* vb = &sc_V[((size_t)n * Nn + half * 256) * Dd + c];
        const float* ap = &sc[h * Nn + half * 256];
        float acc = 0.f;
#pragma unroll 8
        for (int m = 0; m < 256; ++m) acc = fmaf(ap[m], vb[(size_t)m * Dd], acc);
        red2[tid] = acc;
        __syncthreads();
        if (tid < 128) sc_o[n * Dd + tid] = red2[tid] + red2[tid + 128];
    }
}

// ---------- final: out-proj + LN + FFN + LN ----------
__device__ __forceinline__ float bsum128(float v, float* tmp) {
    int lane = threadIdx.x & 31, wid = threadIdx.x >> 5;
#pragma unroll
    for (int off = 16; off >= 1; off >>= 1) v += __shfl_xor_sync(0xffffffffu, v, off);
    if (lane == 0) tmp[wid] = v;
    __syncthreads();
    float s = tmp[0] + tmp[1] + tmp[2] + tmp[3];
    __syncthreads();
    return s;
}
__global__ void k_final(const float* __restrict__ node,
                        const float* __restrict__ Wo, const float* __restrict__ bo,
                        const float* __restrict__ g2, const float* __restrict__ be2,
                        const float* __restrict__ W1, const float* __restrict__ b1,
                        const float* __restrict__ W2, const float* __restrict__ b2,
                        const float* __restrict__ g3, const float* __restrict__ be3,
                        float* __restrict__ out_x) {
    const int n = blockIdx.x;
    const int c = threadIdx.x;
    __shared__ float os[Dd], xs[Dd], hs[Df], tmp[4];
    os[c] = sc_o[n * Dd + c];
    __syncthreads();
    float t = bo[c];
#pragma unroll 8
    for (int k = 0; k < Dd; ++k) t = fmaf(os[k], Wo[k * Dd + c], t);
    float x = node[n * Dd + c] + t;
    float mean = bsum128(x, tmp) * (1.f / 128.f);
    float d = x - mean;
    float var = bsum128(d * d, tmp) * (1.f / 128.f);
    float xn = d * rsqrtf(var + 1e-5f) * g2[c] + be2[c];
    xs[c] = xn;
    __syncthreads();
    float h0 = b1[c], h1 = b1[c + 128];
#pragma unroll 8
    for (int k = 0; k < Dd; ++k) {
        float xv = xs[k];
        h0 = fmaf(xv, W1[k * Df + c], h0);
        h1 = fmaf(xv, W1[k * Df + c + 128], h1);
    }
    hs[c] = fmaxf(h0, 0.f);
    hs[c + 128] = fmaxf(h1, 0.f);
    __syncthreads();
    float y = b2[c];
#pragma unroll 8
    for (int f = 0; f < Df; ++f) y = fmaf(hs[f], W2[f * Dd + c], y);
    float z = xn + y;
    mean = bsum128(z, tmp) * (1.f / 128.f);
    d = z - mean;
    var = bsum128(d * d, tmp) * (1.f / 128.f);
    out_x[n * Dd + c] = d * rsqrtf(var + 1e-5f) * g3[c] + be3[c];
}

// ---------- host ----------
extern "C" void kernel_launch(void* const* d_in, const int* in_sizes, int n_in,
                              void* d_out, int out_size) {
    const float* node = (const float*)d_in[0];
    const float* edge = (const float*)d_in[1];
    const unsigned char* mask = (const unsigned char*)d_in[2];
    const float* W_mem = (const float*)d_in[3];
    const float* b_mem = (const float*)d_in[4];
    const float* g_mem = (const float*)d_in[5];
    const float* be_mem = (const float*)d_in[6];
    const float* W_e = (const float*)d_in[7];
    const float* b_e = (const float*)d_in[8];
    const float* g_e1 = (const float*)d_in[9];
    const float* be_e1 = (const float*)d_in[10];
    const float* g_e2 = (const float*)d_in[11];
    const float* be_e2 = (const float*)d_in[12];
    const float* Wq = (const float*)d_in[13];
    const float* bq = (const float*)d_in[14];
    const float* Wk = (const float*)d_in[15];
    const float* bk = (const float*)d_in[16];
    const float* Wv = (const float*)d_in[17];
    const float* bv = (const float*)d_in[18];
    const float* Wo = (const float*)d_in[19];
    const float* bo = (const float*)d_in[20];
    const float* W1 = (const float*)d_in[21];
    const float* b1 = (const float*)d_in[22];
    const float* W2 = (const float*)d_in[23];
    const float* b2 = (const float*)d_in[24];
    const float* g2 = (const float*)d_in[25];
    const float* be2 = (const float*)d_in[26];
    const float* g3 = (const float*)d_in[27];
    const float* be3 = (const float*)d_in[28];

    float* out = (float*)d_out;
    float* out_x = out;
    float* out_edge = out + Nn * Dd;

    static int init = 0;
    if (!init) {
        cudaFuncSetAttribute(k_prep, cudaFuncAttributeMaxDynamicSharedMemorySize, 128 * 129 * 4);
        cudaFuncSetAttribute(k_mem,  cudaFuncAttributeMaxDynamicSharedMemorySize, DYN);
        cudaFuncSetAttribute(k_edge, cudaFuncAttributeMaxDynamicSharedMemorySize, DYN);
        cudaFuncSetAttribute(k_kv,   cudaFuncAttributeMaxDynamicSharedMemorySize, DYN);
        init = 1;
    }

    k_prep<<<4, 256, 128 * 129 * 4>>>(W_mem, W_e, Wk, Wv);
    k_small<<<Nn, Dd>>>(node, W_mem, Wq, bq);
    k_mem<<<NT, 256, DYN>>>(edge, b_mem, g_mem, be_mem);
    k_edge<<<NT, 256, DYN>>>(edge, b_e, g_e1, be_e1, g_e2, be_e2, out_edge);
    k_kv<<<NT, 256, DYN>>>(bk, bv);
    k_attn<<<Nn, 256>>>(mask);
    k_final<<<Nn, 128>>>(node, Wo, bo, g2, be2, W1, b1, W2, b2, g3, be3, out_x);
}

// round 7
// speedup vs baseline: 2.2232x; 1.5609x over previous
#include <cuda_runtime.h>
#include <math.h>
#include <stdint.h>

#define Nn 512
#define Dd 128
#define Df 256
#define Hh 8
#define ROWS (Nn*Nn)
#define NT 2048

__device__ float sc_K[(size_t)ROWS * Dd];
__device__ float sc_V[(size_t)ROWS * Dd];
__device__ float sc_S[Nn * Dd];
__device__ float sc_T[Nn * Dd];
__device__ float sc_q[Nn * Dd];
__device__ float sc_o[Nn * Dd];
__device__ float wfrag[4][16384];   // Wm_edge, We, Wk, Wv in tf32 frag layout

// dynamic smem float offsets
#define O_A  0
#define O_B0 16384
#define O_B1 32768
#define O_RS 49152
#define O_RQ 49408
#define O_P  49664
#define SMF  49792
#define DYN  (SMF * 4)

__device__ __forceinline__ uint32_t tf32c(float x) {
    uint32_t y; asm("cvt.rna.tf32.f32 %0, %1;" : "=r"(y) : "f"(x)); return y;
}
__device__ __forceinline__ float tf32f(float x) { return __uint_as_float(tf32c(x)); }

__device__ __forceinline__ uint32_t smem_u32(const void* p) {
    uint32_t a;
    asm("{ .reg .u64 t; cvta.to.shared.u64 t, %1; cvt.u32.u64 %0, t; }" : "=r"(a) : "l"(p));
    return a;
}
__device__ __forceinline__ void cpa16(uint32_t s, const void* g) {
    asm volatile("cp.async.cg.shared.global [%0], [%1], 16;" :: "r"(s), "l"(g));
}
#define CPC() asm volatile("cp.async.commit_group;" ::: "memory")
#define CPW(n) asm volatile("cp.async.wait_group %0;" :: "n"(n) : "memory")

__device__ __forceinline__ void mma8(float* c, const uint32_t* a, const uint32_t* b) {
    asm volatile(
        "mma.sync.aligned.m16n8k8.row.col.f32.tf32.tf32.f32 "
        "{%0,%1,%2,%3},{%4,%5,%6,%7},{%8,%9},{%0,%1,%2,%3};"
        : "+f"(c[0]), "+f"(c[1]), "+f"(c[2]), "+f"(c[3])
        : "r"(a[0]), "r"(a[1]), "r"(a[2]), "r"(a[3]), "r"(b[0]), "r"(b[1]));
}

// A-fragment float index for element (row r, col c) of 128x128 tile
__device__ __forceinline__ int AFR(int r, int c) {
    return (((r >> 4) * 16 + (c >> 3)) * 32 + ((r & 7) << 2) + (c & 3)) * 4
           + ((r >> 3) & 1) + (((c >> 2) & 1) << 1);
}
// bank-swizzled raw-tile index (r, c) for B1 raw f32 tiles
__device__ __forceinline__ int SWZ(int r, int c) {
    return r * Dd + ((((c >> 2) ^ ((r & 7) << 2)) & 31) << 2) + (c & 3);
}

// 128x128x128 tile MMA: 8 warps, warp tile 32x64
__device__ __forceinline__ void mma_tile(const float* sA, const float* sB, float c[2][8][4]) {
    int tid = threadIdx.x, w = tid >> 5, lane = tid & 31;
    int wm = w >> 1, wn = w & 1;
#pragma unroll
    for (int mt = 0; mt < 2; ++mt)
#pragma unroll
        for (int nt = 0; nt < 8; ++nt)
#pragma unroll
            for (int i = 0; i < 4; ++i) c[mt][nt][i] = 0.f;
#pragma unroll
    for (int kc = 0; kc < 16; ++kc) {
        uint32_t a[2][4];
#pragma unroll
        for (int mt = 0; mt < 2; ++mt) {
            float4 v = *(const float4*)&sA[(((wm * 2 + mt) * 16 + kc) * 32 + lane) * 4];
            a[mt][0] = __float_as_uint(v.x); a[mt][1] = __float_as_uint(v.y);
            a[mt][2] = __float_as_uint(v.z); a[mt][3] = __float_as_uint(v.w);
        }
#pragma unroll
        for (int nt = 0; nt < 8; ++nt) {
            float2 bv = *(const float2*)&sB[(((wn * 8 + nt) * 16 + kc) * 32 + lane) * 2];
            uint32_t b[2] = {__float_as_uint(bv.x), __float_as_uint(bv.y)};
            mma8(c[0][nt], a[0], b);
            mma8(c[1][nt], a[1], b);
        }
    }
}

// per-row LN stats from fragments: quad shfl + cross-warp-pair smem combine
#define ROWSTATS(sv, qv, mean, rstd) do { \
    _Pragma("unroll") for (int _rs_mt = 0; _rs_mt < 2; ++_rs_mt) \
    _Pragma("unroll") for (int _rs_h = 0; _rs_h < 2; ++_rs_h) { \
        float _rs_s = (sv)[_rs_mt][_rs_h], _rs_q = (qv)[_rs_mt][_rs_h]; \
        _rs_s += __shfl_xor_sync(0xffffffffu, _rs_s, 1); _rs_q += __shfl_xor_sync(0xffffffffu, _rs_q, 1); \
        _rs_s += __shfl_xor_sync(0xffffffffu, _rs_s, 2); _rs_q += __shfl_xor_sync(0xffffffffu, _rs_q, 2); \
        (sv)[_rs_mt][_rs_h] = _rs_s; (qv)[_rs_mt][_rs_h] = _rs_q; } \
    if ((lane & 3) == 0) { \
        _Pragma("unroll") for (int _rs_mt = 0; _rs_mt < 2; ++_rs_mt) \
        _Pragma("unroll") for (int _rs_h = 0; _rs_h < 2; ++_rs_h) { \
            int _rs_row = wm * 32 + _rs_mt * 16 + g + _rs_h * 8; \
            sm[O_RS + _rs_row * 2 + wn] = (sv)[_rs_mt][_rs_h]; \
            sm[O_RQ + _rs_row * 2 + wn] = (qv)[_rs_mt][_rs_h]; } } \
    __syncthreads(); \
    _Pragma("unroll") for (int _rs_mt = 0; _rs_mt < 2; ++_rs_mt) \
    _Pragma("unroll") for (int _rs_h = 0; _rs_h < 2; ++_rs_h) { \
        int _rs_row = wm * 32 + _rs_mt * 16 + g + _rs_h * 8; \
        float _rs_ts = sm[O_RS + _rs_row * 2] + sm[O_RS + _rs_row * 2 + 1]; \
        float _rs_tq = sm[O_RQ + _rs_row * 2] + sm[O_RQ + _rs_row * 2 + 1]; \
        float _rs_mn = _rs_ts * (1.f / 128.f); \
        (mean)[_rs_mt][_rs_h] = _rs_mn; \
        (rstd)[_rs_mt][_rs_h] = rsqrtf(fmaxf(_rs_tq * (1.f / 128.f) - _rs_mn * _rs_mn, 0.f) + 1e-5f); } \
    __syncthreads(); \
} while (0)

// ---------- weight prep: transpose + tf32 + fragment layout ----------
__global__ void k_prep(const float* __restrict__ Wm, const float* __restrict__ We,
                       const float* __restrict__ Wk, const float* __restrict__ Wv) {
    extern __shared__ float ws[];   // [128][129]
    const float* W = blockIdx.x == 0 ? Wm : blockIdx.x == 1 ? We : blockIdx.x == 2 ? Wk : Wv;
    int tid = threadIdx.x;
    for (int t = 0; t < 16; ++t) {
        int id = tid + t * 256;
        int k = id >> 5, n4 = (id & 31) << 2;
        float4 v = *(const float4*)&W[k * Dd + n4];
        ws[k * 129 + n4] = v.x; ws[k * 129 + n4 + 1] = v.y;
        ws[k * 129 + n4 + 2] = v.z; ws[k * 129 + n4 + 3] = v.w;
    }
    __syncthreads();
    float* out = wfrag[blockIdx.x];
    for (int t = 0; t < 32; ++t) {
        int id = tid + t * 256;
        int lane = id & 31, kb = (id >> 5) & 15, nb = id >> 9;
        int n = nb * 8 + (lane >> 2), k = kb * 8 + (lane & 3);
        float2 o;
        o.x = tf32f(ws[k * 129 + n]);
        o.y = tf32f(ws[(k + 4) * 129 + n]);
        *(float2*)&out[id * 2] = o;
    }
}

// ---------- S, T, q ----------
__global__ void k_small(const float* __restrict__ node, const float* __restrict__ Wmem,
                        const float* __restrict__ Wq, const float* __restrict__ bq) {
    int n = blockIdx.x, c = threadIdx.x;
    __shared__ float ns[Dd];
    ns[c] = node[n * Dd + c];
    __syncthreads();
    float s = 0.f, t = 0.f, q = 0.f;
#pragma unroll 8
    for (int k = 0; k < Dd; ++k) {
        float nv = ns[k];
        s = fmaf(nv, Wmem[(Dd + k) * Dd + c], s);
        t = fmaf(nv, Wmem[(2 * Dd + k) * Dd + c], t);
        q = fmaf(nv, Wq[k * Dd + c], q);
    }
    sc_S[n * Dd + c] = s; sc_T[n * Dd + c] = t; sc_q[n * Dd + c] = q + bq[c];
}

// ---------- fused tile kernel: memory -> edge_out, K, V ----------
__global__ __launch_bounds__(256, 1) void k_fused(
    const float* __restrict__ edge,
    const float* __restrict__ bm, const float* __restrict__ gm, const float* __restrict__ bem,
    const float* __restrict__ beb, const float* __restrict__ g1, const float* __restrict__ be1,
    const float* __restrict__ g2, const float* __restrict__ be2,
    const float* __restrict__ bk, const float* __restrict__ bv,
    float* __restrict__ oe)
{
    extern __shared__ float sm[];
    const uint32_t sb = smem_u32(sm);
    const int tid = threadIdx.x, w = tid >> 5, lane = tid & 31;
    const int wm = w >> 1, wn = w & 1, g = lane >> 2, t2 = (lane & 3) << 1;
    const int ib = blockIdx.x >> 2, jn0 = (blockIdx.x & 3) << 7;
    const size_t r0 = (size_t)blockIdx.x * 128;

    // phase0: async B0<-Wm-frag, B1<-S-tile (swizzled); A<-edge (tf32 frag)
    {
        const float* s0 = wfrag[0];
        const float* s1 = &sc_S[(size_t)jn0 * Dd];
#pragma unroll
        for (int t = 0; t < 16; ++t) {
            int id4 = tid + t * 256;               // float4 index
            cpa16(sb + (O_B0 + id4 * 4) * 4, s0 + id4 * 4);
            int r = id4 >> 5, ch = id4 & 31;
            int dch = (ch ^ ((r & 7) << 2)) & 31;
            cpa16(sb + (O_B1 + (r * 32 + dch) * 4) * 4, s1 + id4 * 4);
        }
        CPC();
    }
#pragma unroll
    for (int t = 0; t < 16; ++t) {
        int id = tid + t * 256;
        int r = id >> 5, c4 = (id & 31) << 2;
        float4 v = *(const float4*)&edge[(r0 + r) * Dd + c4];
        int base = AFR(r, c4);
        sm[O_A + base + 0] = tf32f(v.x); sm[O_A + base + 4] = tf32f(v.y);
        sm[O_A + base + 8] = tf32f(v.z); sm[O_A + base + 12] = tf32f(v.w);
    }
    if (tid < Dd) sm[O_P + tid] = bm[tid] + sc_T[ib * Dd + tid];
    CPW(0); __syncthreads();

    float c[2][8][4];
    mma_tile(sm + O_A, sm + O_B0, c);
    __syncthreads();

    // prefetch We -> B0 (G1)
#pragma unroll
    for (int t = 0; t < 16; ++t) { int id4 = tid + t * 256; cpa16(sb + (O_B0 + id4 * 4) * 4, wfrag[1] + id4 * 4); }
    CPC();

    // epilogue1: memory = relu(LN(c + bm+T + S)); rewrite A-frags (tf32)
    {
        float sv[2][2] = {{0,0},{0,0}}, qv[2][2] = {{0,0},{0,0}};
#pragma unroll
        for (int mt = 0; mt < 2; ++mt) {
            int rA = wm * 32 + mt * 16 + g;
#pragma unroll
            for (int nt = 0; nt < 8; ++nt) {
                int col = wn * 64 + nt * 8 + t2;
                float p0 = sm[O_P + col], p1 = sm[O_P + col + 1];
                c[mt][nt][0] += p0 + sm[O_B1 + SWZ(rA, col)];
                c[mt][nt][1] += p1 + sm[O_B1 + SWZ(rA, col + 1)];
                c[mt][nt][2] += p0 + sm[O_B1 + SWZ(rA + 8, col)];
                c[mt][nt][3] += p1 + sm[O_B1 + SWZ(rA + 8, col + 1)];
                sv[mt][0] += c[mt][nt][0] + c[mt][nt][1];
                qv[mt][0] += c[mt][nt][0]*c[mt][nt][0] + c[mt][nt][1]*c[mt][nt][1];
                sv[mt][1] += c[mt][nt][2] + c[mt][nt][3];
                qv[mt][1] += c[mt][nt][2]*c[mt][nt][2] + c[mt][nt][3]*c[mt][nt][3];
            }
        }
        float mean[2][2], rstd[2][2];
        ROWSTATS(sv, qv, mean, rstd);
#pragma unroll
        for (int mt = 0; mt < 2; ++mt) {
            int rA = wm * 32 + mt * 16 + g;
#pragma unroll
            for (int nt = 0; nt < 8; ++nt) {
                int col = wn * 64 + nt * 8 + t2;
                float ga0 = __ldg(&gm[col]), ga1 = __ldg(&gm[col + 1]);
                float bb0 = __ldg(&bem[col]), bb1 = __ldg(&bem[col + 1]);
                sm[O_A + AFR(rA, col)]     = tf32f(fmaxf((c[mt][nt][0]-mean[mt][0])*rstd[mt][0]*ga0+bb0, 0.f));
                sm[O_A + AFR(rA, col + 1)] = tf32f(fmaxf((c[mt][nt][1]-mean[mt][0])*rstd[mt][0]*ga1+bb1, 0.f));
                sm[O_A + AFR(rA + 8, col)]     = tf32f(fmaxf((c[mt][nt][2]-mean[mt][1])*rstd[mt][1]*ga0+bb0, 0.f));
                sm[O_A + AFR(rA + 8, col + 1)] = tf32f(fmaxf((c[mt][nt][3]-mean[mt][1])*rstd[mt][1]*ga1+bb1, 0.f));
            }
        }
    }
    __syncthreads();

    // prefetch edge residual -> B1 (swizzled) (G2)
#pragma unroll
    for (int t = 0; t < 16; ++t) {
        int id4 = tid + t * 256;
        int r = id4 >> 5, ch = id4 & 31;
        int dch = (ch ^ ((r & 7) << 2)) & 31;
        cpa16(sb + (O_B1 + (r * 32 + dch) * 4) * 4, edge + r0 * Dd + (size_t)id4 * 4);
    }
    CPC();
    CPW(1); __syncthreads();    // We ready

    mma_tile(sm + O_A, sm + O_B0, c);     // edge branch GEMM
    __syncthreads();
    // prefetch Wk -> B0 (G3)
#pragma unroll
    for (int t = 0; t < 16; ++t) { int id4 = tid + t * 256; cpa16(sb + (O_B0 + id4 * 4) * 4, wfrag[2] + id4 * 4); }
    CPC();
    CPW(1); __syncthreads();    // residual ready

    // epilogue2: out_edge = LN2(edge + relu(LN1(c + be)))
    {
        float sv[2][2] = {{0,0},{0,0}}, qv[2][2] = {{0,0},{0,0}};
#pragma unroll
        for (int mt = 0; mt < 2; ++mt)
#pragma unroll
            for (int nt = 0; nt < 8; ++nt) {
                int col = wn * 64 + nt * 8 + t2;
                float b0 = __ldg(&beb[col]), b1 = __ldg(&beb[col + 1]);
                c[mt][nt][0] += b0; c[mt][nt][1] += b1;
                c[mt][nt][2] += b0; c[mt][nt][3] += b1;
                sv[mt][0] += c[mt][nt][0] + c[mt][nt][1];
                qv[mt][0] += c[mt][nt][0]*c[mt][nt][0] + c[mt][nt][1]*c[mt][nt][1];
                sv[mt][1] += c[mt][nt][2] + c[mt][nt][3];
                qv[mt][1] += c[mt][nt][2]*c[mt][nt][2] + c[mt][nt][3]*c[mt][nt][3];
            }
        float mean[2][2], rstd[2][2];
        ROWSTATS(sv, qv, mean, rstd);
        float sv2[2][2] = {{0,0},{0,0}}, qv2[2][2] = {{0,0},{0,0}};
#pragma unroll
        for (int mt = 0; mt < 2; ++mt) {
            int rA = wm * 32 + mt * 16 + g;
#pragma unroll
            for (int nt = 0; nt < 8; ++nt) {
                int col = wn * 64 + nt * 8 + t2;
                float ga0 = __ldg(&g1[col]), ga1 = __ldg(&g1[col + 1]);
                float bb0 = __ldg(&be1[col]), bb1 = __ldg(&be1[col + 1]);
                float w00 = fmaxf((c[mt][nt][0]-mean[mt][0])*rstd[mt][0]*ga0+bb0, 0.f) + sm[O_B1 + SWZ(rA, col)];
                float w01 = fmaxf((c[mt][nt][1]-mean[mt][0])*rstd[mt][0]*ga1+bb1, 0.f) + sm[O_B1 + SWZ(rA, col + 1)];
                float w10 = fmaxf((c[mt][nt][2]-mean[mt][1])*rstd[mt][1]*ga0+bb0, 0.f) + sm[O_B1 + SWZ(rA + 8, col)];
                float w11 = fmaxf((c[mt][nt][3]-mean[mt][1])*rstd[mt][1]*ga1+bb1, 0.f) + sm[O_B1 + SWZ(rA + 8, col + 1)];
                c[mt][nt][0] = w00; c[mt][nt][1] = w01; c[mt][nt][2] = w10; c[mt][nt][3] = w11;
                sv2[mt][0] += w00 + w01; qv2[mt][0] += w00*w00 + w01*w01;
                sv2[mt][1] += w10 + w11; qv2[mt][1] += w10*w10 + w11*w11;
            }
        }
        ROWSTATS(sv2, qv2, mean, rstd);
#pragma unroll
        for (int mt = 0; mt < 2; ++mt) {
            int rA = wm * 32 + mt * 16 + g;
#pragma unroll
            for (int nt = 0; nt < 8; ++nt) {
                int col = wn * 64 + nt * 8 + t2;
                float ga0 = __ldg(&g2[col]), ga1 = __ldg(&g2[col + 1]);
                float bb0 = __ldg(&be2[col]), bb1 = __ldg(&be2[col + 1]);
                *(float2*)&oe[(r0 + rA) * Dd + col] =
                    make_float2((c[mt][nt][0]-mean[mt][0])*rstd[mt][0]*ga0+bb0,
                                (c[mt][nt][1]-mean[mt][0])*rstd[mt][0]*ga1+bb1);
                *(float2*)&oe[(r0 + rA + 8) * Dd + col] =
                    make_float2((c[mt][nt][2]-mean[mt][1])*rstd[mt][1]*ga0+bb0,
                                (c[mt][nt][3]-mean[mt][1])*rstd[mt][1]*ga1+bb1);
            }
        }
    }
    CPW(0); __syncthreads();    // Wk ready

    mma_tile(sm + O_A, sm + O_B0, c);     // K GEMM
    __syncthreads();
    // prefetch Wv -> B0 (G4)
#pragma unroll
    for (int t = 0; t < 16; ++t) { int id4 = tid + t * 256; cpa16(sb + (O_B0 + id4 * 4) * 4, wfrag[3] + id4 * 4); }
    CPC();
    // write K (transposed) from fragments
#pragma unroll
    for (int mt = 0; mt < 2; ++mt) {
        int rA = wm * 32 + mt * 16 + g;
#pragma unroll
        for (int nt = 0; nt < 8; ++nt) {
            int col = wn * 64 + nt * 8 + t2;
            float b0 = __ldg(&bk[col]), b1 = __ldg(&bk[col + 1]);
            *(float2*)&sc_K[((size_t)(jn0 + rA) * Nn + ib) * Dd + col] =
                make_float2(c[mt][nt][0] + b0, c[mt][nt][1] + b1);
            *(float2*)&sc_K[((size_t)(jn0 + rA + 8) * Nn + ib) * Dd + col] =
                make_float2(c[mt][nt][2] + b0, c[mt][nt][3] + b1);
        }
    }
    CPW(0); __syncthreads();    // Wv ready

    mma_tile(sm + O_A, sm + O_B0, c);     // V GEMM
#pragma unroll
    for (int mt = 0; mt < 2; ++mt) {
        int rA = wm * 32 + mt * 16 + g;
#pragma unroll
        for (int nt = 0; nt < 8; ++nt) {
            int col = wn * 64 + nt * 8 + t2;
            float b0 = __ldg(&bv[col]), b1 = __ldg(&bv[col + 1]);
            *(float2*)&sc_V[((size_t)(jn0 + rA) * Nn + ib) * Dd + col] =
                make_float2(c[mt][nt][0] + b0, c[mt][nt][1] + b1);
            *(float2*)&sc_V[((size_t)(jn0 + rA + 8) * Nn + ib) * Dd + col] =
                make_float2(c[mt][nt][2] + b0, c[mt][nt][3] + b1);
        }
    }
}

// ---------- attention per batch ----------
__global__ void k_attn(const unsigned char* __restrict__ mask) {
    const int n = blockIdx.x;
    const int tid = threadIdx.x;
    const int w = tid >> 5, lane = tid & 31;
    __shared__ float q_s[Dd];
    __shared__ float sc[Hh * Nn];
    __shared__ float red2[256];

    if (tid < Dd) q_s[tid] = sc_q[n * Dd + tid];
    __syncthreads();
    float4 qv = *(const float4*)&q_s[lane * 4];
    for (int m = w; m < Nn; m += 8) {
        const float* kp = &sc_K[((size_t)n * Nn + m) * Dd];
        float4 kd = *(const float4*)&kp[lane * 4];
        float p = qv.x * kd.x + qv.y * kd.y + qv.z * kd.z + qv.w * kd.w;
        p += __shfl_xor_sync(0xffffffffu, p, 1);
        p += __shfl_xor_sync(0xffffffffu, p, 2);
        if ((lane & 3) == 0) {
            int h = lane >> 2;
            sc[h * Nn + m] = mask[n * Nn + m] ? -INFINITY : p * 0.25f;
        }
    }
    __syncthreads();
    {
        int h = w;
        float mx = -INFINITY;
#pragma unroll
        for (int t = 0; t < 16; ++t) mx = fmaxf(mx, sc[h * Nn + lane + t * 32]);
#pragma unroll
        for (int off = 16; off >= 1; off >>= 1) mx = fmaxf(mx, __shfl_xor_sync(0xffffffffu, mx, off));
        float sum = 0.f;
#pragma unroll
        for (int t = 0; t < 16; ++t) {
            float e = __expf(sc[h * Nn + lane + t * 32] - mx);
            sc[h * Nn + lane + t * 32] = e; sum += e;
        }
#pragma unroll
        for (int off = 16; off >= 1; off >>= 1) sum += __shfl_xor_sync(0xffffffffu, sum, off);
        float inv = 1.f / sum;
#pragma unroll
        for (int t = 0; t < 16; ++t) sc[h * Nn + lane + t * 32] *= inv;
    }
    __syncthreads();
    {
        int c = tid & 127, half = tid >> 7, h = c >> 4;
        const float* vb = &sc_V[((size_t)n * Nn + half * 256) * Dd + c];
        const float* ap = &sc[h * Nn + half * 256];
        float acc = 0.f;
#pragma unroll 8
        for (int m = 0; m < 256; ++m) acc = fmaf(ap[m], vb[(size_t)m * Dd], acc);
        red2[tid] = acc;
        __syncthreads();
        if (tid < 128) sc_o[n * Dd + tid] = red2[tid] + red2[tid + 128];
    }
}

// ---------- final: out-proj + LN + FFN + LN ----------
__device__ __forceinline__ float bsum128(float v, float* tmp) {
    int lane = threadIdx.x & 31, wid = threadIdx.x >> 5;
#pragma unroll
    for (int off = 16; off >= 1; off >>= 1) v += __shfl_xor_sync(0xffffffffu, v, off);
    if (lane == 0) tmp[wid] = v;
    __syncthreads();
    float s = tmp[0] + tmp[1] + tmp[2] + tmp[3];
    __syncthreads();
    return s;
}
__global__ void k_final(const float* __restrict__ node,
                        const float* __restrict__ Wo, const float* __restrict__ bo,
                        const float* __restrict__ g2, const float* __restrict__ be2,
                        const float* __restrict__ W1, const float* __restrict__ b1,
                        const float* __restrict__ W2, const float* __restrict__ b2,
                        const float* __restrict__ g3, const float* __restrict__ be3,
                        float* __restrict__ out_x) {
    const int n = blockIdx.x;
    const int c = threadIdx.x;
    __shared__ float os[Dd], xs[Dd], hs[Df], tmp[4];
    os[c] = sc_o[n * Dd + c];
    __syncthreads();
    float t = bo[c];
#pragma unroll 8
    for (int k = 0; k < Dd; ++k) t = fmaf(os[k], Wo[k * Dd + c], t);
    float x = node[n * Dd + c] + t;
    float mean = bsum128(x, tmp) * (1.f / 128.f);
    float d = x - mean;
    float var = bsum128(d * d, tmp) * (1.f / 128.f);
    float xn = d * rsqrtf(var + 1e-5f) * g2[c] + be2[c];
    xs[c] = xn;
    __syncthreads();
    float h0 = b1[c], h1 = b1[c + 128];
#pragma unroll 8
    for (int k = 0; k < Dd; ++k) {
        float xv = xs[k];
        h0 = fmaf(xv, W1[k * Df + c], h0);
        h1 = fmaf(xv, W1[k * Df + c + 128], h1);
    }
    hs[c] = fmaxf(h0, 0.f);
    hs[c + 128] = fmaxf(h1, 0.f);
    __syncthreads();
    float y = b2[c];
#pragma unroll 8
    for (int f = 0; f < Df; ++f) y = fmaf(hs[f], W2[f * Dd + c], y);
    float z = xn + y;
    mean = bsum128(z, tmp) * (1.f / 128.f);
    d = z - mean;
    var = bsum128(d * d, tmp) * (1.f / 128.f);
    out_x[n * Dd + c] = d * rsqrtf(var + 1e-5f) * g3[c] + be3[c];
}

// ---------- host ----------
extern "C" void kernel_launch(void* const* d_in, const int* in_sizes, int n_in,
                              void* d_out, int out_size) {
    const float* node = (const float*)d_in[0];
    const float* edge = (const float*)d_in[1];
    const unsigned char* mask = (const unsigned char*)d_in[2];
    const float* W_mem = (const float*)d_in[3];
    const float* b_mem = (const float*)d_in[4];
    const float* g_mem = (const float*)d_in[5];
    const float* be_mem = (const float*)d_in[6];
    const float* W_e = (const float*)d_in[7];
    const float* b_e = (const float*)d_in[8];
    const float* g_e1 = (const float*)d_in[9];
    const float* be_e1 = (const float*)d_in[10];
    const float* g_e2 = (const float*)d_in[11];
    const float* be_e2 = (const float*)d_in[12];
    const float* Wq = (const float*)d_in[13];
    const float* bq = (const float*)d_in[14];
    const float* Wk = (const float*)d_in[15];
    const float* bk = (const float*)d_in[16];
    const float* Wv = (const float*)d_in[17];
    const float* bv = (const float*)d_in[18];
    const float* Wo = (const float*)d_in[19];
    const float* bo = (const float*)d_in[20];
    const float* W1 = (const float*)d_in[21];
    const float* b1 = (const float*)d_in[22];
    const float* W2 = (const float*)d_in[23];
    const float* b2 = (const float*)d_in[24];
    const float* g2 = (const float*)d_in[25];
    const float* be2 = (const float*)d_in[26];
    const float* g3 = (const float*)d_in[27];
    const float* be3 = (const float*)d_in[28];

    float* out = (float*)d_out;
    float* out_x = out;
    float* out_edge = out + Nn * Dd;

    static int init = 0;
    if (!init) {
        cudaFuncSetAttribute(k_prep, cudaFuncAttributeMaxDynamicSharedMemorySize, 128 * 129 * 4);
        cudaFuncSetAttribute(k_fused, cudaFuncAttributeMaxDynamicSharedMemorySize, DYN);
        init = 1;
    }

    k_prep<<<4, 256, 128 * 129 * 4>>>(W_mem, W_e, Wk, Wv);
    k_small<<<Nn, Dd>>>(node, W_mem, Wq, bq);
    k_fused<<<NT, 256, DYN>>>(edge, b_mem, g_mem, be_mem,
                              b_e, g_e1, be_e1, g_e2, be_e2, bk, bv, out_edge);
    k_attn<<<Nn, 256>>>(mask);
    k_final<<<Nn, 128>>>(node, Wo, bo, g2, be2, W1, b1, W2, b2, g3, be3, out_x);
}

// round 8
// speedup vs baseline: 2.2688x; 1.0205x over previous
#include <cuda_runtime.h>
#include <math.h>
#include <stdint.h>

#define Nn 512
#define Dd 128
#define Df 256
#define Hh 8
#define ROWS (Nn*Nn)
#define NT 4096                   // 64-row tiles

__device__ float sc_K[(size_t)ROWS * Dd];
__device__ float sc_V[(size_t)ROWS * Dd];
__device__ float sc_S[Nn * Dd];
__device__ float sc_T[Nn * Dd];
__device__ float sc_q[Nn * Dd];
__device__ float sc_o[Nn * Dd];
__device__ float wfrag[4][16384];   // Wm_edge, We, Wk, Wv in tf32 frag layout

// dynamic smem float offsets (k_fused)
#define O_A  0                    // 8192: A fragments (64x128)
#define O_B0 8192                 // 16384: B fragments
#define O_RS 24576                // 256: LN partial sums (64 rows x 4 warps)
#define O_RQ 24832                // 256
#define O_P  25088                // 128: bm + T row
#define O_G  25216                // 9*128 param vectors
#define SMF  26368
#define DYN  (SMF * 4)            // 105472 bytes -> 2 CTAs/SM

// O_G sub-offsets
#define G_GM  (O_G + 0)
#define G_BEM (O_G + 128)
#define G_G1  (O_G + 256)
#define G_BE1 (O_G + 384)
#define G_G2  (O_G + 512)
#define G_BE2 (O_G + 640)
#define G_BEB (O_G + 768)
#define G_BK  (O_G + 896)
#define G_BV  (O_G + 1024)

__device__ __forceinline__ uint32_t tf32c(float x) {
    uint32_t y; asm("cvt.rna.tf32.f32 %0, %1;" : "=r"(y) : "f"(x)); return y;
}
__device__ __forceinline__ float tf32f(float x) { return __uint_as_float(tf32c(x)); }

__device__ __forceinline__ uint32_t smem_u32(const void* p) {
    uint32_t a;
    asm("{ .reg .u64 t; cvta.to.shared.u64 t, %1; cvt.u32.u64 %0, t; }" : "=r"(a) : "l"(p));
    return a;
}
__device__ __forceinline__ void cpa16(uint32_t s, const void* g) {
    asm volatile("cp.async.cg.shared.global [%0], [%1], 16;" :: "r"(s), "l"(g));
}
#define CPC() asm volatile("cp.async.commit_group;" ::: "memory")
#define CPW(n) asm volatile("cp.async.wait_group %0;" :: "n"(n) : "memory")

__device__ __forceinline__ void mma8(float* c, const uint32_t* a, const uint32_t* b) {
    asm volatile(
        "mma.sync.aligned.m16n8k8.row.col.f32.tf32.tf32.f32 "
        "{%0,%1,%2,%3},{%4,%5,%6,%7},{%8,%9},{%0,%1,%2,%3};"
        : "+f"(c[0]), "+f"(c[1]), "+f"(c[2]), "+f"(c[3])
        : "r"(a[0]), "r"(a[1]), "r"(a[2]), "r"(a[3]), "r"(b[0]), "r"(b[1]));
}

// A-fragment float index for element (row r, col c), r<64
__device__ __forceinline__ int AFR(int r, int c) {
    return (((r >> 4) * 16 + (c >> 3)) * 32 + ((r & 7) << 2) + (c & 3)) * 4
           + ((r >> 3) & 1) + (((c >> 2) & 1) << 1);
}

// 64x128x128 tile MMA: 8 warps in 2(m) x 4(n); warp tile 32x32
__device__ __forceinline__ void mma_tile(const float* sA, const float* sB, float c[2][4][4]) {
    int tid = threadIdx.x, w = tid >> 5, lane = tid & 31;
    int wm = w >> 2, wn = w & 3;
#pragma unroll
    for (int mt = 0; mt < 2; ++mt)
#pragma unroll
        for (int nt = 0; nt < 4; ++nt)
#pragma unroll
            for (int i = 0; i < 4; ++i) c[mt][nt][i] = 0.f;
#pragma unroll
    for (int kc = 0; kc < 16; ++kc) {
        uint32_t a[2][4];
#pragma unroll
        for (int mt = 0; mt < 2; ++mt) {
            float4 v = *(const float4*)&sA[(((wm * 2 + mt) * 16 + kc) * 32 + lane) * 4];
            a[mt][0] = __float_as_uint(v.x); a[mt][1] = __float_as_uint(v.y);
            a[mt][2] = __float_as_uint(v.z); a[mt][3] = __float_as_uint(v.w);
        }
#pragma unroll
        for (int nt = 0; nt < 4; ++nt) {
            float2 bv = *(const float2*)&sB[(((wn * 4 + nt) * 16 + kc) * 32 + lane) * 2];
            uint32_t b[2] = {__float_as_uint(bv.x), __float_as_uint(bv.y)};
            mma8(c[0][nt], a[0], b);
            mma8(c[1][nt], a[1], b);
        }
    }
}

// per-row LN stats: quad shfl + 4-warp smem combine (rows 0..63)
#define ROWSTATS(sv, qv, mean, rstd) do { \
    _Pragma("unroll") for (int _mt = 0; _mt < 2; ++_mt) \
    _Pragma("unroll") for (int _h = 0; _h < 2; ++_h) { \
        float _s = (sv)[_mt][_h], _q = (qv)[_mt][_h]; \
        _s += __shfl_xor_sync(0xffffffffu, _s, 1); _q += __shfl_xor_sync(0xffffffffu, _q, 1); \
        _s += __shfl_xor_sync(0xffffffffu, _s, 2); _q += __shfl_xor_sync(0xffffffffu, _q, 2); \
        (sv)[_mt][_h] = _s; (qv)[_mt][_h] = _q; } \
    if ((lane & 3) == 0) { \
        _Pragma("unroll") for (int _mt = 0; _mt < 2; ++_mt) \
        _Pragma("unroll") for (int _h = 0; _h < 2; ++_h) { \
            int _row = wm * 32 + _mt * 16 + g + _h * 8; \
            sm[O_RS + _row * 4 + wn] = (sv)[_mt][_h]; \
            sm[O_RQ + _row * 4 + wn] = (qv)[_mt][_h]; } } \
    __syncthreads(); \
    _Pragma("unroll") for (int _mt = 0; _mt < 2; ++_mt) \
    _Pragma("unroll") for (int _h = 0; _h < 2; ++_h) { \
        int _row = wm * 32 + _mt * 16 + g + _h * 8; \
        float _ts = sm[O_RS + _row * 4] + sm[O_RS + _row * 4 + 1] + sm[O_RS + _row * 4 + 2] + sm[O_RS + _row * 4 + 3]; \
        float _tq = sm[O_RQ + _row * 4] + sm[O_RQ + _row * 4 + 1] + sm[O_RQ + _row * 4 + 2] + sm[O_RQ + _row * 4 + 3]; \
        float _mn = _ts * (1.f / 128.f); \
        (mean)[_mt][_h] = _mn; \
        (rstd)[_mt][_h] = rsqrtf(fmaxf(_tq * (1.f / 128.f) - _mn * _mn, 0.f) + 1e-5f); } \
    __syncthreads(); \
} while (0)

// ---------- weight prep ----------
__global__ void k_prep(const float* __restrict__ Wm, const float* __restrict__ We,
                       const float* __restrict__ Wk, const float* __restrict__ Wv) {
    extern __shared__ float ws[];   // [128][129]
    const float* W = blockIdx.x == 0 ? Wm : blockIdx.x == 1 ? We : blockIdx.x == 2 ? Wk : Wv;
    int tid = threadIdx.x;
    for (int t = 0; t < 16; ++t) {
        int id = tid + t * 256;
        int k = id >> 5, n4 = (id & 31) << 2;
        float4 v = *(const float4*)&W[k * Dd + n4];
        ws[k * 129 + n4] = v.x; ws[k * 129 + n4 + 1] = v.y;
        ws[k * 129 + n4 + 2] = v.z; ws[k * 129 + n4 + 3] = v.w;
    }
    __syncthreads();
    float* out = wfrag[blockIdx.x];
    for (int t = 0; t < 32; ++t) {
        int id = tid + t * 256;
        int lane = id & 31, kb = (id >> 5) & 15, nb = id >> 9;
        int n = nb * 8 + (lane >> 2), k = kb * 8 + (lane & 3);
        float2 o;
        o.x = tf32f(ws[k * 129 + n]);
        o.y = tf32f(ws[(k + 4) * 129 + n]);
        *(float2*)&out[id * 2] = o;
    }
}

// ---------- S, T, q ----------
__global__ void k_small(const float* __restrict__ node, const float* __restrict__ Wmem,
                        const float* __restrict__ Wq, const float* __restrict__ bq) {
    int n = blockIdx.x, c = threadIdx.x;
    __shared__ float ns[Dd];
    ns[c] = node[n * Dd + c];
    __syncthreads();
    float s = 0.f, t = 0.f, q = 0.f;
#pragma unroll 8
    for (int k = 0; k < Dd; ++k) {
        float nv = ns[k];
        s = fmaf(nv, Wmem[(Dd + k) * Dd + c], s);
        t = fmaf(nv, Wmem[(2 * Dd + k) * Dd + c], t);
        q = fmaf(nv, Wq[k * Dd + c], q);
    }
    sc_S[n * Dd + c] = s; sc_T[n * Dd + c] = t; sc_q[n * Dd + c] = q + bq[c];
}

// ---------- fused tile kernel: 64-row tile -> memory -> edge_out, K, V ----------
__global__ __launch_bounds__(256, 2) void k_fused(
    const float* __restrict__ edge,
    const float* __restrict__ bm, const float* __restrict__ gm, const float* __restrict__ bem,
    const float* __restrict__ beb, const float* __restrict__ g1, const float* __restrict__ be1,
    const float* __restrict__ g2, const float* __restrict__ be2,
    const float* __restrict__ bk, const float* __restrict__ bv,
    float* __restrict__ oe)
{
    extern __shared__ float sm[];
    const uint32_t sb = smem_u32(sm);
    const int tid = threadIdx.x, w = tid >> 5, lane = tid & 31;
    const int wm = w >> 2, wn = w & 3, g = lane >> 2, t2 = (lane & 3) << 1;
    const int ib = blockIdx.x >> 3, jn0 = (blockIdx.x & 7) << 6;
    const size_t r0 = (size_t)blockIdx.x * 64;

    // prefetch Wm -> B0
#pragma unroll
    for (int t = 0; t < 16; ++t) { int id4 = tid + t * 256; cpa16(sb + (O_B0 + id4 * 4) * 4, wfrag[0] + id4 * 4); }
    CPC();

    // A <- edge (tf32 frags)
#pragma unroll
    for (int t = 0; t < 8; ++t) {
        int id = tid + t * 256;
        int r = id >> 5, c4 = (id & 31) << 2;
        float4 v = *(const float4*)&edge[(r0 + r) * Dd + c4];
        int base = AFR(r, c4);
        sm[O_A + base + 0] = tf32f(v.x); sm[O_A + base + 4] = tf32f(v.y);
        sm[O_A + base + 8] = tf32f(v.z); sm[O_A + base + 12] = tf32f(v.w);
    }
    if (tid < Dd) {
        sm[O_P + tid]  = bm[tid] + sc_T[ib * Dd + tid];
        sm[G_GM + tid] = gm[tid];  sm[G_BEM + tid] = bem[tid];
        sm[G_G1 + tid] = g1[tid];  sm[G_BE1 + tid] = be1[tid];
        sm[G_G2 + tid] = g2[tid];  sm[G_BE2 + tid] = be2[tid];
        sm[G_BEB + tid] = beb[tid]; sm[G_BK + tid] = bk[tid]; sm[G_BV + tid] = bv[tid];
    }
    CPW(0); __syncthreads();

    float c[2][4][4];
    mma_tile(sm + O_A, sm + O_B0, c);
    __syncthreads();
    // prefetch We -> B0
#pragma unroll
    for (int t = 0; t < 16; ++t) { int id4 = tid + t * 256; cpa16(sb + (O_B0 + id4 * 4) * 4, wfrag[1] + id4 * 4); }
    CPC();

    // epilogue1: memory = relu(LN(c + (bm+T) + S)), rewrite A frags
    {
        float sv[2][2] = {{0,0},{0,0}}, qv[2][2] = {{0,0},{0,0}};
#pragma unroll
        for (int mt = 0; mt < 2; ++mt) {
            int rA = wm * 32 + mt * 16 + g;
#pragma unroll
            for (int nt = 0; nt < 4; ++nt) {
                int col = wn * 32 + nt * 8 + t2;
                float p0 = sm[O_P + col], p1 = sm[O_P + col + 1];
                float2 s0 = *(const float2*)&sc_S[(jn0 + rA) * Dd + col];
                float2 s1 = *(const float2*)&sc_S[(jn0 + rA + 8) * Dd + col];
                c[mt][nt][0] += p0 + s0.x; c[mt][nt][1] += p1 + s0.y;
                c[mt][nt][2] += p0 + s1.x; c[mt][nt][3] += p1 + s1.y;
                sv[mt][0] += c[mt][nt][0] + c[mt][nt][1];
                qv[mt][0] += c[mt][nt][0]*c[mt][nt][0] + c[mt][nt][1]*c[mt][nt][1];
                sv[mt][1] += c[mt][nt][2] + c[mt][nt][3];
                qv[mt][1] += c[mt][nt][2]*c[mt][nt][2] + c[mt][nt][3]*c[mt][nt][3];
            }
        }
        float mean[2][2], rstd[2][2];
        ROWSTATS(sv, qv, mean, rstd);
#pragma unroll
        for (int mt = 0; mt < 2; ++mt) {
            int rA = wm * 32 + mt * 16 + g;
#pragma unroll
            for (int nt = 0; nt < 4; ++nt) {
                int col = wn * 32 + nt * 8 + t2;
                float ga0 = sm[G_GM + col], ga1 = sm[G_GM + col + 1];
                float bb0 = sm[G_BEM + col], bb1 = sm[G_BEM + col + 1];
                sm[O_A + AFR(rA, col)]     = tf32f(fmaxf((c[mt][nt][0]-mean[mt][0])*rstd[mt][0]*ga0+bb0, 0.f));
                sm[O_A + AFR(rA, col + 1)] = tf32f(fmaxf((c[mt][nt][1]-mean[mt][0])*rstd[mt][0]*ga1+bb1, 0.f));
                sm[O_A + AFR(rA + 8, col)]     = tf32f(fmaxf((c[mt][nt][2]-mean[mt][1])*rstd[mt][1]*ga0+bb0, 0.f));
                sm[O_A + AFR(rA + 8, col + 1)] = tf32f(fmaxf((c[mt][nt][3]-mean[mt][1])*rstd[mt][1]*ga1+bb1, 0.f));
            }
        }
    }
    CPW(0); __syncthreads();    // We ready + A rewritten

    mma_tile(sm + O_A, sm + O_B0, c);     // edge branch GEMM
    __syncthreads();
    // prefetch Wk -> B0
#pragma unroll
    for (int t = 0; t < 16; ++t) { int id4 = tid + t * 256; cpa16(sb + (O_B0 + id4 * 4) * 4, wfrag[2] + id4 * 4); }
    CPC();

    // epilogue2: out_edge = LN2(edge + relu(LN1(c + beb)))
    {
        float sv[2][2] = {{0,0},{0,0}}, qv[2][2] = {{0,0},{0,0}};
#pragma unroll
        for (int mt = 0; mt < 2; ++mt)
#pragma unroll
            for (int nt = 0; nt < 4; ++nt) {
                int col = wn * 32 + nt * 8 + t2;
                float b0 = sm[G_BEB + col], b1 = sm[G_BEB + col + 1];
                c[mt][nt][0] += b0; c[mt][nt][1] += b1;
                c[mt][nt][2] += b0; c[mt][nt][3] += b1;
                sv[mt][0] += c[mt][nt][0] + c[mt][nt][1];
                qv[mt][0] += c[mt][nt][0]*c[mt][nt][0] + c[mt][nt][1]*c[mt][nt][1];
                sv[mt][1] += c[mt][nt][2] + c[mt][nt][3];
                qv[mt][1] += c[mt][nt][2]*c[mt][nt][2] + c[mt][nt][3]*c[mt][nt][3];
            }
        float mean[2][2], rstd[2][2];
        ROWSTATS(sv, qv, mean, rstd);
        float sv2[2][2] = {{0,0},{0,0}}, qv2[2][2] = {{0,0},{0,0}};
#pragma unroll
        for (int mt = 0; mt < 2; ++mt) {
            int rA = wm * 32 + mt * 16 + g;
#pragma unroll
            for (int nt = 0; nt < 4; ++nt) {
                int col = wn * 32 + nt * 8 + t2;
                float ga0 = sm[G_G1 + col], ga1 = sm[G_G1 + col + 1];
                float bb0 = sm[G_BE1 + col], bb1 = sm[G_BE1 + col + 1];
                float2 e0 = *(const float2*)&edge[(r0 + rA) * Dd + col];
                float2 e1 = *(const float2*)&edge[(r0 + rA + 8) * Dd + col];
                float w00 = fmaxf((c[mt][nt][0]-mean[mt][0])*rstd[mt][0]*ga0+bb0, 0.f) + e0.x;
                float w01 = fmaxf((c[mt][nt][1]-mean[mt][0])*rstd[mt][0]*ga1+bb1, 0.f) + e0.y;
                float w10 = fmaxf((c[mt][nt][2]-mean[mt][1])*rstd[mt][1]*ga0+bb0, 0.f) + e1.x;
                float w11 = fmaxf((c[mt][nt][3]-mean[mt][1])*rstd[mt][1]*ga1+bb1, 0.f) + e1.y;
                c[mt][nt][0] = w00; c[mt][nt][1] = w01; c[mt][nt][2] = w10; c[mt][nt][3] = w11;
                sv2[mt][0] += w00 + w01; qv2[mt][0] += w00*w00 + w01*w01;
                sv2[mt][1] += w10 + w11; qv2[mt][1] += w10*w10 + w11*w11;
            }
        }
        ROWSTATS(sv2, qv2, mean, rstd);
#pragma unroll
        for (int mt = 0; mt < 2; ++mt) {
            int rA = wm * 32 + mt * 16 + g;
#pragma unroll
            for (int nt = 0; nt < 4; ++nt) {
                int col = wn * 32 + nt * 8 + t2;
                float ga0 = sm[G_G2 + col], ga1 = sm[G_G2 + col + 1];
                float bb0 = sm[G_BE2 + col], bb1 = sm[G_BE2 + col + 1];
                *(float2*)&oe[(r0 + rA) * Dd + col] =
                    make_float2((c[mt][nt][0]-mean[mt][0])*rstd[mt][0]*ga0+bb0,
                                (c[mt][nt][1]-mean[mt][0])*rstd[mt][0]*ga1+bb1);
                *(float2*)&oe[(r0 + rA + 8) * Dd + col] =
                    make_float2((c[mt][nt][2]-mean[mt][1])*rstd[mt][1]*ga0+bb0,
                                (c[mt][nt][3]-mean[mt][1])*rstd[mt][1]*ga1+bb1);
            }
        }
    }
    CPW(0); __syncthreads();    // Wk ready

    mma_tile(sm + O_A, sm + O_B0, c);     // K GEMM
    __syncthreads();
    // prefetch Wv -> B0
#pragma unroll
    for (int t = 0; t < 16; ++t) { int id4 = tid + t * 256; cpa16(sb + (O_B0 + id4 * 4) * 4, wfrag[3] + id4 * 4); }
    CPC();
    // write K (transposed)
#pragma unroll
    for (int mt = 0; mt < 2; ++mt) {
        int rA = wm * 32 + mt * 16 + g;
#pragma unroll
        for (int nt = 0; nt < 4; ++nt) {
            int col = wn * 32 + nt * 8 + t2;
            float b0 = sm[G_BK + col], b1 = sm[G_BK + col + 1];
            *(float2*)&sc_K[((size_t)(jn0 + rA) * Nn + ib) * Dd + col] =
                make_float2(c[mt][nt][0] + b0, c[mt][nt][1] + b1);
            *(float2*)&sc_K[((size_t)(jn0 + rA + 8) * Nn + ib) * Dd + col] =
                make_float2(c[mt][nt][2] + b0, c[mt][nt][3] + b1);
        }
    }
    CPW(0); __syncthreads();    // Wv ready

    mma_tile(sm + O_A, sm + O_B0, c);     // V GEMM
#pragma unroll
    for (int mt = 0; mt < 2; ++mt) {
        int rA = wm * 32 + mt * 16 + g;
#pragma unroll
        for (int nt = 0; nt < 4; ++nt) {
            int col = wn * 32 + nt * 8 + t2;
            float b0 = sm[G_BV + col], b1 = sm[G_BV + col + 1];
            *(float2*)&sc_V[((size_t)(jn0 + rA) * Nn + ib) * Dd + col] =
                make_float2(c[mt][nt][0] + b0, c[mt][nt][1] + b1);
            *(float2*)&sc_V[((size_t)(jn0 + rA + 8) * Nn + ib) * Dd + col] =
                make_float2(c[mt][nt][2] + b0, c[mt][nt][3] + b1);
        }
    }
}

// ---------- attention per batch ----------
__global__ void k_attn(const unsigned char* __restrict__ mask) {
    const int n = blockIdx.x;
    const int tid = threadIdx.x;
    const int w = tid >> 5, lane = tid & 31;
    __shared__ float q_s[Dd];
    __shared__ float sc[Hh * Nn];
    __shared__ float red2[256];

    if (tid < Dd) q_s[tid] = sc_q[n * Dd + tid];
    __syncthreads();
    float4 qv = *(const float4*)&q_s[lane * 4];
    for (int m = w; m < Nn; m += 8) {
        const float* kp = &sc_K[((size_t)n * Nn + m) * Dd];
        float4 kd = *(const float4*)&kp[lane * 4];
        float p = qv.x * kd.x + qv.y * kd.y + qv.z * kd.z + qv.w * kd.w;
        p += __shfl_xor_sync(0xffffffffu, p, 1);
        p += __shfl_xor_sync(0xffffffffu, p, 2);
        if ((lane & 3) == 0) {
            int h = lane >> 2;
            sc[h * Nn + m] = mask[n * Nn + m] ? -INFINITY : p * 0.25f;
        }
    }
    __syncthreads();
    {
        int h = w;
        float mx = -INFINITY;
#pragma unroll
        for (int t = 0; t < 16; ++t) mx = fmaxf(mx, sc[h * Nn + lane + t * 32]);
#pragma unroll
        for (int off = 16; off >= 1; off >>= 1) mx = fmaxf(mx, __shfl_xor_sync(0xffffffffu, mx, off));
        float sum = 0.f;
#pragma unroll
        for (int t = 0; t < 16; ++t) {
            float e = __expf(sc[h * Nn + lane + t * 32] - mx);
            sc[h * Nn + lane + t * 32] = e; sum += e;
        }
#pragma unroll
        for (int off = 16; off >= 1; off >>= 1) sum += __shfl_xor_sync(0xffffffffu, sum, off);
        float inv = 1.f / sum;
#pragma unroll
        for (int t = 0; t < 16; ++t) sc[h * Nn + lane + t * 32] *= inv;
    }
    __syncthreads();
    {
        int c = tid & 127, half = tid >> 7, h = c >> 4;
        const float* vb = &sc_V[((size_t)n * Nn + half * 256) * Dd + c];
        const float* ap = &sc[h * Nn + half * 256];
        float acc = 0.f;
#pragma unroll 8
        for (int m = 0; m < 256; ++m) acc = fmaf(ap[m], vb[(size_t)m * Dd], acc);
        red2[tid] = acc;
        __syncthreads();
        if (tid < 128) sc_o[n * Dd + tid] = red2[tid] + red2[tid + 128];
    }
}

// ---------- final: out-proj + LN + FFN + LN ----------
__device__ __forceinline__ float bsum128(float v, float* tmp) {
    int lane = threadIdx.x & 31, wid = threadIdx.x >> 5;
#pragma unroll
    for (int off = 16; off >= 1; off >>= 1) v += __shfl_xor_sync(0xffffffffu, v, off);
    if (lane == 0) tmp[wid] = v;
    __syncthreads();
    float s = tmp[0] + tmp[1] + tmp[2] + tmp[3];
    __syncthreads();
    return s;
}
__global__ void k_final(const float* __restrict__ node,
                        const float* __restrict__ Wo, const float* __restrict__ bo,
                        const float* __restrict__ g2, const float* __restrict__ be2,
                        const float* __restrict__ W1, const float* __restrict__ b1,
                        const float* __restrict__ W2, const float* __restrict__ b2,
                        const float* __restrict__ g3, const float* __restrict__ be3,
                        float* __restrict__ out_x) {
    const int n = blockIdx.x;
    const int c = threadIdx.x;
    __shared__ float os[Dd], xs[Dd], hs[Df], tmp[4];
    os[c] = sc_o[n * Dd + c];
    __syncthreads();
    float t = bo[c];
#pragma unroll 8
    for (int k = 0; k < Dd; ++k) t = fmaf(os[k], Wo[k * Dd + c], t);
    float x = node[n * Dd + c] + t;
    float mean = bsum128(x, tmp) * (1.f / 128.f);
    float d = x - mean;
    float var = bsum128(d * d, tmp) * (1.f / 128.f);
    float xn = d * rsqrtf(var + 1e-5f) * g2[c] + be2[c];
    xs[c] = xn;
    __syncthreads();
    float h0 = b1[c], h1 = b1[c + 128];
#pragma unroll 8
    for (int k = 0; k < Dd; ++k) {
        float xv = xs[k];
        h0 = fmaf(xv, W1[k * Df + c], h0);
        h1 = fmaf(xv, W1[k * Df + c + 128], h1);
    }
    hs[c] = fmaxf(h0, 0.f);
    hs[c + 128] = fmaxf(h1, 0.f);
    __syncthreads();
    float y = b2[c];
#pragma unroll 8
    for (int f = 0; f < Df; ++f) y = fmaf(hs[f], W2[f * Dd + c], y);
    float z = xn + y;
    mean = bsum128(z, tmp) * (1.f / 128.f);
    d = z - mean;
    var = bsum128(d * d, tmp) * (1.f / 128.f);
    out_x[n * Dd + c] = d * rsqrtf(var + 1e-5f) * g3[c] + be3[c];
}

// ---------- host ----------
extern "C" void kernel_launch(void* const* d_in, const int* in_sizes, int n_in,
                              void* d_out, int out_size) {
    const float* node = (const float*)d_in[0];
    const float* edge = (const float*)d_in[1];
    const unsigned char* mask = (const unsigned char*)d_in[2];
    const float* W_mem = (const float*)d_in[3];
    const float* b_mem = (const float*)d_in[4];
    const float* g_mem = (const float*)d_in[5];
    const float* be_mem = (const float*)d_in[6];
    const float* W_e = (const float*)d_in[7];
    const float* b_e = (const float*)d_in[8];
    const float* g_e1 = (const float*)d_in[9];
    const float* be_e1 = (const float*)d_in[10];
    const float* g_e2 = (const float*)d_in[11];
    const float* be_e2 = (const float*)d_in[12];
    const float* Wq = (const float*)d_in[13];
    const float* bq = (const float*)d_in[14];
    const float* Wk = (const float*)d_in[15];
    const float* bk = (const float*)d_in[16];
    const float* Wv = (const float*)d_in[17];
    const float* bv = (const float*)d_in[18];
    const float* Wo = (const float*)d_in[19];
    const float* bo = (const float*)d_in[20];
    const float* W1 = (const float*)d_in[21];
    const float* b1 = (const float*)d_in[22];
    const float* W2 = (const float*)d_in[23];
    const float* b2 = (const float*)d_in[24];
    const float* g2 = (const float*)d_in[25];
    const float* be2 = (const float*)d_in[26];
    const float* g3 = (const float*)d_in[27];
    const float* be3 = (const float*)d_in[28];

    float* out = (float*)d_out;
    float* out_x = out;
    float* out_edge = out + Nn * Dd;

    static int init = 0;
    if (!init) {
        cudaFuncSetAttribute(k_prep, cudaFuncAttributeMaxDynamicSharedMemorySize, 128 * 129 * 4);
        cudaFuncSetAttribute(k_fused, cudaFuncAttributeMaxDynamicSharedMemorySize, DYN);
        init = 1;
    }

    k_prep<<<4, 256, 128 * 129 * 4>>>(W_mem, W_e, Wk, Wv);
    k_small<<<Nn, Dd>>>(node, W_mem, Wq, bq);
    k_fused<<<NT, 256, DYN>>>(edge, b_mem, g_mem, be_mem,
                              b_e, g_e1, be_e1, g_e2, be_e2, bk, bv, out_edge);
    k_attn<<<Nn, 256>>>(mask);
    k_final<<<Nn, 128>>>(node, Wo, bo, g2, be2, W1, b1, W2, b2, g3, be3, out_x);
}

// round 9
// speedup vs baseline: 2.3460x; 1.0340x over previous
#include <cuda_runtime.h>
#include <cuda_bf16.h>
#include <math.h>
#include <stdint.h>

#define Nn 512
#define Dd 128
#define Df 256
#define Hh 8
#define ROWS (Nn*Nn)
#define NT 4096                   // 64-row tiles

__device__ float sc_S[Nn * Dd];
__device__ float sc_T[Nn * Dd];
__device__ float sc_qk[Nn * Hh * Dd];           // 0.25 * Wk-projected q
__device__ float sc_o[Nn * Dd];
__device__ float wfrag[2][16384];               // Wm_edge, We tf32 frag layout
__device__ uint32_t sc_memt[(size_t)ROWS * 64]; // memory bf16x2, [n][m][c] (67MB)

// k_fused dynamic smem float offsets
#define O_A  0                    // 8192
#define O_B0 8192                 // 16384
#define O_RS 24576                // 256
#define O_RQ 24832                // 256
#define O_P  25088                // 128 (bm + T)
#define O_G  25216                // 7*128
#define SMF  26112
#define DYN  (SMF * 4)            // 104448 B -> 2 CTA/SM

#define G_GM  (O_G + 0)
#define G_BEM (O_G + 128)
#define G_G1  (O_G + 256)
#define G_BE1 (O_G + 384)
#define G_G2  (O_G + 512)
#define G_BE2 (O_G + 640)
#define G_BEB (O_G + 768)

__device__ __forceinline__ uint32_t tf32c(float x) {
    uint32_t y; asm("cvt.rna.tf32.f32 %0, %1;" : "=r"(y) : "f"(x)); return y;
}
__device__ __forceinline__ float tf32f(float x) { return __uint_as_float(tf32c(x)); }

__device__ __forceinline__ uint32_t smem_u32(const void* p) {
    uint32_t a;
    asm("{ .reg .u64 t; cvta.to.shared.u64 t, %1; cvt.u32.u64 %0, t; }" : "=r"(a) : "l"(p));
    return a;
}
__device__ __forceinline__ void cpa16(uint32_t s, const void* g) {
    asm volatile("cp.async.cg.shared.global [%0], [%1], 16;" :: "r"(s), "l"(g));
}
#define CPC() asm volatile("cp.async.commit_group;" ::: "memory")
#define CPW(n) asm volatile("cp.async.wait_group %0;" :: "n"(n) : "memory")

__device__ __forceinline__ void mma8(float* c, const uint32_t* a, const uint32_t* b) {
    asm volatile(
        "mma.sync.aligned.m16n8k8.row.col.f32.tf32.tf32.f32 "
        "{%0,%1,%2,%3},{%4,%5,%6,%7},{%8,%9},{%0,%1,%2,%3};"
        : "+f"(c[0]), "+f"(c[1]), "+f"(c[2]), "+f"(c[3])
        : "r"(a[0]), "r"(a[1]), "r"(a[2]), "r"(a[3]), "r"(b[0]), "r"(b[1]));
}

__device__ __forceinline__ int AFR(int r, int c) {
    return (((r >> 4) * 16 + (c >> 3)) * 32 + ((r & 7) << 2) + (c & 3)) * 4
           + ((r >> 3) & 1) + (((c >> 2) & 1) << 1);
}

// 64x128x128 tile MMA: 8 warps 2(m) x 4(n), warp tile 32x32
__device__ __forceinline__ void mma_tile(const float* sA, const float* sB, float c[2][4][4]) {
    int tid = threadIdx.x, w = tid >> 5, lane = tid & 31;
    int wm = w >> 2, wn = w & 3;
#pragma unroll
    for (int mt = 0; mt < 2; ++mt)
#pragma unroll
        for (int nt = 0; nt < 4; ++nt)
#pragma unroll
            for (int i = 0; i < 4; ++i) c[mt][nt][i] = 0.f;
#pragma unroll
    for (int kc = 0; kc < 16; ++kc) {
        uint32_t a[2][4];
#pragma unroll
        for (int mt = 0; mt < 2; ++mt) {
            float4 v = *(const float4*)&sA[(((wm * 2 + mt) * 16 + kc) * 32 + lane) * 4];
            a[mt][0] = __float_as_uint(v.x); a[mt][1] = __float_as_uint(v.y);
            a[mt][2] = __float_as_uint(v.z); a[mt][3] = __float_as_uint(v.w);
        }
#pragma unroll
        for (int nt = 0; nt < 4; ++nt) {
            float2 bv = *(const float2*)&sB[(((wn * 4 + nt) * 16 + kc) * 32 + lane) * 2];
            uint32_t b[2] = {__float_as_uint(bv.x), __float_as_uint(bv.y)};
            mma8(c[0][nt], a[0], b);
            mma8(c[1][nt], a[1], b);
        }
    }
}

#define ROWSTATS(sv, qv, mean, rstd) do { \
    _Pragma("unroll") for (int _mt = 0; _mt < 2; ++_mt) \
    _Pragma("unroll") for (int _h = 0; _h < 2; ++_h) { \
        float _s = (sv)[_mt][_h], _q = (qv)[_mt][_h]; \
        _s += __shfl_xor_sync(0xffffffffu, _s, 1); _q += __shfl_xor_sync(0xffffffffu, _q, 1); \
        _s += __shfl_xor_sync(0xffffffffu, _s, 2); _q += __shfl_xor_sync(0xffffffffu, _q, 2); \
        (sv)[_mt][_h] = _s; (qv)[_mt][_h] = _q; } \
    if ((lane & 3) == 0) { \
        _Pragma("unroll") for (int _mt = 0; _mt < 2; ++_mt) \
        _Pragma("unroll") for (int _h = 0; _h < 2; ++_h) { \
            int _row = wm * 32 + _mt * 16 + g + _h * 8; \
            sm[O_RS + _row * 4 + wn] = (sv)[_mt][_h]; \
            sm[O_RQ + _row * 4 + wn] = (qv)[_mt][_h]; } } \
    __syncthreads(); \
    _Pragma("unroll") for (int _mt = 0; _mt < 2; ++_mt) \
    _Pragma("unroll") for (int _h = 0; _h < 2; ++_h) { \
        int _row = wm * 32 + _mt * 16 + g + _h * 8; \
        float _ts = sm[O_RS + _row * 4] + sm[O_RS + _row * 4 + 1] + sm[O_RS + _row * 4 + 2] + sm[O_RS + _row * 4 + 3]; \
        float _tq = sm[O_RQ + _row * 4] + sm[O_RQ + _row * 4 + 1] + sm[O_RQ + _row * 4 + 2] + sm[O_RQ + _row * 4 + 3]; \
        float _mn = _ts * (1.f / 128.f); \
        (mean)[_mt][_h] = _mn; \
        (rstd)[_mt][_h] = rsqrtf(fmaxf(_tq * (1.f / 128.f) - _mn * _mn, 0.f) + 1e-5f); } \
    __syncthreads(); \
} while (0)

// ---------- weight prep (Wm, We) ----------
__global__ void k_prep(const float* __restrict__ Wm, const float* __restrict__ We) {
    extern __shared__ float ws[];   // [128][129]
    const float* W = blockIdx.x == 0 ? Wm : We;
    int tid = threadIdx.x;
    for (int t = 0; t < 16; ++t) {
        int id = tid + t * 256;
        int k = id >> 5, n4 = (id & 31) << 2;
        float4 v = *(const float4*)&W[k * Dd + n4];
        ws[k * 129 + n4] = v.x; ws[k * 129 + n4 + 1] = v.y;
        ws[k * 129 + n4 + 2] = v.z; ws[k * 129 + n4 + 3] = v.w;
    }
    __syncthreads();
    float* out = wfrag[blockIdx.x];
    for (int t = 0; t < 32; ++t) {
        int id = tid + t * 256;
        int lane = id & 31, kb = (id >> 5) & 15, nb = id >> 9;
        int n = nb * 8 + (lane >> 2), k = kb * 8 + (lane & 3);
        float2 o;
        o.x = tf32f(ws[k * 129 + n]);
        o.y = tf32f(ws[(k + 4) * 129 + n]);
        *(float2*)&out[id * 2] = o;
    }
}

// ---------- S, T, qk ----------
__global__ void k_small(const float* __restrict__ node, const float* __restrict__ Wmem,
                        const float* __restrict__ Wq, const float* __restrict__ bq,
                        const float* __restrict__ Wk) {
    int n = blockIdx.x, c = threadIdx.x;
    __shared__ float ns[Dd], qs[Dd];
    ns[c] = node[n * Dd + c];
    __syncthreads();
    float s = 0.f, t = 0.f, q = 0.f;
#pragma unroll 8
    for (int k = 0; k < Dd; ++k) {
        float nv = ns[k];
        s = fmaf(nv, Wmem[(Dd + k) * Dd + c], s);
        t = fmaf(nv, Wmem[(2 * Dd + k) * Dd + c], t);
        q = fmaf(nv, Wq[k * Dd + c], q);
    }
    sc_S[n * Dd + c] = s; sc_T[n * Dd + c] = t;
    qs[c] = q + bq[c];
    __syncthreads();
    float a[8] = {0,0,0,0,0,0,0,0};
#pragma unroll
    for (int hd = 0; hd < 128; ++hd)
        a[hd >> 4] = fmaf(Wk[c * Dd + hd], qs[hd], a[hd >> 4]);
#pragma unroll
    for (int h = 0; h < 8; ++h)
        sc_qk[n * 1024 + h * 128 + c] = a[h] * 0.25f;
}

// ---------- fused tile kernel: memory (bf16 out) + edge_out ----------
__global__ __launch_bounds__(256, 2) void k_fused(
    const float* __restrict__ edge,
    const float* __restrict__ bm, const float* __restrict__ gm, const float* __restrict__ bem,
    const float* __restrict__ beb, const float* __restrict__ g1, const float* __restrict__ be1,
    const float* __restrict__ g2, const float* __restrict__ be2,
    float* __restrict__ oe)
{
    extern __shared__ float sm[];
    const uint32_t sb = smem_u32(sm);
    const int tid = threadIdx.x, w = tid >> 5, lane = tid & 31;
    const int wm = w >> 2, wn = w & 3, g = lane >> 2, t2 = (lane & 3) << 1;
    const int ib = blockIdx.x >> 3, jn0 = (blockIdx.x & 7) << 6;
    const size_t r0 = (size_t)blockIdx.x * 64;

#pragma unroll
    for (int t = 0; t < 16; ++t) { int id4 = tid + t * 256; cpa16(sb + (O_B0 + id4 * 4) * 4, wfrag[0] + id4 * 4); }
    CPC();

#pragma unroll
    for (int t = 0; t < 8; ++t) {
        int id = tid + t * 256;
        int r = id >> 5, c4 = (id & 31) << 2;
        float4 v = *(const float4*)&edge[(r0 + r) * Dd + c4];
        int base = AFR(r, c4);
        sm[O_A + base + 0] = tf32f(v.x); sm[O_A + base + 4] = tf32f(v.y);
        sm[O_A + base + 8] = tf32f(v.z); sm[O_A + base + 12] = tf32f(v.w);
    }
    if (tid < Dd) {
        sm[O_P + tid]  = bm[tid] + sc_T[ib * Dd + tid];
        sm[G_GM + tid] = gm[tid];  sm[G_BEM + tid] = bem[tid];
        sm[G_G1 + tid] = g1[tid];  sm[G_BE1 + tid] = be1[tid];
        sm[G_G2 + tid] = g2[tid];  sm[G_BE2 + tid] = be2[tid];
        sm[G_BEB + tid] = beb[tid];
    }
    CPW(0); __syncthreads();

    float c[2][4][4];
    mma_tile(sm + O_A, sm + O_B0, c);       // memory GEMM
    __syncthreads();
#pragma unroll
    for (int t = 0; t < 16; ++t) { int id4 = tid + t * 256; cpa16(sb + (O_B0 + id4 * 4) * 4, wfrag[1] + id4 * 4); }
    CPC();

    // epilogue1: memory = relu(LN(c + (bm+T) + S)), rewrite A-frags (tf32)
    {
        float sv[2][2] = {{0,0},{0,0}}, qv[2][2] = {{0,0},{0,0}};
#pragma unroll
        for (int mt = 0; mt < 2; ++mt) {
            int rA = wm * 32 + mt * 16 + g;
#pragma unroll
            for (int nt = 0; nt < 4; ++nt) {
                int col = wn * 32 + nt * 8 + t2;
                float p0 = sm[O_P + col], p1 = sm[O_P + col + 1];
                float2 s0 = *(const float2*)&sc_S[(jn0 + rA) * Dd + col];
                float2 s1 = *(const float2*)&sc_S[(jn0 + rA + 8) * Dd + col];
                c[mt][nt][0] += p0 + s0.x; c[mt][nt][1] += p1 + s0.y;
                c[mt][nt][2] += p0 + s1.x; c[mt][nt][3] += p1 + s1.y;
                sv[mt][0] += c[mt][nt][0] + c[mt][nt][1];
                qv[mt][0] += c[mt][nt][0]*c[mt][nt][0] + c[mt][nt][1]*c[mt][nt][1];
                sv[mt][1] += c[mt][nt][2] + c[mt][nt][3];
                qv[mt][1] += c[mt][nt][2]*c[mt][nt][2] + c[mt][nt][3]*c[mt][nt][3];
            }
        }
        float mean[2][2], rstd[2][2];
        ROWSTATS(sv, qv, mean, rstd);
#pragma unroll
        for (int mt = 0; mt < 2; ++mt) {
            int rA = wm * 32 + mt * 16 + g;
#pragma unroll
            for (int nt = 0; nt < 4; ++nt) {
                int col = wn * 32 + nt * 8 + t2;
                float ga0 = sm[G_GM + col], ga1 = sm[G_GM + col + 1];
                float bb0 = sm[G_BEM + col], bb1 = sm[G_BEM + col + 1];
                sm[O_A + AFR(rA, col)]     = tf32f(fmaxf((c[mt][nt][0]-mean[mt][0])*rstd[mt][0]*ga0+bb0, 0.f));
                sm[O_A + AFR(rA, col + 1)] = tf32f(fmaxf((c[mt][nt][1]-mean[mt][0])*rstd[mt][0]*ga1+bb1, 0.f));
                sm[O_A + AFR(rA + 8, col)]     = tf32f(fmaxf((c[mt][nt][2]-mean[mt][1])*rstd[mt][1]*ga0+bb0, 0.f));
                sm[O_A + AFR(rA + 8, col + 1)] = tf32f(fmaxf((c[mt][nt][3]-mean[mt][1])*rstd[mt][1]*ga1+bb1, 0.f));
            }
        }
    }
    CPW(0); __syncthreads();    // A rewritten + We ready

    mma_tile(sm + O_A, sm + O_B0, c);       // edge GEMM

    // write memory as bf16 [jn][ib][c], coalesced (A-frags are read-only now)
#pragma unroll
    for (int t = 0; t < 16; ++t) {
        int id = tid + t * 256;             // uint index over 64x64
        int r = id >> 6, cu = id & 63;
        int c0 = cu << 1;
        float f0 = sm[O_A + AFR(r, c0)], f1 = sm[O_A + AFR(r, c0 + 1)];
        __nv_bfloat162 h2 = __floats2bfloat162_rn(f0, f1);
        sc_memt[((size_t)(jn0 + r) * Nn + ib) * 64 + cu] = *reinterpret_cast<uint32_t*>(&h2);
    }

    // epilogue2: out_edge = LN2(edge + relu(LN1(c + beb)))
    {
        float sv[2][2] = {{0,0},{0,0}}, qv[2][2] = {{0,0},{0,0}};
#pragma unroll
        for (int mt = 0; mt < 2; ++mt)
#pragma unroll
            for (int nt = 0; nt < 4; ++nt) {
                int col = wn * 32 + nt * 8 + t2;
                float b0 = sm[G_BEB + col], b1 = sm[G_BEB + col + 1];
                c[mt][nt][0] += b0; c[mt][nt][1] += b1;
                c[mt][nt][2] += b0; c[mt][nt][3] += b1;
                sv[mt][0] += c[mt][nt][0] + c[mt][nt][1];
                qv[mt][0] += c[mt][nt][0]*c[mt][nt][0] + c[mt][nt][1]*c[mt][nt][1];
                sv[mt][1] += c[mt][nt][2] + c[mt][nt][3];
                qv[mt][1] += c[mt][nt][2]*c[mt][nt][2] + c[mt][nt][3]*c[mt][nt][3];
            }
        float mean[2][2], rstd[2][2];
        ROWSTATS(sv, qv, mean, rstd);
        float sv2[2][2] = {{0,0},{0,0}}, qv2[2][2] = {{0,0},{0,0}};
#pragma unroll
        for (int mt = 0; mt < 2; ++mt) {
            int rA = wm * 32 + mt * 16 + g;
#pragma unroll
            for (int nt = 0; nt < 4; ++nt) {
                int col = wn * 32 + nt * 8 + t2;
                float ga0 = sm[G_G1 + col], ga1 = sm[G_G1 + col + 1];
                float bb0 = sm[G_BE1 + col], bb1 = sm[G_BE1 + col + 1];
                float2 e0 = *(const float2*)&edge[(r0 + rA) * Dd + col];
                float2 e1 = *(const float2*)&edge[(r0 + rA + 8) * Dd + col];
                float w00 = fmaxf((c[mt][nt][0]-mean[mt][0])*rstd[mt][0]*ga0+bb0, 0.f) + e0.x;
                float w01 = fmaxf((c[mt][nt][1]-mean[mt][0])*rstd[mt][0]*ga1+bb1, 0.f) + e0.y;
                float w10 = fmaxf((c[mt][nt][2]-mean[mt][1])*rstd[mt][1]*ga0+bb0, 0.f) + e1.x;
                float w11 = fmaxf((c[mt][nt][3]-mean[mt][1])*rstd[mt][1]*ga1+bb1, 0.f) + e1.y;
                c[mt][nt][0] = w00; c[mt][nt][1] = w01; c[mt][nt][2] = w10; c[mt][nt][3] = w11;
                sv2[mt][0] += w00 + w01; qv2[mt][0] += w00*w00 + w01*w01;
                sv2[mt][1] += w10 + w11; qv2[mt][1] += w10*w10 + w11*w11;
            }
        }
        ROWSTATS(sv2, qv2, mean, rstd);
#pragma unroll
        for (int mt = 0; mt < 2; ++mt) {
            int rA = wm * 32 + mt * 16 + g;
#pragma unroll
            for (int nt = 0; nt < 4; ++nt) {
                int col = wn * 32 + nt * 8 + t2;
                float ga0 = sm[G_G2 + col], ga1 = sm[G_G2 + col + 1];
                float bb0 = sm[G_BE2 + col], bb1 = sm[G_BE2 + col + 1];
                *(float2*)&oe[(r0 + rA) * Dd + col] =
                    make_float2((c[mt][nt][0]-mean[mt][0])*rstd[mt][0]*ga0+bb0,
                                (c[mt][nt][1]-mean[mt][0])*rstd[mt][0]*ga1+bb1);
                *(float2*)&oe[(r0 + rA + 8) * Dd + col] =
                    make_float2((c[mt][nt][2]-mean[mt][1])*rstd[mt][1]*ga0+bb0,
                                (c[mt][nt][3]-mean[mt][1])*rstd[mt][1]*ga1+bb1);
            }
        }
    }
}

// ---------- attention: flash-style single pass over bf16 memory ----------
__global__ __launch_bounds__(256, 4) void k_attn(const unsigned char* __restrict__ mask,
                                                 const float* __restrict__ Wv,
                                                 const float* __restrict__ bv) {
    const int n = blockIdx.x, tid = threadIdx.x, w = tid >> 5, lane = tid & 31;
    __shared__ float qk_s[8 * 128];
    __shared__ uint32_t buf[2][4096];
    __shared__ float sc_s[8 * 64], p_s[8 * 64];
    __shared__ float f_s[8], sum_s[8];
    __shared__ float ctx_s[8 * 128];

    for (int i = tid; i < 1024; i += 256) qk_s[i] = sc_qk[n * 1024 + i];

    const uint32_t sbuf = smem_u32(buf);
    // issue chunk 0
#pragma unroll
    for (int t = 0; t < 4; ++t) {
        int id4 = tid + t * 256;
        int m = id4 >> 4, j4 = id4 & 15;
        cpa16(sbuf + ((m * 64 + ((j4 ^ (m & 15)) << 2)) << 2),
              sc_memt + ((size_t)n * Nn + m) * 64 + j4 * 4);
    }
    CPC();

    float run_max = -1e30f, run_sum = 0.f;
    float ctx0 = 0.f, ctx1 = 0.f, ctx2 = 0.f, ctx3 = 0.f;
    const int sm_ = tid & 63, h0 = (tid >> 6) << 1;   // scores mapping
    const int cq = lane;                               // ctx mapping (h = w)

    for (int ch = 0; ch < 8; ++ch) {
        int bsel = ch & 1;
        if (ch < 7) {
            int m0n = (ch + 1) * 64, bn = (ch + 1) & 1;
#pragma unroll
            for (int t = 0; t < 4; ++t) {
                int id4 = tid + t * 256;
                int m = id4 >> 4, j4 = id4 & 15;
                cpa16(sbuf + ((bn * 4096 + m * 64 + ((j4 ^ (m & 15)) << 2)) << 2),
                      sc_memt + ((size_t)n * Nn + m0n + m) * 64 + j4 * 4);
            }
            CPC();
            CPW(1);
        } else {
            CPW(0);
        }
        __syncthreads();

        // scores: thread -> (m, h0/h0+1)
        {
            const uint32_t* bp = &buf[bsel][sm_ * 64];
            float a0 = 0.f, a1 = 0.f;
#pragma unroll
            for (int j4 = 0; j4 < 16; ++j4) {
                uint4 B = *(const uint4*)&bp[(j4 ^ (sm_ & 15)) << 2];
                float4 qa0 = *(const float4*)&qk_s[h0 * 128 + j4 * 8];
                float4 qa1 = *(const float4*)&qk_s[h0 * 128 + j4 * 8 + 4];
                float4 qb0 = *(const float4*)&qk_s[(h0 + 1) * 128 + j4 * 8];
                float4 qb1 = *(const float4*)&qk_s[(h0 + 1) * 128 + j4 * 8 + 4];
                float2 f0 = __bfloat1622float2(*reinterpret_cast<__nv_bfloat162*>(&B.x));
                float2 f1 = __bfloat1622float2(*reinterpret_cast<__nv_bfloat162*>(&B.y));
                float2 f2 = __bfloat1622float2(*reinterpret_cast<__nv_bfloat162*>(&B.z));
                float2 f3 = __bfloat1622float2(*reinterpret_cast<__nv_bfloat162*>(&B.w));
                a0 += f0.x*qa0.x + f0.y*qa0.y + f1.x*qa0.z + f1.y*qa0.w
                    + f2.x*qa1.x + f2.y*qa1.y + f3.x*qa1.z + f3.y*qa1.w;
                a1 += f0.x*qb0.x + f0.y*qb0.y + f1.x*qb0.z + f1.y*qb0.w
                    + f2.x*qb1.x + f2.y*qb1.y + f3.x*qb1.z + f3.y*qb1.w;
            }
            bool mk = mask[n * Nn + ch * 64 + sm_] != 0;
            sc_s[h0 * 64 + sm_]       = mk ? -1e30f : a0;
            sc_s[(h0 + 1) * 64 + sm_] = mk ? -1e30f : a1;
        }
        __syncthreads();

        // online softmax: warp w owns head w
        {
            float s0v = sc_s[w * 64 + lane], s1v = sc_s[w * 64 + lane + 32];
            float mx = fmaxf(s0v, s1v);
#pragma unroll
            for (int off = 16; off >= 1; off >>= 1)
                mx = fmaxf(mx, __shfl_xor_sync(0xffffffffu, mx, off));
            float nm = fmaxf(run_max, mx);
            float f = __expf(run_max - nm);
            float p0 = __expf(s0v - nm), p1 = __expf(s1v - nm);
            p_s[w * 64 + lane] = p0; p_s[w * 64 + lane + 32] = p1;
            float cs = p0 + p1;
#pragma unroll
            for (int off = 16; off >= 1; off >>= 1)
                cs += __shfl_xor_sync(0xffffffffu, cs, off);
            run_sum = run_sum * f + cs;
            run_max = nm;
            if (lane == 0) f_s[w] = f;
        }
        __syncthreads();

        // ctx accumulate: thread (h = w, c quad = cq)
        {
            float f = f_s[w];
            ctx0 *= f; ctx1 *= f; ctx2 *= f; ctx3 *= f;
            int j4 = cq >> 1, sub = (cq * 2) & 3;
#pragma unroll 8
            for (int m = 0; m < 64; ++m) {
                float p = p_s[w * 64 + m];
                const uint32_t* row = &buf[bsel][m * 64];
                int o = ((j4 ^ (m & 15)) << 2) + sub;
                uint32_t u0 = row[o], u1 = row[o + 1];
                float2 fa = __bfloat1622float2(*reinterpret_cast<__nv_bfloat162*>(&u0));
                float2 fb = __bfloat1622float2(*reinterpret_cast<__nv_bfloat162*>(&u1));
                ctx0 = fmaf(p, fa.x, ctx0); ctx1 = fmaf(p, fa.y, ctx1);
                ctx2 = fmaf(p, fb.x, ctx2); ctx3 = fmaf(p, fb.y, ctx3);
            }
        }
        __syncthreads();
    }

    if (lane == 0) sum_s[w] = run_sum;
    __syncthreads();
    {
        float inv = 1.f / sum_s[w];
        ctx_s[w * 128 + cq * 4 + 0] = ctx0 * inv;
        ctx_s[w * 128 + cq * 4 + 1] = ctx1 * inv;
        ctx_s[w * 128 + cq * 4 + 2] = ctx2 * inv;
        ctx_s[w * 128 + cq * 4 + 3] = ctx3 * inv;
    }
    __syncthreads();
    if (tid < 128) {
        int h = tid >> 4;
        float acc = bv[tid];
#pragma unroll 8
        for (int cc = 0; cc < 128; ++cc)
            acc = fmaf(ctx_s[h * 128 + cc], Wv[cc * Dd + tid], acc);
        sc_o[n * Dd + tid] = acc;
    }
}

// ---------- final: out-proj + LN + FFN + LN ----------
__device__ __forceinline__ float bsum128(float v, float* tmp) {
    int lane = threadIdx.x & 31, wid = threadIdx.x >> 5;
#pragma unroll
    for (int off = 16; off >= 1; off >>= 1) v += __shfl_xor_sync(0xffffffffu, v, off);
    if (lane == 0) tmp[wid] = v;
    __syncthreads();
    float s = tmp[0] + tmp[1] + tmp[2] + tmp[3];
    __syncthreads();
    return s;
}
__global__ void k_final(const float* __restrict__ node,
                        const float* __restrict__ Wo, const float* __restrict__ bo,
                        const float* __restrict__ g2, const float* __restrict__ be2,
                        const float* __restrict__ W1, const float* __restrict__ b1,
                        const float* __restrict__ W2, const float* __restrict__ b2,
                        const float* __restrict__ g3, const float* __restrict__ be3,
                        float* __restrict__ out_x) {
    const int n = blockIdx.x;
    const int c = threadIdx.x;
    __shared__ float os[Dd], xs[Dd], hs[Df], tmp[4];
    os[c] = sc_o[n * Dd + c];
    __syncthreads();
    float t = bo[c];
#pragma unroll 8
    for (int k = 0; k < Dd; ++k) t = fmaf(os[k], Wo[k * Dd + c], t);
    float x = node[n * Dd + c] + t;
    float mean = bsum128(x, tmp) * (1.f / 128.f);
    float d = x - mean;
    float var = bsum128(d * d, tmp) * (1.f / 128.f);
    float xn = d * rsqrtf(var + 1e-5f) * g2[c] + be2[c];
    xs[c] = xn;
    __syncthreads();
    float h0 = b1[c], h1 = b1[c + 128];
#pragma unroll 8
    for (int k = 0; k < Dd; ++k) {
        float xv = xs[k];
        h0 = fmaf(xv, W1[k * Df + c], h0);
        h1 = fmaf(xv, W1[k * Df + c + 128], h1);
    }
    hs[c] = fmaxf(h0, 0.f);
    hs[c + 128] = fmaxf(h1, 0.f);
    __syncthreads();
    float y = b2[c];
#pragma unroll 8
    for (int f = 0; f < Df; ++f) y = fmaf(hs[f], W2[f * Dd + c], y);
    float z = xn + y;
    mean = bsum128(z, tmp) * (1.f / 128.f);
    d = z - mean;
    var = bsum128(d * d, tmp) * (1.f / 128.f);
    out_x[n * Dd + c] = d * rsqrtf(var + 1e-5f) * g3[c] + be3[c];
}

// ---------- host ----------
extern "C" void kernel_launch(void* const* d_in, const int* in_sizes, int n_in,
                              void* d_out, int out_size) {
    const float* node = (const float*)d_in[0];
    const float* edge = (const float*)d_in[1];
    const unsigned char* mask = (const unsigned char*)d_in[2];
    const float* W_mem = (const float*)d_in[3];
    const float* b_mem = (const float*)d_in[4];
    const float* g_mem = (const float*)d_in[5];
    const float* be_mem = (const float*)d_in[6];
    const float* W_e = (const float*)d_in[7];
    const float* b_e = (const float*)d_in[8];
    const float* g_e1 = (const float*)d_in[9];
    const float* be_e1 = (const float*)d_in[10];
    const float* g_e2 = (const float*)d_in[11];
    const float* be_e2 = (const float*)d_in[12];
    const float* Wq = (const float*)d_in[13];
    const float* bq = (const float*)d_in[14];
    const float* Wk = (const float*)d_in[15];
    const float* bk = (const float*)d_in[16]; (void)bk;   // cancels in softmax
    const float* Wv = (const float*)d_in[17];
    const float* bv = (const float*)d_in[18];
    const float* Wo = (const float*)d_in[19];
    const float* bo = (const float*)d_in[20];
    const float* W1 = (const float*)d_in[21];
    const float* b1 = (const float*)d_in[22];
    const float* W2 = (const float*)d_in[23];
    const float* b2 = (const float*)d_in[24];
    const float* g2 = (const float*)d_in[25];
    const float* be2 = (const float*)d_in[26];
    const float* g3 = (const float*)d_in[27];
    const float* be3 = (const float*)d_in[28];

    float* out = (float*)d_out;
    float* out_x = out;
    float* out_edge = out + Nn * Dd;

    static int init = 0;
    if (!init) {
        cudaFuncSetAttribute(k_prep, cudaFuncAttributeMaxDynamicSharedMemorySize, 128 * 129 * 4);
        cudaFuncSetAttribute(k_fused, cudaFuncAttributeMaxDynamicSharedMemorySize, DYN);
        init = 1;
    }

    k_prep<<<2, 256, 128 * 129 * 4>>>(W_mem, W_e);
    k_small<<<Nn, Dd>>>(node, W_mem, Wq, bq, Wk);
    k_fused<<<NT, 256, DYN>>>(edge, b_mem, g_mem, be_mem,
                              b_e, g_e1, be_e1, g_e2, be_e2, out_edge);
    k_attn<<<Nn, 256>>>(mask, Wv, bv);
    k_final<<<Nn, 128>>>(node, Wo, bo, g2, be2, W1, b1, W2, b2, g3, be3, out_x);
}

// round 10
// speedup vs baseline: 2.4197x; 1.0314x over previous
#include <cuda_runtime.h>
#include <math.h>
#include <stdint.h>

#define Nn 512
#define Dd 128
#define Df 256
#define Hh 8
#define ROWS (Nn*Nn)
#define NT 4096                   // 64-row tiles

__device__ float sc_S[Nn * Dd];
__device__ float sc_T[Nn * Dd];
__device__ float sc_qk[Nn * Hh * Dd];        // 0.25 * Wk^T q  per (n, h)
__device__ float sc_o[Nn * Dd];
__device__ float wfrag[2][16384];            // Wm_edge, We tf32 frag layout
__device__ float sc_memf[(size_t)ROWS * Dd]; // memory f32 [n][m][c] (134MB)

// k_fused dynamic smem float offsets
#define O_A  0                    // 8192
#define O_B0 8192                 // 16384
#define O_RS 24576                // 256
#define O_RQ 24832                // 256
#define O_P  25088                // 128 (bm + T)
#define O_G  25216                // 7*128
#define SMF  26112
#define DYN  (SMF * 4)            // 104448 B -> 2 CTA/SM

#define G_GM  (O_G + 0)
#define G_BEM (O_G + 128)
#define G_G1  (O_G + 256)
#define G_BE1 (O_G + 384)
#define G_G2  (O_G + 512)
#define G_BE2 (O_G + 640)
#define G_BEB (O_G + 768)

// k_attn dynamic smem float offsets
#define A_QK  0
#define A_BF  1024                // 2 x (64*132)
#define A_SC  17920
#define A_P   18432
#define A_F   18944
#define A_SUM 18952
#define A_CTX 18960
#define A_SMF 19984
#define A_DYN (A_SMF * 4)         // 79936 B -> 2 CTA/SM

__device__ __forceinline__ uint32_t tf32c(float x) {
    uint32_t y; asm("cvt.rna.tf32.f32 %0, %1;" : "=r"(y) : "f"(x)); return y;
}
__device__ __forceinline__ float tf32f(float x) { return __uint_as_float(tf32c(x)); }

__device__ __forceinline__ uint32_t smem_u32(const void* p) {
    uint32_t a;
    asm("{ .reg .u64 t; cvta.to.shared.u64 t, %1; cvt.u32.u64 %0, t; }" : "=r"(a) : "l"(p));
    return a;
}
__device__ __forceinline__ void cpa16(uint32_t s, const void* g) {
    asm volatile("cp.async.cg.shared.global [%0], [%1], 16;" :: "r"(s), "l"(g));
}
#define CPC() asm volatile("cp.async.commit_group;" ::: "memory")
#define CPW(n) asm volatile("cp.async.wait_group %0;" :: "n"(n) : "memory")

__device__ __forceinline__ void mma8(float* c, const uint32_t* a, const uint32_t* b) {
    asm volatile(
        "mma.sync.aligned.m16n8k8.row.col.f32.tf32.tf32.f32 "
        "{%0,%1,%2,%3},{%4,%5,%6,%7},{%8,%9},{%0,%1,%2,%3};"
        : "+f"(c[0]), "+f"(c[1]), "+f"(c[2]), "+f"(c[3])
        : "r"(a[0]), "r"(a[1]), "r"(a[2]), "r"(a[3]), "r"(b[0]), "r"(b[1]));
}

// A-fragment float index for element (row r, col c), r<64 — bank-swizzled
__device__ __forceinline__ int AFR(int r, int c) {
    int kb = c >> 3;
    int q  = ((r & 7) << 2) + (c & 3);
    return ((((r >> 4) * 16 + kb) * 32 + (q ^ ((kb & 7) << 2))) << 2)
           + ((r >> 3) & 1) + (((c >> 2) & 1) << 1);
}

// 64x128x128 tile MMA: 8 warps 2(m) x 4(n), warp tile 32x32
__device__ __forceinline__ void mma_tile(const float* sA, const float* sB, float c[2][4][4]) {
    int tid = threadIdx.x, w = tid >> 5, lane = tid & 31;
    int wm = w >> 2, wn = w & 3;
#pragma unroll
    for (int mt = 0; mt < 2; ++mt)
#pragma unroll
        for (int nt = 0; nt < 4; ++nt)
#pragma unroll
            for (int i = 0; i < 4; ++i) c[mt][nt][i] = 0.f;
#pragma unroll
    for (int kc = 0; kc < 16; ++kc) {
        uint32_t a[2][4];
#pragma unroll
        for (int mt = 0; mt < 2; ++mt) {
            float4 v = *(const float4*)&sA[((((wm * 2 + mt) * 16 + kc) * 32
                                            + (lane ^ ((kc & 7) << 2))) << 2)];
            a[mt][0] = __float_as_uint(v.x); a[mt][1] = __float_as_uint(v.y);
            a[mt][2] = __float_as_uint(v.z); a[mt][3] = __float_as_uint(v.w);
        }
#pragma unroll
        for (int nt = 0; nt < 4; ++nt) {
            float2 bv = *(const float2*)&sB[(((wn * 4 + nt) * 16 + kc) * 32 + lane) * 2];
            uint32_t b[2] = {__float_as_uint(bv.x), __float_as_uint(bv.y)};
            mma8(c[0][nt], a[0], b);
            mma8(c[1][nt], a[1], b);
        }
    }
}

#define ROWSTATS(sv, qv, mean, rstd) do { \
    _Pragma("unroll") for (int _mt = 0; _mt < 2; ++_mt) \
    _Pragma("unroll") for (int _h = 0; _h < 2; ++_h) { \
        float _s = (sv)[_mt][_h], _q = (qv)[_mt][_h]; \
        _s += __shfl_xor_sync(0xffffffffu, _s, 1); _q += __shfl_xor_sync(0xffffffffu, _q, 1); \
        _s += __shfl_xor_sync(0xffffffffu, _s, 2); _q += __shfl_xor_sync(0xffffffffu, _q, 2); \
        (sv)[_mt][_h] = _s; (qv)[_mt][_h] = _q; } \
    if ((lane & 3) == 0) { \
        _Pragma("unroll") for (int _mt = 0; _mt < 2; ++_mt) \
        _Pragma("unroll") for (int _h = 0; _h < 2; ++_h) { \
            int _row = wm * 32 + _mt * 16 + g + _h * 8; \
            sm[O_RS + _row * 4 + wn] = (sv)[_mt][_h]; \
            sm[O_RQ + _row * 4 + wn] = (qv)[_mt][_h]; } } \
    __syncthreads(); \
    _Pragma("unroll") for (int _mt = 0; _mt < 2; ++_mt) \
    _Pragma("unroll") for (int _h = 0; _h < 2; ++_h) { \
        int _row = wm * 32 + _mt * 16 + g + _h * 8; \
        float _ts = sm[O_RS + _row * 4] + sm[O_RS + _row * 4 + 1] + sm[O_RS + _row * 4 + 2] + sm[O_RS + _row * 4 + 3]; \
        float _tq = sm[O_RQ + _row * 4] + sm[O_RQ + _row * 4 + 1] + sm[O_RQ + _row * 4 + 2] + sm[O_RQ + _row * 4 + 3]; \
        float _mn = _ts * (1.f / 128.f); \
        (mean)[_mt][_h] = _mn; \
        (rstd)[_mt][_h] = rsqrtf(fmaxf(_tq * (1.f / 128.f) - _mn * _mn, 0.f) + 1e-5f); } \
    __syncthreads(); \
} while (0)

// ---------- weight prep (Wm, We) ----------
__global__ void k_prep(const float* __restrict__ Wm, const float* __restrict__ We) {
    extern __shared__ float ws[];   // [128][129]
    const float* W = blockIdx.x == 0 ? Wm : We;
    int tid = threadIdx.x;
    for (int t = 0; t < 16; ++t) {
        int id = tid + t * 256;
        int k = id >> 5, n4 = (id & 31) << 2;
        float4 v = *(const float4*)&W[k * Dd + n4];
        ws[k * 129 + n4] = v.x; ws[k * 129 + n4 + 1] = v.y;
        ws[k * 129 + n4 + 2] = v.z; ws[k * 129 + n4 + 3] = v.w;
    }
    __syncthreads();
    float* out = wfrag[blockIdx.x];
    for (int t = 0; t < 32; ++t) {
        int id = tid + t * 256;
        int lane = id & 31, kb = (id >> 5) & 15, nb = id >> 9;
        int n = nb * 8 + (lane >> 2), k = kb * 8 + (lane & 3);
        float2 o;
        o.x = tf32f(ws[k * 129 + n]);
        o.y = tf32f(ws[(k + 4) * 129 + n]);
        *(float2*)&out[id * 2] = o;
    }
}

// ---------- S, T, qk ----------
__global__ void k_small(const float* __restrict__ node, const float* __restrict__ Wmem,
                        const float* __restrict__ Wq, const float* __restrict__ bq,
                        const float* __restrict__ Wk) {
    int n = blockIdx.x, c = threadIdx.x;
    __shared__ float ns[Dd], qs[Dd];
    ns[c] = node[n * Dd + c];
    __syncthreads();
    float s = 0.f, t = 0.f, q = 0.f;
#pragma unroll 8
    for (int k = 0; k < Dd; ++k) {
        float nv = ns[k];
        s = fmaf(nv, Wmem[(Dd + k) * Dd + c], s);
        t = fmaf(nv, Wmem[(2 * Dd + k) * Dd + c], t);
        q = fmaf(nv, Wq[k * Dd + c], q);
    }
    sc_S[n * Dd + c] = s; sc_T[n * Dd + c] = t;
    qs[c] = q + bq[c];
    __syncthreads();
    float a[8] = {0,0,0,0,0,0,0,0};
#pragma unroll
    for (int hd = 0; hd < 128; ++hd)
        a[hd >> 4] = fmaf(Wk[c * Dd + hd], qs[hd], a[hd >> 4]);
#pragma unroll
    for (int h = 0; h < 8; ++h)
        sc_qk[n * 1024 + h * 128 + c] = a[h] * 0.25f;
}

// ---------- fused tile kernel: memory (f32 out) + edge_out ----------
__global__ __launch_bounds__(256, 2) void k_fused(
    const float* __restrict__ edge,
    const float* __restrict__ bm, const float* __restrict__ gm, const float* __restrict__ bem,
    const float* __restrict__ beb, const float* __restrict__ g1, const float* __restrict__ be1,
    const float* __restrict__ g2, const float* __restrict__ be2,
    float* __restrict__ oe)
{
    extern __shared__ float sm[];
    const uint32_t sb = smem_u32(sm);
    const int tid = threadIdx.x, w = tid >> 5, lane = tid & 31;
    const int wm = w >> 2, wn = w & 3, g = lane >> 2, t2 = (lane & 3) << 1;
    const int ib = blockIdx.x >> 3, jn0 = (blockIdx.x & 7) << 6;
    const size_t r0 = (size_t)blockIdx.x * 64;

#pragma unroll
    for (int t = 0; t < 16; ++t) { int id4 = tid + t * 256; cpa16(sb + (O_B0 + id4 * 4) * 4, wfrag[0] + id4 * 4); }
    CPC();

#pragma unroll
    for (int t = 0; t < 8; ++t) {
        int id = tid + t * 256;
        int r = id >> 5, c4 = (id & 31) << 2;
        float4 v = *(const float4*)&edge[(r0 + r) * Dd + c4];
        int base = AFR(r, c4);
        sm[O_A + base + 0] = tf32f(v.x); sm[O_A + base + 4] = tf32f(v.y);
        sm[O_A + base + 8] = tf32f(v.z); sm[O_A + base + 12] = tf32f(v.w);
    }
    if (tid < Dd) {
        sm[O_P + tid]  = bm[tid] + sc_T[ib * Dd + tid];
        sm[G_GM + tid] = gm[tid];  sm[G_BEM + tid] = bem[tid];
        sm[G_G1 + tid] = g1[tid];  sm[G_BE1 + tid] = be1[tid];
        sm[G_G2 + tid] = g2[tid];  sm[G_BE2 + tid] = be2[tid];
        sm[G_BEB + tid] = beb[tid];
    }
    CPW(0); __syncthreads();

    float c[2][4][4];
    mma_tile(sm + O_A, sm + O_B0, c);       // memory GEMM
    __syncthreads();
#pragma unroll
    for (int t = 0; t < 16; ++t) { int id4 = tid + t * 256; cpa16(sb + (O_B0 + id4 * 4) * 4, wfrag[1] + id4 * 4); }
    CPC();

    // epilogue1: memory = relu(LN(c + (bm+T) + S)), rewrite A-frags (tf32)
    {
        float sv[2][2] = {{0,0},{0,0}}, qv[2][2] = {{0,0},{0,0}};
#pragma unroll
        for (int mt = 0; mt < 2; ++mt) {
            int rA = wm * 32 + mt * 16 + g;
#pragma unroll
            for (int nt = 0; nt < 4; ++nt) {
                int col = wn * 32 + nt * 8 + t2;
                float p0 = sm[O_P + col], p1 = sm[O_P + col + 1];
                float2 s0 = *(const float2*)&sc_S[(jn0 + rA) * Dd + col];
                float2 s1 = *(const float2*)&sc_S[(jn0 + rA + 8) * Dd + col];
                c[mt][nt][0] += p0 + s0.x; c[mt][nt][1] += p1 + s0.y;
                c[mt][nt][2] += p0 + s1.x; c[mt][nt][3] += p1 + s1.y;
                sv[mt][0] += c[mt][nt][0] + c[mt][nt][1];
                qv[mt][0] += c[mt][nt][0]*c[mt][nt][0] + c[mt][nt][1]*c[mt][nt][1];
                sv[mt][1] += c[mt][nt][2] + c[mt][nt][3];
                qv[mt][1] += c[mt][nt][2]*c[mt][nt][2] + c[mt][nt][3]*c[mt][nt][3];
            }
        }
        float mean[2][2], rstd[2][2];
        ROWSTATS(sv, qv, mean, rstd);
#pragma unroll
        for (int mt = 0; mt < 2; ++mt) {
            int rA = wm * 32 + mt * 16 + g;
#pragma unroll
            for (int nt = 0; nt < 4; ++nt) {
                int col = wn * 32 + nt * 8 + t2;
                float ga0 = sm[G_GM + col], ga1 = sm[G_GM + col + 1];
                float bb0 = sm[G_BEM + col], bb1 = sm[G_BEM + col + 1];
                sm[O_A + AFR(rA, col)]     = tf32f(fmaxf((c[mt][nt][0]-mean[mt][0])*rstd[mt][0]*ga0+bb0, 0.f));
                sm[O_A + AFR(rA, col + 1)] = tf32f(fmaxf((c[mt][nt][1]-mean[mt][0])*rstd[mt][0]*ga1+bb1, 0.f));
                sm[O_A + AFR(rA + 8, col)]     = tf32f(fmaxf((c[mt][nt][2]-mean[mt][1])*rstd[mt][1]*ga0+bb0, 0.f));
                sm[O_A + AFR(rA + 8, col + 1)] = tf32f(fmaxf((c[mt][nt][3]-mean[mt][1])*rstd[mt][1]*ga1+bb1, 0.f));
            }
        }
    }
    CPW(0); __syncthreads();    // A rewritten + We ready

    mma_tile(sm + O_A, sm + O_B0, c);       // edge GEMM

    // write memory f32 [jn][ib][c], coalesced float4 (A-frags read-only now)
#pragma unroll
    for (int t = 0; t < 8; ++t) {
        int id4 = tid + t * 256;             // 2048 float4 over 64x128
        int r = id4 >> 5, c4 = (id4 & 31) << 2;
        int base = AFR(r, c4);
        float4 o;
        o.x = sm[O_A + base + 0]; o.y = sm[O_A + base + 4];
        o.z = sm[O_A + base + 8]; o.w = sm[O_A + base + 12];
        *(float4*)&sc_memf[((size_t)(jn0 + r) * Nn + ib) * Dd + c4] = o;
    }

    // epilogue2: out_edge = LN2(edge + relu(LN1(c + beb)))
    {
        float sv[2][2] = {{0,0},{0,0}}, qv[2][2] = {{0,0},{0,0}};
#pragma unroll
        for (int mt = 0; mt < 2; ++mt)
#pragma unroll
            for (int nt = 0; nt < 4; ++nt) {
                int col = wn * 32 + nt * 8 + t2;
                float b0 = sm[G_BEB + col], b1 = sm[G_BEB + col + 1];
                c[mt][nt][0] += b0; c[mt][nt][1] += b1;
                c[mt][nt][2] += b0; c[mt][nt][3] += b1;
                sv[mt][0] += c[mt][nt][0] + c[mt][nt][1];
                qv[mt][0] += c[mt][nt][0]*c[mt][nt][0] + c[mt][nt][1]*c[mt][nt][1];
                sv[mt][1] += c[mt][nt][2] + c[mt][nt][3];
                qv[mt][1] += c[mt][nt][2]*c[mt][nt][2] + c[mt][nt][3]*c[mt][nt][3];
            }
        float mean[2][2], rstd[2][2];
        ROWSTATS(sv, qv, mean, rstd);
        float sv2[2][2] = {{0,0},{0,0}}, qv2[2][2] = {{0,0},{0,0}};
#pragma unroll
        for (int mt = 0; mt < 2; ++mt) {
            int rA = wm * 32 + mt * 16 + g;
#pragma unroll
            for (int nt = 0; nt < 4; ++nt) {
                int col = wn * 32 + nt * 8 + t2;
                float ga0 = sm[G_G1 + col], ga1 = sm[G_G1 + col + 1];
                float bb0 = sm[G_BE1 + col], bb1 = sm[G_BE1 + col + 1];
                float2 e0 = *(const float2*)&edge[(r0 + rA) * Dd + col];
                float2 e1 = *(const float2*)&edge[(r0 + rA + 8) * Dd + col];
                float w00 = fmaxf((c[mt][nt][0]-mean[mt][0])*rstd[mt][0]*ga0+bb0, 0.f) + e0.x;
                float w01 = fmaxf((c[mt][nt][1]-mean[mt][0])*rstd[mt][0]*ga1+bb1, 0.f) + e0.y;
                float w10 = fmaxf((c[mt][nt][2]-mean[mt][1])*rstd[mt][1]*ga0+bb0, 0.f) + e1.x;
                float w11 = fmaxf((c[mt][nt][3]-mean[mt][1])*rstd[mt][1]*ga1+bb1, 0.f) + e1.y;
                c[mt][nt][0] = w00; c[mt][nt][1] = w01; c[mt][nt][2] = w10; c[mt][nt][3] = w11;
                sv2[mt][0] += w00 + w01; qv2[mt][0] += w00*w00 + w01*w01;
                sv2[mt][1] += w10 + w11; qv2[mt][1] += w10*w10 + w11*w11;
            }
        }
        ROWSTATS(sv2, qv2, mean, rstd);
#pragma unroll
        for (int mt = 0; mt < 2; ++mt) {
            int rA = wm * 32 + mt * 16 + g;
#pragma unroll
            for (int nt = 0; nt < 4; ++nt) {
                int col = wn * 32 + nt * 8 + t2;
                float ga0 = sm[G_G2 + col], ga1 = sm[G_G2 + col + 1];
                float bb0 = sm[G_BE2 + col], bb1 = sm[G_BE2 + col + 1];
                *(float2*)&oe[(r0 + rA) * Dd + col] =
                    make_float2((c[mt][nt][0]-mean[mt][0])*rstd[mt][0]*ga0+bb0,
                                (c[mt][nt][1]-mean[mt][0])*rstd[mt][0]*ga1+bb1);
                *(float2*)&oe[(r0 + rA + 8) * Dd + col] =
                    make_float2((c[mt][nt][2]-mean[mt][1])*rstd[mt][1]*ga0+bb0,
                                (c[mt][nt][3]-mean[mt][1])*rstd[mt][1]*ga1+bb1);
            }
        }
    }
}

// ---------- attention: flash-style over f32 memory, smem-tiled ----------
__global__ void k_attn(const unsigned char* __restrict__ mask,
                       const float* __restrict__ Wv,
                       const float* __restrict__ bv) {
    extern __shared__ float sa[];
    const int n = blockIdx.x, tid = threadIdx.x, w = tid >> 5, lane = tid & 31;
    const uint32_t sb = smem_u32(sa);

    for (int i = tid; i < 1024; i += 256) sa[A_QK + i] = sc_qk[n * 1024 + i];

    const float* base = sc_memf + (size_t)n * (Nn * Dd);
    // chunk 0
#pragma unroll
    for (int t = 0; t < 8; ++t) {
        int id4 = tid + t * 256;
        int m = id4 >> 5, j = id4 & 31;
        cpa16(sb + (A_BF + m * 132 + j * 4) * 4, base + (size_t)id4 * 4);
    }
    CPC();

    float run_max = -1e30f, run_sum = 0.f;
    float c0 = 0.f, c1 = 0.f, c2 = 0.f, c3 = 0.f;
    const int sm_ = tid & 63, h0 = (tid >> 6) << 1;

    for (int ch = 0; ch < 8; ++ch) {
        const float* mf = sa + A_BF + (ch & 1) * 8448;
        if (ch < 7) {
            const float* src = base + (size_t)(ch + 1) * 64 * Dd;
            int bo = A_BF + ((ch + 1) & 1) * 8448;
#pragma unroll
            for (int t = 0; t < 8; ++t) {
                int id4 = tid + t * 256;
                int m = id4 >> 5, j = id4 & 31;
                cpa16(sb + (bo + m * 132 + j * 4) * 4, src + (size_t)id4 * 4);
            }
            CPC(); CPW(1);
        } else {
            CPW(0);
        }
        __syncthreads();

        // scores: thread -> (m = sm_, heads h0, h0+1)
        {
            float a0 = 0.f, a1 = 0.f;
            const float* mr = &mf[sm_ * 132];
            const float* qa = &sa[A_QK + h0 * 128];
            const float* qb = &sa[A_QK + (h0 + 1) * 128];
#pragma unroll 8
            for (int j = 0; j < 32; ++j) {
                float4 m4 = *(const float4*)&mr[j * 4];
                float4 a4 = *(const float4*)&qa[j * 4];
                float4 b4 = *(const float4*)&qb[j * 4];
                a0 += m4.x*a4.x + m4.y*a4.y + m4.z*a4.z + m4.w*a4.w;
                a1 += m4.x*b4.x + m4.y*b4.y + m4.z*b4.z + m4.w*b4.w;
            }
            bool mk = mask[n * Nn + ch * 64 + sm_] != 0;
            sa[A_SC + h0 * 64 + sm_]       = mk ? -1e30f : a0;
            sa[A_SC + (h0 + 1) * 64 + sm_] = mk ? -1e30f : a1;
        }
        __syncthreads();

        // online softmax: warp w = head w
        {
            float s0v = sa[A_SC + w * 64 + lane], s1v = sa[A_SC + w * 64 + lane + 32];
            float mx = fmaxf(s0v, s1v);
#pragma unroll
            for (int off = 16; off >= 1; off >>= 1)
                mx = fmaxf(mx, __shfl_xor_sync(0xffffffffu, mx, off));
            float nm = fmaxf(run_max, mx);
            float f = __expf(run_max - nm);
            float p0 = __expf(s0v - nm), p1 = __expf(s1v - nm);
            sa[A_P + w * 64 + lane] = p0; sa[A_P + w * 64 + lane + 32] = p1;
            float cs = p0 + p1;
#pragma unroll
            for (int off = 16; off >= 1; off >>= 1)
                cs += __shfl_xor_sync(0xffffffffu, cs, off);
            run_sum = run_sum * f + cs;
            run_max = nm;
            if (lane == 0) sa[A_F + w] = f;
        }
        __syncthreads();

        // ctx: thread (h = w, cols lane*4..lane*4+3)
        {
            float f = sa[A_F + w];
            c0 *= f; c1 *= f; c2 *= f; c3 *= f;
            const float* pp = &sa[A_P + w * 64];
#pragma unroll 8
            for (int m = 0; m < 64; ++m) {
                float p = pp[m];
                float4 v = *(const float4*)&mf[m * 132 + lane * 4];
                c0 = fmaf(p, v.x, c0); c1 = fmaf(p, v.y, c1);
                c2 = fmaf(p, v.z, c2); c3 = fmaf(p, v.w, c3);
            }
        }
        __syncthreads();
    }

    if (lane == 0) sa[A_SUM + w] = run_sum;
    __syncthreads();
    {
        float inv = 1.f / sa[A_SUM + w];
        sa[A_CTX + w * 128 + lane * 4 + 0] = c0 * inv;
        sa[A_CTX + w * 128 + lane * 4 + 1] = c1 * inv;
        sa[A_CTX + w * 128 + lane * 4 + 2] = c2 * inv;
        sa[A_CTX + w * 128 + lane * 4 + 3] = c3 * inv;
    }
    __syncthreads();
    if (tid < 128) {
        int h = tid >> 4;
        float acc = bv[tid];
#pragma unroll 8
        for (int cc = 0; cc < 128; ++cc)
            acc = fmaf(sa[A_CTX + h * 128 + cc], Wv[cc * Dd + tid], acc);
        sc_o[n * Dd + tid] = acc;
    }
}

// ---------- final: out-proj + LN + FFN + LN ----------
__device__ __forceinline__ float bsum128(float v, float* tmp) {
    int lane = threadIdx.x & 31, wid = threadIdx.x >> 5;
#pragma unroll
    for (int off = 16; off >= 1; off >>= 1) v += __shfl_xor_sync(0xffffffffu, v, off);
    if (lane == 0) tmp[wid] = v;
    __syncthreads();
    float s = tmp[0] + tmp[1] + tmp[2] + tmp[3];
    __syncthreads();
    return s;
}
__global__ void k_final(const float* __restrict__ node,
                        const float* __restrict__ Wo, const float* __restrict__ bo,
                        const float* __restrict__ g2, const float* __restrict__ be2,
                        const float* __restrict__ W1, const float* __restrict__ b1,
                        const float* __restrict__ W2, const float* __restrict__ b2,
                        const float* __restrict__ g3, const float* __restrict__ be3,
                        float* __restrict__ out_x) {
    const int n = blockIdx.x;
    const int c = threadIdx.x;
    __shared__ float os[Dd], xs[Dd], hs[Df], tmp[4];
    os[c] = sc_o[n * Dd + c];
    __syncthreads();
    float t = bo[c];
#pragma unroll 8
    for (int k = 0; k < Dd; ++k) t = fmaf(os[k], Wo[k * Dd + c], t);
    float x = node[n * Dd + c] + t;
    float mean = bsum128(x, tmp) * (1.f / 128.f);
    float d = x - mean;
    float var = bsum128(d * d, tmp) * (1.f / 128.f);
    float xn = d * rsqrtf(var + 1e-5f) * g2[c] + be2[c];
    xs[c] = xn;
    __syncthreads();
    float h0 = b1[c], h1 = b1[c + 128];
#pragma unroll 8
    for (int k = 0; k < Dd; ++k) {
        float xv = xs[k];
        h0 = fmaf(xv, W1[k * Df + c], h0);
        h1 = fmaf(xv, W1[k * Df + c + 128], h1);
    }
    hs[c] = fmaxf(h0, 0.f);
    hs[c + 128] = fmaxf(h1, 0.f);
    __syncthreads();
    float y = b2[c];
#pragma unroll 8
    for (int f = 0; f < Df; ++f) y = fmaf(hs[f], W2[f * Dd + c], y);
    float z = xn + y;
    mean = bsum128(z, tmp) * (1.f / 128.f);
    d = z - mean;
    var = bsum128(d * d, tmp) * (1.f / 128.f);
    out_x[n * Dd + c] = d * rsqrtf(var + 1e-5f) * g3[c] + be3[c];
}

// ---------- host ----------
extern "C" void kernel_launch(void* const* d_in, const int* in_sizes, int n_in,
                              void* d_out, int out_size) {
    const float* node = (const float*)d_in[0];
    const float* edge = (const float*)d_in[1];
    const unsigned char* mask = (const unsigned char*)d_in[2];
    const float* W_mem = (const float*)d_in[3];
    const float* b_mem = (const float*)d_in[4];
    const float* g_mem = (const float*)d_in[5];
    const float* be_mem = (const float*)d_in[6];
    const float* W_e = (const float*)d_in[7];
    const float* b_e = (const float*)d_in[8];
    const float* g_e1 = (const float*)d_in[9];
    const float* be_e1 = (const float*)d_in[10];
    const float* g_e2 = (const float*)d_in[11];
    const float* be_e2 = (const float*)d_in[12];
    const float* Wq = (const float*)d_in[13];
    const float* bq = (const float*)d_in[14];
    const float* Wk = (const float*)d_in[15];
    const float* bk = (const float*)d_in[16]; (void)bk;   // cancels in softmax
    const float* Wv = (const float*)d_in[17];
    const float* bv = (const float*)d_in[18];
    const float* Wo = (const float*)d_in[19];
    const float* bo = (const float*)d_in[20];
    const float* W1 = (const float*)d_in[21];
    const float* b1 = (const float*)d_in[22];
    const float* W2 = (const float*)d_in[23];
    const float* b2 = (const float*)d_in[24];
    const float* g2 = (const float*)d_in[25];
    const float* be2 = (const float*)d_in[26];
    const float* g3 = (const float*)d_in[27];
    const float* be3 = (const float*)d_in[28];

    float* out = (float*)d_out;
    float* out_x = out;
    float* out_edge = out + Nn * Dd;

    static int init = 0;
    if (!init) {
        cudaFuncSetAttribute(k_prep, cudaFuncAttributeMaxDynamicSharedMemorySize, 128 * 129 * 4);
        cudaFuncSetAttribute(k_fused, cudaFuncAttributeMaxDynamicSharedMemorySize, DYN);
        cudaFuncSetAttribute(k_attn, cudaFuncAttributeMaxDynamicSharedMemorySize, A_DYN);
        init = 1;
    }

    k_prep<<<2, 256, 128 * 129 * 4>>>(W_mem, W_e);
    k_small<<<Nn, Dd>>>(node, W_mem, Wq, bq, Wk);
    k_fused<<<NT, 256, DYN>>>(edge, b_mem, g_mem, be_mem,
                              b_e, g_e1, be_e1, g_e2, be_e2, out_edge);
    k_attn<<<Nn, 256, A_DYN>>>(mask, Wv, bv);
    k_final<<<Nn, 128>>>(node, Wo, bo, g2, be2, W1, b1, W2, b2, g3, be3, out_x);
}

// round 11
// speedup vs baseline: 2.4916x; 1.0297x over previous
#include <cuda_runtime.h>
#include <math.h>
#include <stdint.h>

#define Nn 512
#define Dd 128
#define Df 256
#define Hh 8
#define ROWS (Nn*Nn)
#define NT 4096                   // 64-row tiles

__device__ float sc_S[Nn * Dd];
__device__ float sc_T[Nn * Dd];
__device__ float sc_qk[Nn * Hh * Dd];        // 0.25 * Wk^T q  per (n, h)
__device__ float sc_o[Nn * Dd];
__device__ float wfrag[2][16384];            // Wm_edge, We tf32 frag layout
__device__ float sc_memf[(size_t)ROWS * Dd]; // memory f32 [n][m][c] (134MB)
__device__ float sc_part[(size_t)4096 * 1040]; // split-KV partials (17MB)

// k_fused dynamic smem float offsets
#define O_A  0                    // 8192
#define O_B0 8192                 // 16384
#define O_RS 24576                // 256
#define O_RQ 24832                // 256
#define O_P  25088                // 128 (bm + T)
#define O_G  25216                // 7*128
#define SMF  26112
#define DYN  (SMF * 4)            // 104448 B -> 2 CTA/SM

#define G_GM  (O_G + 0)
#define G_BEM (O_G + 128)
#define G_G1  (O_G + 256)
#define G_BE1 (O_G + 384)
#define G_G2  (O_G + 512)
#define G_BE2 (O_G + 640)
#define G_BEB (O_G + 768)

__device__ __forceinline__ uint32_t tf32c(float x) {
    uint32_t y; asm("cvt.rna.tf32.f32 %0, %1;" : "=r"(y) : "f"(x)); return y;
}
__device__ __forceinline__ float tf32f(float x) { return __uint_as_float(tf32c(x)); }

__device__ __forceinline__ uint32_t smem_u32(const void* p) {
    uint32_t a;
    asm("{ .reg .u64 t; cvta.to.shared.u64 t, %1; cvt.u32.u64 %0, t; }" : "=r"(a) : "l"(p));
    return a;
}
__device__ __forceinline__ void cpa16(uint32_t s, const void* g) {
    asm volatile("cp.async.cg.shared.global [%0], [%1], 16;" :: "r"(s), "l"(g));
}
#define CPC() asm volatile("cp.async.commit_group;" ::: "memory")
#define CPW(n) asm volatile("cp.async.wait_group %0;" :: "n"(n) : "memory")

__device__ __forceinline__ void mma8(float* c, const uint32_t* a, const uint32_t* b) {
    asm volatile(
        "mma.sync.aligned.m16n8k8.row.col.f32.tf32.tf32.f32 "
        "{%0,%1,%2,%3},{%4,%5,%6,%7},{%8,%9},{%0,%1,%2,%3};"
        : "+f"(c[0]), "+f"(c[1]), "+f"(c[2]), "+f"(c[3])
        : "r"(a[0]), "r"(a[1]), "r"(a[2]), "r"(a[3]), "r"(b[0]), "r"(b[1]));
}

// A-fragment float index for element (row r, col c), r<64 — bank-swizzled
__device__ __forceinline__ int AFR(int r, int c) {
    int kb = c >> 3;
    int q  = ((r & 7) << 2) + (c & 3);
    return ((((r >> 4) * 16 + kb) * 32 + (q ^ ((kb & 7) << 2))) << 2)
           + ((r >> 3) & 1) + (((c >> 2) & 1) << 1);
}

// 64x128x128 tile MMA: 8 warps 2(m) x 4(n), warp tile 32x32
__device__ __forceinline__ void mma_tile(const float* sA, const float* sB, float c[2][4][4]) {
    int tid = threadIdx.x, w = tid >> 5, lane = tid & 31;
    int wm = w >> 2, wn = w & 3;
#pragma unroll
    for (int mt = 0; mt < 2; ++mt)
#pragma unroll
        for (int nt = 0; nt < 4; ++nt)
#pragma unroll
            for (int i = 0; i < 4; ++i) c[mt][nt][i] = 0.f;
#pragma unroll
    for (int kc = 0; kc < 16; ++kc) {
        uint32_t a[2][4];
#pragma unroll
        for (int mt = 0; mt < 2; ++mt) {
            float4 v = *(const float4*)&sA[((((wm * 2 + mt) * 16 + kc) * 32
                                            + (lane ^ ((kc & 7) << 2))) << 2)];
            a[mt][0] = __float_as_uint(v.x); a[mt][1] = __float_as_uint(v.y);
            a[mt][2] = __float_as_uint(v.z); a[mt][3] = __float_as_uint(v.w);
        }
#pragma unroll
        for (int nt = 0; nt < 4; ++nt) {
            float2 bv = *(const float2*)&sB[(((wn * 4 + nt) * 16 + kc) * 32 + lane) * 2];
            uint32_t b[2] = {__float_as_uint(bv.x), __float_as_uint(bv.y)};
            mma8(c[0][nt], a[0], b);
            mma8(c[1][nt], a[1], b);
        }
    }
}

#define ROWSTATS(sv, qv, mean, rstd) do { \
    _Pragma("unroll") for (int _mt = 0; _mt < 2; ++_mt) \
    _Pragma("unroll") for (int _h = 0; _h < 2; ++_h) { \
        float _s = (sv)[_mt][_h], _q = (qv)[_mt][_h]; \
        _s += __shfl_xor_sync(0xffffffffu, _s, 1); _q += __shfl_xor_sync(0xffffffffu, _q, 1); \
        _s += __shfl_xor_sync(0xffffffffu, _s, 2); _q += __shfl_xor_sync(0xffffffffu, _q, 2); \
        (sv)[_mt][_h] = _s; (qv)[_mt][_h] = _q; } \
    if ((lane & 3) == 0) { \
        _Pragma("unroll") for (int _mt = 0; _mt < 2; ++_mt) \
        _Pragma("unroll") for (int _h = 0; _h < 2; ++_h) { \
            int _row = wm * 32 + _mt * 16 + g + _h * 8; \
            sm[O_RS + _row * 4 + wn] = (sv)[_mt][_h]; \
            sm[O_RQ + _row * 4 + wn] = (qv)[_mt][_h]; } } \
    __syncthreads(); \
    _Pragma("unroll") for (int _mt = 0; _mt < 2; ++_mt) \
    _Pragma("unroll") for (int _h = 0; _h < 2; ++_h) { \
        int _row = wm * 32 + _mt * 16 + g + _h * 8; \
        float _ts = sm[O_RS + _row * 4] + sm[O_RS + _row * 4 + 1] + sm[O_RS + _row * 4 + 2] + sm[O_RS + _row * 4 + 3]; \
        float _tq = sm[O_RQ + _row * 4] + sm[O_RQ + _row * 4 + 1] + sm[O_RQ + _row * 4 + 2] + sm[O_RQ + _row * 4 + 3]; \
        float _mn = _ts * (1.f / 128.f); \
        (mean)[_mt][_h] = _mn; \
        (rstd)[_mt][_h] = rsqrtf(fmaxf(_tq * (1.f / 128.f) - _mn * _mn, 0.f) + 1e-5f); } \
    __syncthreads(); \
} while (0)

// ---------- weight prep (Wm, We) ----------
__global__ void k_prep(const float* __restrict__ Wm, const float* __restrict__ We) {
    extern __shared__ float ws[];   // [128][129]
    const float* W = blockIdx.x == 0 ? Wm : We;
    int tid = threadIdx.x;
    for (int t = 0; t < 16; ++t) {
        int id = tid + t * 256;
        int k = id >> 5, n4 = (id & 31) << 2;
        float4 v = *(const float4*)&W[k * Dd + n4];
        ws[k * 129 + n4] = v.x; ws[k * 129 + n4 + 1] = v.y;
        ws[k * 129 + n4 + 2] = v.z; ws[k * 129 + n4 + 3] = v.w;
    }
    __syncthreads();
    float* out = wfrag[blockIdx.x];
    for (int t = 0; t < 32; ++t) {
        int id = tid + t * 256;
        int lane = id & 31, kb = (id >> 5) & 15, nb = id >> 9;
        int n = nb * 8 + (lane >> 2), k = kb * 8 + (lane & 3);
        float2 o;
        o.x = tf32f(ws[k * 129 + n]);
        o.y = tf32f(ws[(k + 4) * 129 + n]);
        *(float2*)&out[id * 2] = o;
    }
}

// ---------- S, T, qk ----------
__global__ void k_small(const float* __restrict__ node, const float* __restrict__ Wmem,
                        const float* __restrict__ Wq, const float* __restrict__ bq,
                        const float* __restrict__ Wk) {
    int n = blockIdx.x, c = threadIdx.x;
    __shared__ float ns[Dd], qs[Dd];
    ns[c] = node[n * Dd + c];
    __syncthreads();
    float s = 0.f, t = 0.f, q = 0.f;
#pragma unroll 8
    for (int k = 0; k < Dd; ++k) {
        float nv = ns[k];
        s = fmaf(nv, Wmem[(Dd + k) * Dd + c], s);
        t = fmaf(nv, Wmem[(2 * Dd + k) * Dd + c], t);
        q = fmaf(nv, Wq[k * Dd + c], q);
    }
    sc_S[n * Dd + c] = s; sc_T[n * Dd + c] = t;
    qs[c] = q + bq[c];
    __syncthreads();
    float a[8] = {0,0,0,0,0,0,0,0};
#pragma unroll
    for (int hd = 0; hd < 128; ++hd)
        a[hd >> 4] = fmaf(Wk[c * Dd + hd], qs[hd], a[hd >> 4]);
#pragma unroll
    for (int h = 0; h < 8; ++h)
        sc_qk[n * 1024 + h * 128 + c] = a[h] * 0.25f;
}

// ---------- fused tile kernel: memory (f32 out) + edge_out ----------
__global__ __launch_bounds__(256, 2) void k_fused(
    const float* __restrict__ edge,
    const float* __restrict__ bm, const float* __restrict__ gm, const float* __restrict__ bem,
    const float* __restrict__ beb, const float* __restrict__ g1, const float* __restrict__ be1,
    const float* __restrict__ g2, const float* __restrict__ be2,
    float* __restrict__ oe)
{
    extern __shared__ float sm[];
    const uint32_t sb = smem_u32(sm);
    const int tid = threadIdx.x, w = tid >> 5, lane = tid & 31;
    const int wm = w >> 2, wn = w & 3, g = lane >> 2, t2 = (lane & 3) << 1;
    const int ib = blockIdx.x >> 3, jn0 = (blockIdx.x & 7) << 6;
    const size_t r0 = (size_t)blockIdx.x * 64;

#pragma unroll
    for (int t = 0; t < 16; ++t) { int id4 = tid + t * 256; cpa16(sb + (O_B0 + id4 * 4) * 4, wfrag[0] + id4 * 4); }
    CPC();

#pragma unroll
    for (int t = 0; t < 8; ++t) {
        int id = tid + t * 256;
        int r = id >> 5, c4 = (id & 31) << 2;
        float4 v = *(const float4*)&edge[(r0 + r) * Dd + c4];
        int base = AFR(r, c4);
        sm[O_A + base + 0] = tf32f(v.x); sm[O_A + base + 4] = tf32f(v.y);
        sm[O_A + base + 8] = tf32f(v.z); sm[O_A + base + 12] = tf32f(v.w);
    }
    if (tid < Dd) {
        sm[O_P + tid]  = bm[tid] + sc_T[ib * Dd + tid];
        sm[G_GM + tid] = gm[tid];  sm[G_BEM + tid] = bem[tid];
        sm[G_G1 + tid] = g1[tid];  sm[G_BE1 + tid] = be1[tid];
        sm[G_G2 + tid] = g2[tid];  sm[G_BE2 + tid] = be2[tid];
        sm[G_BEB + tid] = beb[tid];
    }
    CPW(0); __syncthreads();

    float c[2][4][4];
    mma_tile(sm + O_A, sm + O_B0, c);       // memory GEMM
    __syncthreads();
#pragma unroll
    for (int t = 0; t < 16; ++t) { int id4 = tid + t * 256; cpa16(sb + (O_B0 + id4 * 4) * 4, wfrag[1] + id4 * 4); }
    CPC();

    // epilogue1: memory = relu(LN(c + (bm+T) + S)), rewrite A-frags (tf32)
    {
        float sv[2][2] = {{0,0},{0,0}}, qv[2][2] = {{0,0},{0,0}};
#pragma unroll
        for (int mt = 0; mt < 2; ++mt) {
            int rA = wm * 32 + mt * 16 + g;
#pragma unroll
            for (int nt = 0; nt < 4; ++nt) {
                int col = wn * 32 + nt * 8 + t2;
                float p0 = sm[O_P + col], p1 = sm[O_P + col + 1];
                float2 s0 = *(const float2*)&sc_S[(jn0 + rA) * Dd + col];
                float2 s1 = *(const float2*)&sc_S[(jn0 + rA + 8) * Dd + col];
                c[mt][nt][0] += p0 + s0.x; c[mt][nt][1] += p1 + s0.y;
                c[mt][nt][2] += p0 + s1.x; c[mt][nt][3] += p1 + s1.y;
                sv[mt][0] += c[mt][nt][0] + c[mt][nt][1];
                qv[mt][0] += c[mt][nt][0]*c[mt][nt][0] + c[mt][nt][1]*c[mt][nt][1];
                sv[mt][1] += c[mt][nt][2] + c[mt][nt][3];
                qv[mt][1] += c[mt][nt][2]*c[mt][nt][2] + c[mt][nt][3]*c[mt][nt][3];
            }
        }
        float mean[2][2], rstd[2][2];
        ROWSTATS(sv, qv, mean, rstd);
#pragma unroll
        for (int mt = 0; mt < 2; ++mt) {
            int rA = wm * 32 + mt * 16 + g;
#pragma unroll
            for (int nt = 0; nt < 4; ++nt) {
                int col = wn * 32 + nt * 8 + t2;
                float ga0 = sm[G_GM + col], ga1 = sm[G_GM + col + 1];
                float bb0 = sm[G_BEM + col], bb1 = sm[G_BEM + col + 1];
                sm[O_A + AFR(rA, col)]     = tf32f(fmaxf((c[mt][nt][0]-mean[mt][0])*rstd[mt][0]*ga0+bb0, 0.f));
                sm[O_A + AFR(rA, col + 1)] = tf32f(fmaxf((c[mt][nt][1]-mean[mt][0])*rstd[mt][0]*ga1+bb1, 0.f));
                sm[O_A + AFR(rA + 8, col)]     = tf32f(fmaxf((c[mt][nt][2]-mean[mt][1])*rstd[mt][1]*ga0+bb0, 0.f));
                sm[O_A + AFR(rA + 8, col + 1)] = tf32f(fmaxf((c[mt][nt][3]-mean[mt][1])*rstd[mt][1]*ga1+bb1, 0.f));
            }
        }
    }
    CPW(0); __syncthreads();    // A rewritten + We ready

    mma_tile(sm + O_A, sm + O_B0, c);       // edge GEMM

    // write memory f32 [jn][ib][c], coalesced float4 (A-frags read-only now)
#pragma unroll
    for (int t = 0; t < 8; ++t) {
        int id4 = tid + t * 256;             // 2048 float4 over 64x128
        int r = id4 >> 5, c4 = (id4 & 31) << 2;
        int base = AFR(r, c4);
        float4 o;
        o.x = sm[O_A + base + 0]; o.y = sm[O_A + base + 4];
        o.z = sm[O_A + base + 8]; o.w = sm[O_A + base + 12];
        *(float4*)&sc_memf[((size_t)(jn0 + r) * Nn + ib) * Dd + c4] = o;
    }

    // epilogue2: out_edge = LN2(edge + relu(LN1(c + beb)))
    {
        float sv[2][2] = {{0,0},{0,0}}, qv[2][2] = {{0,0},{0,0}};
#pragma unroll
        for (int mt = 0; mt < 2; ++mt)
#pragma unroll
            for (int nt = 0; nt < 4; ++nt) {
                int col = wn * 32 + nt * 8 + t2;
                float b0 = sm[G_BEB + col], b1 = sm[G_BEB + col + 1];
                c[mt][nt][0] += b0; c[mt][nt][1] += b1;
                c[mt][nt][2] += b0; c[mt][nt][3] += b1;
                sv[mt][0] += c[mt][nt][0] + c[mt][nt][1];
                qv[mt][0] += c[mt][nt][0]*c[mt][nt][0] + c[mt][nt][1]*c[mt][nt][1];
                sv[mt][1] += c[mt][nt][2] + c[mt][nt][3];
                qv[mt][1] += c[mt][nt][2]*c[mt][nt][2] + c[mt][nt][3]*c[mt][nt][3];
            }
        float mean[2][2], rstd[2][2];
        ROWSTATS(sv, qv, mean, rstd);
        float sv2[2][2] = {{0,0},{0,0}}, qv2[2][2] = {{0,0},{0,0}};
#pragma unroll
        for (int mt = 0; mt < 2; ++mt) {
            int rA = wm * 32 + mt * 16 + g;
#pragma unroll
            for (int nt = 0; nt < 4; ++nt) {
                int col = wn * 32 + nt * 8 + t2;
                float ga0 = sm[G_G1 + col], ga1 = sm[G_G1 + col + 1];
                float bb0 = sm[G_BE1 + col], bb1 = sm[G_BE1 + col + 1];
                float2 e0 = *(const float2*)&edge[(r0 + rA) * Dd + col];
                float2 e1 = *(const float2*)&edge[(r0 + rA + 8) * Dd + col];
                float w00 = fmaxf((c[mt][nt][0]-mean[mt][0])*rstd[mt][0]*ga0+bb0, 0.f) + e0.x;
                float w01 = fmaxf((c[mt][nt][1]-mean[mt][0])*rstd[mt][0]*ga1+bb1, 0.f) + e0.y;
                float w10 = fmaxf((c[mt][nt][2]-mean[mt][1])*rstd[mt][1]*ga0+bb0, 0.f) + e1.x;
                float w11 = fmaxf((c[mt][nt][3]-mean[mt][1])*rstd[mt][1]*ga1+bb1, 0.f) + e1.y;
                c[mt][nt][0] = w00; c[mt][nt][1] = w01; c[mt][nt][2] = w10; c[mt][nt][3] = w11;
                sv2[mt][0] += w00 + w01; qv2[mt][0] += w00*w00 + w01*w01;
                sv2[mt][1] += w10 + w11; qv2[mt][1] += w10*w10 + w11*w11;
            }
        }
        ROWSTATS(sv2, qv2, mean, rstd);
#pragma unroll
        for (int mt = 0; mt < 2; ++mt) {
            int rA = wm * 32 + mt * 16 + g;
#pragma unroll
            for (int nt = 0; nt < 4; ++nt) {
                int col = wn * 32 + nt * 8 + t2;
                float ga0 = sm[G_G2 + col], ga1 = sm[G_G2 + col + 1];
                float bb0 = sm[G_BE2 + col], bb1 = sm[G_BE2 + col + 1];
                *(float2*)&oe[(r0 + rA) * Dd + col] =
                    make_float2((c[mt][nt][0]-mean[mt][0])*rstd[mt][0]*ga0+bb0,
                                (c[mt][nt][1]-mean[mt][0])*rstd[mt][0]*ga1+bb1);
                *(float2*)&oe[(r0 + rA + 8) * Dd + col] =
                    make_float2((c[mt][nt][2]-mean[mt][1])*rstd[mt][1]*ga0+bb0,
                                (c[mt][nt][3]-mean[mt][1])*rstd[mt][1]*ga1+bb1);
            }
        }
    }
}

// ---------- split-KV attention: partial kernel (one 64-key chunk per block) ----------
__global__ __launch_bounds__(256, 4) void k_attnp(const unsigned char* __restrict__ mask) {
    __shared__ float qk_s[1024];
    __shared__ float buf[64 * 132];
    __shared__ float scs[512], ps[512];
    const int bid = blockIdx.x, n = bid >> 3, part = bid & 7;
    const int tid = threadIdx.x, w = tid >> 5, lane = tid & 31;
    const uint32_t sbuf = smem_u32(buf);

    for (int i = tid; i < 1024; i += 256) qk_s[i] = sc_qk[n * 1024 + i];

    const float* src = sc_memf + ((size_t)n * Nn + part * 64) * Dd;
#pragma unroll
    for (int t = 0; t < 8; ++t) {
        int id4 = tid + t * 256;
        int m = id4 >> 5, j = id4 & 31;
        cpa16(sbuf + ((m * 132 + j * 4) << 2), src + (size_t)id4 * 4);
    }
    CPC(); CPW(0);
    __syncthreads();

    // scores: thread -> (m = sm_, heads h0, h0+1)
    {
        const int sm_ = tid & 63, h0 = (tid >> 6) << 1;
        float a0 = 0.f, a1 = 0.f;
        const float* mr = &buf[sm_ * 132];
        const float* qa = &qk_s[h0 * 128];
        const float* qb = &qk_s[(h0 + 1) * 128];
#pragma unroll 8
        for (int j = 0; j < 32; ++j) {
            float4 m4 = *(const float4*)&mr[j * 4];
            float4 a4 = *(const float4*)&qa[j * 4];
            float4 b4 = *(const float4*)&qb[j * 4];
            a0 += m4.x*a4.x + m4.y*a4.y + m4.z*a4.z + m4.w*a4.w;
            a1 += m4.x*b4.x + m4.y*b4.y + m4.z*b4.z + m4.w*b4.w;
        }
        bool mk = mask[n * Nn + part * 64 + sm_] != 0;
        scs[h0 * 64 + sm_]       = mk ? -1e30f : a0;
        scs[(h0 + 1) * 64 + sm_] = mk ? -1e30f : a1;
    }
    __syncthreads();

    float* op = &sc_part[(size_t)bid * 1040];
    // local softmax: warp w = head w (no online rescale — single chunk)
    {
        float s0v = scs[w * 64 + lane], s1v = scs[w * 64 + lane + 32];
        float mx = fmaxf(s0v, s1v);
#pragma unroll
        for (int off = 16; off >= 1; off >>= 1)
            mx = fmaxf(mx, __shfl_xor_sync(0xffffffffu, mx, off));
        float p0 = __expf(s0v - mx), p1 = __expf(s1v - mx);
        ps[w * 64 + lane] = p0; ps[w * 64 + lane + 32] = p1;
        float cs = p0 + p1;
#pragma unroll
        for (int off = 16; off >= 1; off >>= 1)
            cs += __shfl_xor_sync(0xffffffffu, cs, off);
        if (lane == 0) { op[1024 + w] = mx; op[1032 + w] = cs; }
    }
    __syncthreads();

    // unnormalized ctx: thread (h = w, cols lane*4..+3)
    {
        float c0 = 0.f, c1 = 0.f, c2 = 0.f, c3 = 0.f;
        const float* pp = &ps[w * 64];
#pragma unroll 8
        for (int m = 0; m < 64; ++m) {
            float p = pp[m];
            float4 v = *(const float4*)&buf[m * 132 + lane * 4];
            c0 = fmaf(p, v.x, c0); c1 = fmaf(p, v.y, c1);
            c2 = fmaf(p, v.z, c2); c3 = fmaf(p, v.w, c3);
        }
        *(float4*)&op[w * 128 + lane * 4] = make_float4(c0, c1, c2, c3);
    }
}

// ---------- split-KV attention: combine + Wv projection ----------
__global__ __launch_bounds__(256, 4) void k_attnc(const float* __restrict__ Wv,
                                                  const float* __restrict__ bv) {
    __shared__ float ctx_s[1024];
    __shared__ float f_s[64];     // [part][h]
    __shared__ float ginv_s[8];
    const int n = blockIdx.x, tid = threadIdx.x;
    const float* base = &sc_part[(size_t)(n * 8) * 1040];

    if (tid < 8) {
        int h = tid;
        float gmax = -1e30f;
#pragma unroll
        for (int p = 0; p < 8; ++p) gmax = fmaxf(gmax, base[(size_t)p * 1040 + 1024 + h]);
        float gsum = 0.f;
#pragma unroll
        for (int p = 0; p < 8; ++p) {
            float f = __expf(base[(size_t)p * 1040 + 1024 + h] - gmax);
            f_s[p * 8 + h] = f;
            gsum = fmaf(f, base[(size_t)p * 1040 + 1032 + h], gsum);
        }
        ginv_s[h] = 1.f / gsum;
    }
    __syncthreads();

    {
        int e0 = tid * 4, h = e0 >> 7;
        float a0 = 0.f, a1 = 0.f, a2 = 0.f, a3 = 0.f;
#pragma unroll
        for (int p = 0; p < 8; ++p) {
            float f = f_s[p * 8 + h];
            float4 v = *(const float4*)&base[(size_t)p * 1040 + e0];
            a0 = fmaf(f, v.x, a0); a1 = fmaf(f, v.y, a1);
            a2 = fmaf(f, v.z, a2); a3 = fmaf(f, v.w, a3);
        }
        float inv = ginv_s[h];
        ctx_s[e0] = a0 * inv; ctx_s[e0 + 1] = a1 * inv;
        ctx_s[e0 + 2] = a2 * inv; ctx_s[e0 + 3] = a3 * inv;
    }
    __syncthreads();

    if (tid < 128) {
        int h = tid >> 4;
        float acc = bv[tid];
#pragma unroll 8
        for (int cc = 0; cc < 128; ++cc)
            acc = fmaf(ctx_s[h * 128 + cc], Wv[cc * Dd + tid], acc);
        sc_o[n * Dd + tid] = acc;
    }
}

// ---------- final: out-proj + LN + FFN + LN ----------
__device__ __forceinline__ float bsum128(float v, float* tmp) {
    int lane = threadIdx.x & 31, wid = threadIdx.x >> 5;
#pragma unroll
    for (int off = 16; off >= 1; off >>= 1) v += __shfl_xor_sync(0xffffffffu, v, off);
    if (lane == 0) tmp[wid] = v;
    __syncthreads();
    float s = tmp[0] + tmp[1] + tmp[2] + tmp[3];
    __syncthreads();
    return s;
}
__global__ void k_final(const float* __restrict__ node,
                        const float* __restrict__ Wo, const float* __restrict__ bo,
                        const float* __restrict__ g2, const float* __restrict__ be2,
                        const float* __restrict__ W1, const float* __restrict__ b1,
                        const float* __restrict__ W2, const float* __restrict__ b2,
                        const float* __restrict__ g3, const float* __restrict__ be3,
                        float* __restrict__ out_x) {
    const int n = blockIdx.x;
    const int c = threadIdx.x;
    __shared__ float os[Dd], xs[Dd], hs[Df], tmp[4];
    os[c] = sc_o[n * Dd + c];
    __syncthreads();
    float t = bo[c];
#pragma unroll 8
    for (int k = 0; k < Dd; ++k) t = fmaf(os[k], Wo[k * Dd + c], t);
    float x = node[n * Dd + c] + t;
    float mean = bsum128(x, tmp) * (1.f / 128.f);
    float d = x - mean;
    float var = bsum128(d * d, tmp) * (1.f / 128.f);
    float xn = d * rsqrtf(var + 1e-5f) * g2[c] + be2[c];
    xs[c] = xn;
    __syncthreads();
    float h0 = b1[c], h1 = b1[c + 128];
#pragma unroll 8
    for (int k = 0; k < Dd; ++k) {
        float xv = xs[k];
        h0 = fmaf(xv, W1[k * Df + c], h0);
        h1 = fmaf(xv, W1[k * Df + c + 128], h1);
    }
    hs[c] = fmaxf(h0, 0.f);
    hs[c + 128] = fmaxf(h1, 0.f);
    __syncthreads();
    float y = b2[c];
#pragma unroll 8
    for (int f = 0; f < Df; ++f) y = fmaf(hs[f], W2[f * Dd + c], y);
    float z = xn + y;
    mean = bsum128(z, tmp) * (1.f / 128.f);
    d = z - mean;
    var = bsum128(d * d, tmp) * (1.f / 128.f);
    out_x[n * Dd + c] = d * rsqrtf(var + 1e-5f) * g3[c] + be3[c];
}

// ---------- host ----------
extern "C" void kernel_launch(void* const* d_in, const int* in_sizes, int n_in,
                              void* d_out, int out_size) {
    const float* node = (const float*)d_in[0];
    const float* edge = (const float*)d_in[1];
    const unsigned char* mask = (const unsigned char*)d_in[2];
    const float* W_mem = (const float*)d_in[3];
    const float* b_mem = (const float*)d_in[4];
    const float* g_mem = (const float*)d_in[5];
    const float* be_mem = (const float*)d_in[6];
    const float* W_e = (const float*)d_in[7];
    const float* b_e = (const float*)d_in[8];
    const float* g_e1 = (const float*)d_in[9];
    const float* be_e1 = (const float*)d_in[10];
    const float* g_e2 = (const float*)d_in[11];
    const float* be_e2 = (const float*)d_in[12];
    const float* Wq = (const float*)d_in[13];
    const float* bq = (const float*)d_in[14];
    const float* Wk = (const float*)d_in[15];
    const float* bk = (const float*)d_in[16]; (void)bk;   // cancels in softmax
    const float* Wv = (const float*)d_in[17];
    const float* bv = (const float*)d_in[18];
    const float* Wo = (const float*)d_in[19];
    const float* bo = (const float*)d_in[20];
    const float* W1 = (const float*)d_in[21];
    const float* b1 = (const float*)d_in[22];
    const float* W2 = (const float*)d_in[23];
    const float* b2 = (const float*)d_in[24];
    const float* g2 = (const float*)d_in[25];
    const float* be2 = (const float*)d_in[26];
    const float* g3 = (const float*)d_in[27];
    const float* be3 = (const float*)d_in[28];

    float* out = (float*)d_out;
    float* out_x = out;
    float* out_edge = out + Nn * Dd;

    static int init = 0;
    if (!init) {
        cudaFuncSetAttribute(k_prep, cudaFuncAttributeMaxDynamicSharedMemorySize, 128 * 129 * 4);
        cudaFuncSetAttribute(k_fused, cudaFuncAttributeMaxDynamicSharedMemorySize, DYN);
        init = 1;
    }

    k_prep<<<2, 256, 128 * 129 * 4>>>(W_mem, W_e);
    k_small<<<Nn, Dd>>>(node, W_mem, Wq, bq, Wk);
    k_fused<<<NT, 256, DYN>>>(edge, b_mem, g_mem, be_mem,
                              b_e, g_e1, be_e1, g_e2, be_e2, out_edge);
    k_attnp<<<4096, 256>>>(mask);
    k_attnc<<<Nn, 256>>>(Wv, bv);
    k_final<<<Nn, 128>>>(node, Wo, bo, g2, be2, W1, b1, W2, b2, g3, be3, out_x);
}

// round 12
// speedup vs baseline: 2.6202x; 1.0516x over previous
#include <cuda_runtime.h>
#include <math.h>
#include <stdint.h>

#define Nn 512
#define Dd 128
#define Df 256
#define Hh 8
#define ROWS (Nn*Nn)
#define NT 4096                   // 64-row tiles

__device__ float sc_S[Nn * Dd];
__device__ float sc_T[Nn * Dd];
__device__ float sc_qk[Nn * Hh * Dd];        // 0.25 * Wk^T q  per (n, h)
__device__ float sc_o[Nn * Dd];
__device__ float wfrag[2][16384];            // Wm_edge, We tf32 frag layout
__device__ float sc_memf[(size_t)ROWS * Dd]; // memory f32 [n][m][c] (134MB)
__device__ float sc_part[(size_t)4096 * 1040]; // split-KV partials (17MB)

// k_fused dynamic smem float offsets (B0 eliminated — weights read from L1/L2)
#define O_A  0                    // 8192
#define O_RS 8192                 // 256
#define O_RQ 8448                 // 256
#define O_P  8704                 // 128 (bm + T)
#define O_G  8832                 // 7*128
#define SMF  9728
#define DYN  (SMF * 4)            // 38912 B -> 3+ CTA/SM

#define G_GM  (O_G + 0)
#define G_BEM (O_G + 128)
#define G_G1  (O_G + 256)
#define G_BE1 (O_G + 384)
#define G_G2  (O_G + 512)
#define G_BE2 (O_G + 640)
#define G_BEB (O_G + 768)

__device__ __forceinline__ uint32_t tf32c(float x) {
    uint32_t y; asm("cvt.rna.tf32.f32 %0, %1;" : "=r"(y) : "f"(x)); return y;
}
__device__ __forceinline__ float tf32f(float x) { return __uint_as_float(tf32c(x)); }

__device__ __forceinline__ uint32_t smem_u32(const void* p) {
    uint32_t a;
    asm("{ .reg .u64 t; cvta.to.shared.u64 t, %1; cvt.u32.u64 %0, t; }" : "=r"(a) : "l"(p));
    return a;
}
__device__ __forceinline__ void cpa16(uint32_t s, const void* g) {
    asm volatile("cp.async.cg.shared.global [%0], [%1], 16;" :: "r"(s), "l"(g));
}
#define CPC() asm volatile("cp.async.commit_group;" ::: "memory")
#define CPW(n) asm volatile("cp.async.wait_group %0;" :: "n"(n) : "memory")

__device__ __forceinline__ void mma8(float* c, const uint32_t* a, const uint32_t* b) {
    asm volatile(
        "mma.sync.aligned.m16n8k8.row.col.f32.tf32.tf32.f32 "
        "{%0,%1,%2,%3},{%4,%5,%6,%7},{%8,%9},{%0,%1,%2,%3};"
        : "+f"(c[0]), "+f"(c[1]), "+f"(c[2]), "+f"(c[3])
        : "r"(a[0]), "r"(a[1]), "r"(a[2]), "r"(a[3]), "r"(b[0]), "r"(b[1]));
}

// A-fragment float index for element (row r, col c), r<64 — bank-swizzled
__device__ __forceinline__ int AFR(int r, int c) {
    int kb = c >> 3;
    int q  = ((r & 7) << 2) + (c & 3);
    return ((((r >> 4) * 16 + kb) * 32 + (q ^ ((kb & 7) << 2))) << 2)
           + ((r >> 3) & 1) + (((c >> 2) & 1) << 1);
}

// 64x128x128 tile MMA: 8 warps 2(m) x 4(n), warp tile 32x32.
// A from smem fragments; B read directly from gmem wfrag (L1/L2-resident).
__device__ __forceinline__ void mma_tile(const float* sA, const float* __restrict__ gB,
                                         float c[2][4][4]) {
    int tid = threadIdx.x, w = tid >> 5, lane = tid & 31;
    int wm = w >> 2, wn = w & 3;
#pragma unroll
    for (int mt = 0; mt < 2; ++mt)
#pragma unroll
        for (int nt = 0; nt < 4; ++nt)
#pragma unroll
            for (int i = 0; i < 4; ++i) c[mt][nt][i] = 0.f;
#pragma unroll
    for (int kc = 0; kc < 16; ++kc) {
        uint32_t a[2][4];
#pragma unroll
        for (int mt = 0; mt < 2; ++mt) {
            float4 v = *(const float4*)&sA[((((wm * 2 + mt) * 16 + kc) * 32
                                            + (lane ^ ((kc & 7) << 2))) << 2)];
            a[mt][0] = __float_as_uint(v.x); a[mt][1] = __float_as_uint(v.y);
            a[mt][2] = __float_as_uint(v.z); a[mt][3] = __float_as_uint(v.w);
        }
#pragma unroll
        for (int nt = 0; nt < 4; ++nt) {
            float2 bv = __ldg((const float2*)&gB[(((wn * 4 + nt) * 16 + kc) * 32 + lane) * 2]);
            uint32_t b[2] = {__float_as_uint(bv.x), __float_as_uint(bv.y)};
            mma8(c[0][nt], a[0], b);
            mma8(c[1][nt], a[1], b);
        }
    }
}

#define ROWSTATS(sv, qv, mean, rstd) do { \
    _Pragma("unroll") for (int _mt = 0; _mt < 2; ++_mt) \
    _Pragma("unroll") for (int _h = 0; _h < 2; ++_h) { \
        float _s = (sv)[_mt][_h], _q = (qv)[_mt][_h]; \
        _s += __shfl_xor_sync(0xffffffffu, _s, 1); _q += __shfl_xor_sync(0xffffffffu, _q, 1); \
        _s += __shfl_xor_sync(0xffffffffu, _s, 2); _q += __shfl_xor_sync(0xffffffffu, _q, 2); \
        (sv)[_mt][_h] = _s; (qv)[_mt][_h] = _q; } \
    if ((lane & 3) == 0) { \
        _Pragma("unroll") for (int _mt = 0; _mt < 2; ++_mt) \
        _Pragma("unroll") for (int _h = 0; _h < 2; ++_h) { \
            int _row = wm * 32 + _mt * 16 + g + _h * 8; \
            sm[O_RS + _row * 4 + wn] = (sv)[_mt][_h]; \
            sm[O_RQ + _row * 4 + wn] = (qv)[_mt][_h]; } } \
    __syncthreads(); \
    _Pragma("unroll") for (int _mt = 0; _mt < 2; ++_mt) \
    _Pragma("unroll") for (int _h = 0; _h < 2; ++_h) { \
        int _row = wm * 32 + _mt * 16 + g + _h * 8; \
        float _ts = sm[O_RS + _row * 4] + sm[O_RS + _row * 4 + 1] + sm[O_RS + _row * 4 + 2] + sm[O_RS + _row * 4 + 3]; \
        float _tq = sm[O_RQ + _row * 4] + sm[O_RQ + _row * 4 + 1] + sm[O_RQ + _row * 4 + 2] + sm[O_RQ + _row * 4 + 3]; \
        float _mn = _ts * (1.f / 128.f); \
        (mean)[_mt][_h] = _mn; \
        (rstd)[_mt][_h] = rsqrtf(fmaxf(_tq * (1.f / 128.f) - _mn * _mn, 0.f) + 1e-5f); } \
    __syncthreads(); \
} while (0)

// ---------- weight prep (Wm, We) ----------
__global__ void k_prep(const float* __restrict__ Wm, const float* __restrict__ We) {
    extern __shared__ float ws[];   // [128][129]
    const float* W = blockIdx.x == 0 ? Wm : We;
    int tid = threadIdx.x;
    for (int t = 0; t < 16; ++t) {
        int id = tid + t * 256;
        int k = id >> 5, n4 = (id & 31) << 2;
        float4 v = *(const float4*)&W[k * Dd + n4];
        ws[k * 129 + n4] = v.x; ws[k * 129 + n4 + 1] = v.y;
        ws[k * 129 + n4 + 2] = v.z; ws[k * 129 + n4 + 3] = v.w;
    }
    __syncthreads();
    float* out = wfrag[blockIdx.x];
    for (int t = 0; t < 32; ++t) {
        int id = tid + t * 256;
        int lane = id & 31, kb = (id >> 5) & 15, nb = id >> 9;
        int n = nb * 8 + (lane >> 2), k = kb * 8 + (lane & 3);
        float2 o;
        o.x = tf32f(ws[k * 129 + n]);
        o.y = tf32f(ws[(k + 4) * 129 + n]);
        *(float2*)&out[id * 2] = o;
    }
}

// ---------- S, T, qk ----------
__global__ void k_small(const float* __restrict__ node, const float* __restrict__ Wmem,
                        const float* __restrict__ Wq, const float* __restrict__ bq,
                        const float* __restrict__ Wk) {
    int n = blockIdx.x, c = threadIdx.x;
    __shared__ float ns[Dd], qs[Dd];
    ns[c] = node[n * Dd + c];
    __syncthreads();
    float s = 0.f, t = 0.f, q = 0.f;
#pragma unroll 8
    for (int k = 0; k < Dd; ++k) {
        float nv = ns[k];
        s = fmaf(nv, Wmem[(Dd + k) * Dd + c], s);
        t = fmaf(nv, Wmem[(2 * Dd + k) * Dd + c], t);
        q = fmaf(nv, Wq[k * Dd + c], q);
    }
    sc_S[n * Dd + c] = s; sc_T[n * Dd + c] = t;
    qs[c] = q + bq[c];
    __syncthreads();
    float a[8] = {0,0,0,0,0,0,0,0};
#pragma unroll
    for (int hd = 0; hd < 128; ++hd)
        a[hd >> 4] = fmaf(Wk[c * Dd + hd], qs[hd], a[hd >> 4]);
#pragma unroll
    for (int h = 0; h < 8; ++h)
        sc_qk[n * 1024 + h * 128 + c] = a[h] * 0.25f;
}

// ---------- fused tile kernel: memory (f32 out) + edge_out ----------
__global__ __launch_bounds__(256, 3) void k_fused(
    const float* __restrict__ edge,
    const float* __restrict__ bm, const float* __restrict__ gm, const float* __restrict__ bem,
    const float* __restrict__ beb, const float* __restrict__ g1, const float* __restrict__ be1,
    const float* __restrict__ g2, const float* __restrict__ be2,
    float* __restrict__ oe)
{
    extern __shared__ float sm[];
    const int tid = threadIdx.x, w = tid >> 5, lane = tid & 31;
    const int wm = w >> 2, wn = w & 3, g = lane >> 2, t2 = (lane & 3) << 1;
    const int ib = blockIdx.x >> 3, jn0 = (blockIdx.x & 7) << 6;
    const size_t r0 = (size_t)blockIdx.x * 64;

    // A <- edge (tf32 frags)
#pragma unroll
    for (int t = 0; t < 8; ++t) {
        int id = tid + t * 256;
        int r = id >> 5, c4 = (id & 31) << 2;
        float4 v = *(const float4*)&edge[(r0 + r) * Dd + c4];
        int base = AFR(r, c4);
        sm[O_A + base + 0] = tf32f(v.x); sm[O_A + base + 4] = tf32f(v.y);
        sm[O_A + base + 8] = tf32f(v.z); sm[O_A + base + 12] = tf32f(v.w);
    }
    if (tid < Dd) {
        sm[O_P + tid]  = bm[tid] + sc_T[ib * Dd + tid];
        sm[G_GM + tid] = gm[tid];  sm[G_BEM + tid] = bem[tid];
        sm[G_G1 + tid] = g1[tid];  sm[G_BE1 + tid] = be1[tid];
        sm[G_G2 + tid] = g2[tid];  sm[G_BE2 + tid] = be2[tid];
        sm[G_BEB + tid] = beb[tid];
    }
    __syncthreads();

    float c[2][4][4];
    mma_tile(sm + O_A, wfrag[0], c);        // memory GEMM (B from L1/L2)
    __syncthreads();

    // epilogue1: memory = relu(LN(c + (bm+T) + S)), rewrite A-frags (tf32)
    {
        float sv[2][2] = {{0,0},{0,0}}, qv[2][2] = {{0,0},{0,0}};
#pragma unroll
        for (int mt = 0; mt < 2; ++mt) {
            int rA = wm * 32 + mt * 16 + g;
#pragma unroll
            for (int nt = 0; nt < 4; ++nt) {
                int col = wn * 32 + nt * 8 + t2;
                float p0 = sm[O_P + col], p1 = sm[O_P + col + 1];
                float2 s0 = *(const float2*)&sc_S[(jn0 + rA) * Dd + col];
                float2 s1 = *(const float2*)&sc_S[(jn0 + rA + 8) * Dd + col];
                c[mt][nt][0] += p0 + s0.x; c[mt][nt][1] += p1 + s0.y;
                c[mt][nt][2] += p0 + s1.x; c[mt][nt][3] += p1 + s1.y;
                sv[mt][0] += c[mt][nt][0] + c[mt][nt][1];
                qv[mt][0] += c[mt][nt][0]*c[mt][nt][0] + c[mt][nt][1]*c[mt][nt][1];
                sv[mt][1] += c[mt][nt][2] + c[mt][nt][3];
                qv[mt][1] += c[mt][nt][2]*c[mt][nt][2] + c[mt][nt][3]*c[mt][nt][3];
            }
        }
        float mean[2][2], rstd[2][2];
        ROWSTATS(sv, qv, mean, rstd);
#pragma unroll
        for (int mt = 0; mt < 2; ++mt) {
            int rA = wm * 32 + mt * 16 + g;
#pragma unroll
            for (int nt = 0; nt < 4; ++nt) {
                int col = wn * 32 + nt * 8 + t2;
                float ga0 = sm[G_GM + col], ga1 = sm[G_GM + col + 1];
                float bb0 = sm[G_BEM + col], bb1 = sm[G_BEM + col + 1];
                sm[O_A + AFR(rA, col)]     = tf32f(fmaxf((c[mt][nt][0]-mean[mt][0])*rstd[mt][0]*ga0+bb0, 0.f));
                sm[O_A + AFR(rA, col + 1)] = tf32f(fmaxf((c[mt][nt][1]-mean[mt][0])*rstd[mt][0]*ga1+bb1, 0.f));
                sm[O_A + AFR(rA + 8, col)]     = tf32f(fmaxf((c[mt][nt][2]-mean[mt][1])*rstd[mt][1]*ga0+bb0, 0.f));
                sm[O_A + AFR(rA + 8, col + 1)] = tf32f(fmaxf((c[mt][nt][3]-mean[mt][1])*rstd[mt][1]*ga1+bb1, 0.f));
            }
        }
    }
    __syncthreads();

    mma_tile(sm + O_A, wfrag[1], c);        // edge GEMM (B from L1/L2)

    // write memory f32 [jn][ib][c], coalesced float4 (A-frags read-only now)
#pragma unroll
    for (int t = 0; t < 8; ++t) {
        int id4 = tid + t * 256;             // 2048 float4 over 64x128
        int r = id4 >> 5, c4 = (id4 & 31) << 2;
        int base = AFR(r, c4);
        float4 o;
        o.x = sm[O_A + base + 0]; o.y = sm[O_A + base + 4];
        o.z = sm[O_A + base + 8]; o.w = sm[O_A + base + 12];
        *(float4*)&sc_memf[((size_t)(jn0 + r) * Nn + ib) * Dd + c4] = o;
    }

    // epilogue2: out_edge = LN2(edge + relu(LN1(c + beb)))
    {
        float sv[2][2] = {{0,0},{0,0}}, qv[2][2] = {{0,0},{0,0}};
#pragma unroll
        for (int mt = 0; mt < 2; ++mt)
#pragma unroll
            for (int nt = 0; nt < 4; ++nt) {
                int col = wn * 32 + nt * 8 + t2;
                float b0 = sm[G_BEB + col], b1 = sm[G_BEB + col + 1];
                c[mt][nt][0] += b0; c[mt][nt][1] += b1;
                c[mt][nt][2] += b0; c[mt][nt][3] += b1;
                sv[mt][0] += c[mt][nt][0] + c[mt][nt][1];
                qv[mt][0] += c[mt][nt][0]*c[mt][nt][0] + c[mt][nt][1]*c[mt][nt][1];
                sv[mt][1] += c[mt][nt][2] + c[mt][nt][3];
                qv[mt][1] += c[mt][nt][2]*c[mt][nt][2] + c[mt][nt][3]*c[mt][nt][3];
            }
        float mean[2][2], rstd[2][2];
        ROWSTATS(sv, qv, mean, rstd);
        float sv2[2][2] = {{0,0},{0,0}}, qv2[2][2] = {{0,0},{0,0}};
#pragma unroll
        for (int mt = 0; mt < 2; ++mt) {
            int rA = wm * 32 + mt * 16 + g;
#pragma unroll
            for (int nt = 0; nt < 4; ++nt) {
                int col = wn * 32 + nt * 8 + t2;
                float ga0 = sm[G_G1 + col], ga1 = sm[G_G1 + col + 1];
                float bb0 = sm[G_BE1 + col], bb1 = sm[G_BE1 + col + 1];
                float2 e0 = *(const float2*)&edge[(r0 + rA) * Dd + col];
                float2 e1 = *(const float2*)&edge[(r0 + rA + 8) * Dd + col];
                float w00 = fmaxf((c[mt][nt][0]-mean[mt][0])*rstd[mt][0]*ga0+bb0, 0.f) + e0.x;
                float w01 = fmaxf((c[mt][nt][1]-mean[mt][0])*rstd[mt][0]*ga1+bb1, 0.f) + e0.y;
                float w10 = fmaxf((c[mt][nt][2]-mean[mt][1])*rstd[mt][1]*ga0+bb0, 0.f) + e1.x;
                float w11 = fmaxf((c[mt][nt][3]-mean[mt][1])*rstd[mt][1]*ga1+bb1, 0.f) + e1.y;
                c[mt][nt][0] = w00; c[mt][nt][1] = w01; c[mt][nt][2] = w10; c[mt][nt][3] = w11;
                sv2[mt][0] += w00 + w01; qv2[mt][0] += w00*w00 + w01*w01;
                sv2[mt][1] += w10 + w11; qv2[mt][1] += w10*w10 + w11*w11;
            }
        }
        ROWSTATS(sv2, qv2, mean, rstd);
#pragma unroll
        for (int mt = 0; mt < 2; ++mt) {
            int rA = wm * 32 + mt * 16 + g;
#pragma unroll
            for (int nt = 0; nt < 4; ++nt) {
                int col = wn * 32 + nt * 8 + t2;
                float ga0 = sm[G_G2 + col], ga1 = sm[G_G2 + col + 1];
                float bb0 = sm[G_BE2 + col], bb1 = sm[G_BE2 + col + 1];
                *(float2*)&oe[(r0 + rA) * Dd + col] =
                    make_float2((c[mt][nt][0]-mean[mt][0])*rstd[mt][0]*ga0+bb0,
                                (c[mt][nt][1]-mean[mt][0])*rstd[mt][0]*ga1+bb1);
                *(float2*)&oe[(r0 + rA + 8) * Dd + col] =
                    make_float2((c[mt][nt][2]-mean[mt][1])*rstd[mt][1]*ga0+bb0,
                                (c[mt][nt][3]-mean[mt][1])*rstd[mt][1]*ga1+bb1);
            }
        }
    }
}

// ---------- split-KV attention: partial kernel (one 64-key chunk per block) ----------
__global__ __launch_bounds__(256, 4) void k_attnp(const unsigned char* __restrict__ mask) {
    __shared__ float qk_s[1024];
    __shared__ float buf[64 * 132];
    __shared__ float scs[512], ps[512];
    const int bid = blockIdx.x, n = bid >> 3, part = bid & 7;
    const int tid = threadIdx.x, w = tid >> 5, lane = tid & 31;
    const uint32_t sbuf = smem_u32(buf);

    for (int i = tid; i < 1024; i += 256) qk_s[i] = sc_qk[n * 1024 + i];

    const float* src = sc_memf + ((size_t)n * Nn + part * 64) * Dd;
#pragma unroll
    for (int t = 0; t < 8; ++t) {
        int id4 = tid + t * 256;
        int m = id4 >> 5, j = id4 & 31;
        cpa16(sbuf + ((m * 132 + j * 4) << 2), src + (size_t)id4 * 4);
    }
    CPC(); CPW(0);
    __syncthreads();

    // scores: thread -> (m = sm_, heads h0, h0+1)
    {
        const int sm_ = tid & 63, h0 = (tid >> 6) << 1;
        float a0 = 0.f, a1 = 0.f;
        const float* mr = &buf[sm_ * 132];
        const float* qa = &qk_s[h0 * 128];
        const float* qb = &qk_s[(h0 + 1) * 128];
#pragma unroll 8
        for (int j = 0; j < 32; ++j) {
            float4 m4 = *(const float4*)&mr[j * 4];
            float4 a4 = *(const float4*)&qa[j * 4];
            float4 b4 = *(const float4*)&qb[j * 4];
            a0 += m4.x*a4.x + m4.y*a4.y + m4.z*a4.z + m4.w*a4.w;
            a1 += m4.x*b4.x + m4.y*b4.y + m4.z*b4.z + m4.w*b4.w;
        }
        bool mk = mask[n * Nn + part * 64 + sm_] != 0;
        scs[h0 * 64 + sm_]       = mk ? -1e30f : a0;
        scs[(h0 + 1) * 64 + sm_] = mk ? -1e30f : a1;
    }
    __syncthreads();

    float* op = &sc_part[(size_t)bid * 1040];
    // local softmax: warp w = head w (single chunk, no online rescale)
    {
        float s0v = scs[w * 64 + lane], s1v = scs[w * 64 + lane + 32];
        float mx = fmaxf(s0v, s1v);
#pragma unroll
        for (int off = 16; off >= 1; off >>= 1)
            mx = fmaxf(mx, __shfl_xor_sync(0xffffffffu, mx, off));
        float p0 = __expf(s0v - mx), p1 = __expf(s1v - mx);
        ps[w * 64 + lane] = p0; ps[w * 64 + lane + 32] = p1;
        float cs = p0 + p1;
#pragma unroll
        for (int off = 16; off >= 1; off >>= 1)
            cs += __shfl_xor_sync(0xffffffffu, cs, off);
        if (lane == 0) { op[1024 + w] = mx; op[1032 + w] = cs; }
    }
    __syncthreads();

    // unnormalized ctx: thread (h = w, cols lane*4..+3)
    {
        float c0 = 0.f, c1 = 0.f, c2 = 0.f, c3 = 0.f;
        const float* pp = &ps[w * 64];
#pragma unroll 8
        for (int m = 0; m < 64; ++m) {
            float p = pp[m];
            float4 v = *(const float4*)&buf[m * 132 + lane * 4];
            c0 = fmaf(p, v.x, c0); c1 = fmaf(p, v.y, c1);
            c2 = fmaf(p, v.z, c2); c3 = fmaf(p, v.w, c3);
        }
        *(float4*)&op[w * 128 + lane * 4] = make_float4(c0, c1, c2, c3);
    }
}

// ---------- split-KV attention: combine + Wv projection ----------
__global__ __launch_bounds__(256, 4) void k_attnc(const float* __restrict__ Wv,
                                                  const float* __restrict__ bv) {
    __shared__ float ctx_s[1024];
    __shared__ float f_s[64];     // [part][h]
    __shared__ float ginv_s[8];
    const int n = blockIdx.x, tid = threadIdx.x;
    const float* base = &sc_part[(size_t)(n * 8) * 1040];

    if (tid < 8) {
        int h = tid;
        float gmax = -1e30f;
#pragma unroll
        for (int p = 0; p < 8; ++p) gmax = fmaxf(gmax, base[(size_t)p * 1040 + 1024 + h]);
        float gsum = 0.f;
#pragma unroll
        for (int p = 0; p < 8; ++p) {
            float f = __expf(base[(size_t)p * 1040 + 1024 + h] - gmax);
            f_s[p * 8 + h] = f;
            gsum = fmaf(f, base[(size_t)p * 1040 + 1032 + h], gsum);
        }
        ginv_s[h] = 1.f / gsum;
    }
    __syncthreads();

    {
        int e0 = tid * 4, h = e0 >> 7;
        float a0 = 0.f, a1 = 0.f, a2 = 0.f, a3 = 0.f;
#pragma unroll
        for (int p = 0; p < 8; ++p) {
            float f = f_s[p * 8 + h];
            float4 v = *(const float4*)&base[(size_t)p * 1040 + e0];
            a0 = fmaf(f, v.x, a0); a1 = fmaf(f, v.y, a1);
            a2 = fmaf(f, v.z, a2); a3 = fmaf(f, v.w, a3);
        }
        float inv = ginv_s[h];
        ctx_s[e0] = a0 * inv; ctx_s[e0 + 1] = a1 * inv;
        ctx_s[e0 + 2] = a2 * inv; ctx_s[e0 + 3] = a3 * inv;
    }
    __syncthreads();

    if (tid < 128) {
        int h = tid >> 4;
        float acc = bv[tid];
#pragma unroll 8
        for (int cc = 0; cc < 128; ++cc)
            acc = fmaf(ctx_s[h * 128 + cc], Wv[cc * Dd + tid], acc);
        sc_o[n * Dd + tid] = acc;
    }
}

// ---------- final: out-proj + LN + FFN + LN ----------
__device__ __forceinline__ float bsum128(float v, float* tmp) {
    int lane = threadIdx.x & 31, wid = threadIdx.x >> 5;
#pragma unroll
    for (int off = 16; off >= 1; off >>= 1) v += __shfl_xor_sync(0xffffffffu, v, off);
    if (lane == 0) tmp[wid] = v;
    __syncthreads();
    float s = tmp[0] + tmp[1] + tmp[2] + tmp[3];
    __syncthreads();
    return s;
}
__global__ void k_final(const float* __restrict__ node,
                        const float* __restrict__ Wo, const float* __restrict__ bo,
                        const float* __restrict__ g2, const float* __restrict__ be2,
                        const float* __restrict__ W1, const float* __restrict__ b1,
                        const float* __restrict__ W2, const float* __restrict__ b2,
                        const float* __restrict__ g3, const float* __restrict__ be3,
                        float* __restrict__ out_x) {
    const int n = blockIdx.x;
    const int c = threadIdx.x;
    __shared__ float os[Dd], xs[Dd], hs[Df], tmp[4];
    os[c] = sc_o[n * Dd + c];
    __syncthreads();
    float t = bo[c];
#pragma unroll 8
    for (int k = 0; k < Dd; ++k) t = fmaf(os[k], Wo[k * Dd + c], t);
    float x = node[n * Dd + c] + t;
    float mean = bsum128(x, tmp) * (1.f / 128.f);
    float d = x - mean;
    float var = bsum128(d * d, tmp) * (1.f / 128.f);
    float xn = d * rsqrtf(var + 1e-5f) * g2[c] + be2[c];
    xs[c] = xn;
    __syncthreads();
    float h0 = b1[c], h1 = b1[c + 128];
#pragma unroll 8
    for (int k = 0; k < Dd; ++k) {
        float xv = xs[k];
        h0 = fmaf(xv, W1[k * Df + c], h0);
        h1 = fmaf(xv, W1[k * Df + c + 128], h1);
    }
    hs[c] = fmaxf(h0, 0.f);
    hs[c + 128] = fmaxf(h1, 0.f);
    __syncthreads();
    float y = b2[c];
#pragma unroll 8
    for (int f = 0; f < Df; ++f) y = fmaf(hs[f], W2[f * Dd + c], y);
    float z = xn + y;
    mean = bsum128(z, tmp) * (1.f / 128.f);
    d = z - mean;
    var = bsum128(d * d, tmp) * (1.f / 128.f);
    out_x[n * Dd + c] = d * rsqrtf(var + 1e-5f) * g3[c] + be3[c];
}

// ---------- host ----------
extern "C" void kernel_launch(void* const* d_in, const int* in_sizes, int n_in,
                              void* d_out, int out_size) {
    const float* node = (const float*)d_in[0];
    const float* edge = (const float*)d_in[1];
    const unsigned char* mask = (const unsigned char*)d_in[2];
    const float* W_mem = (const float*)d_in[3];
    const float* b_mem = (const float*)d_in[4];
    const float* g_mem = (const float*)d_in[5];
    const float* be_mem = (const float*)d_in[6];
    const float* W_e = (const float*)d_in[7];
    const float* b_e = (const float*)d_in[8];
    const float* g_e1 = (const float*)d_in[9];
    const float* be_e1 = (const float*)d_in[10];
    const float* g_e2 = (const float*)d_in[11];
    const float* be_e2 = (const float*)d_in[12];
    const float* Wq = (const float*)d_in[13];
    const float* bq = (const float*)d_in[14];
    const float* Wk = (const float*)d_in[15];
    const float* bk = (const float*)d_in[16]; (void)bk;   // cancels in softmax
    const float* Wv = (const float*)d_in[17];
    const float* bv = (const float*)d_in[18];
    const float* Wo = (const float*)d_in[19];
    const float* bo = (const float*)d_in[20];
    const float* W1 = (const float*)d_in[21];
    const float* b1 = (const float*)d_in[22];
    const float* W2 = (const float*)d_in[23];
    const float* b2 = (const float*)d_in[24];
    const float* g2 = (const float*)d_in[25];
    const float* be2 = (const float*)d_in[26];
    const float* g3 = (const float*)d_in[27];
    const float* be3 = (const float*)d_in[28];

    float* out = (float*)d_out;
    float* out_x = out;
    float* out_edge = out + Nn * Dd;

    static int init = 0;
    if (!init) {
        cudaFuncSetAttribute(k_prep, cudaFuncAttributeMaxDynamicSharedMemorySize, 128 * 129 * 4);
        cudaFuncSetAttribute(k_fused, cudaFuncAttributeMaxDynamicSharedMemorySize, DYN);
        init = 1;
    }

    k_prep<<<2, 256, 128 * 129 * 4>>>(W_mem, W_e);
    k_small<<<Nn, Dd>>>(node, W_mem, Wq, bq, Wk);
    k_fused<<<NT, 256, DYN>>>(edge, b_mem, g_mem, be_mem,
                              b_e, g_e1, be_e1, g_e2, be_e2, out_edge);
    k_attnp<<<4096, 256>>>(mask);
    k_attnc<<<Nn, 256>>>(Wv, bv);
    k_final<<<Nn, 128>>>(node, Wo, bo, g2, be2, W1, b1, W2, b2, g3, be3, out_x);
}

// round 13
// speedup vs baseline: 2.8274x; 1.0791x over previous
#include <cuda_runtime.h>
#include <math.h>
#include <stdint.h>

#define Nn 512
#define Dd 128
#define Df 256
#define Hh 8
#define ROWS (Nn*Nn)
#define NT 4096                   // 64-row tiles

__device__ float sc_S[Nn * Dd];
__device__ float sc_T[Nn * Dd];
__device__ float sc_qk[Nn * Hh * Dd];        // 0.25 * Wk^T q  per (n, h)
__device__ float sc_o[Nn * Dd];
__device__ float wfrag[2][16384];            // Wm_edge, We tf32 frag layout
__device__ float sc_memf[(size_t)ROWS * Dd]; // memory f32 [n][m][c] (134MB)
__device__ float sc_part[(size_t)4096 * 1040]; // split-KV partials (17MB)

// k_fused dynamic smem float offsets
#define O_A  0                    // 8192
#define O_RS 8192                 // 256
#define O_RQ 8448                 // 256
#define O_P  8704                 // 128 (bm + T)
#define O_G  8832                 // 7*128
#define SMF  9728
#define DYN  (SMF * 4)            // 38912 B -> 3 CTA/SM

#define G_GM  (O_G + 0)
#define G_BEM (O_G + 128)
#define G_G1  (O_G + 256)
#define G_BE1 (O_G + 384)
#define G_G2  (O_G + 512)
#define G_BE2 (O_G + 640)
#define G_BEB (O_G + 768)

__device__ __forceinline__ uint32_t tf32c(float x) {
    uint32_t y; asm("cvt.rna.tf32.f32 %0, %1;" : "=r"(y) : "f"(x)); return y;
}
__device__ __forceinline__ float tf32f(float x) { return __uint_as_float(tf32c(x)); }

__device__ __forceinline__ uint32_t smem_u32(const void* p) {
    uint32_t a;
    asm("{ .reg .u64 t; cvta.to.shared.u64 t, %1; cvt.u32.u64 %0, t; }" : "=r"(a) : "l"(p));
    return a;
}
__device__ __forceinline__ void cpa16(uint32_t s, const void* g) {
    asm volatile("cp.async.cg.shared.global [%0], [%1], 16;" :: "r"(s), "l"(g));
}
#define CPC() asm volatile("cp.async.commit_group;" ::: "memory")
#define CPW(n) asm volatile("cp.async.wait_group %0;" :: "n"(n) : "memory")

__device__ __forceinline__ void mma8(float* c, const uint32_t* a, const uint32_t* b) {
    asm volatile(
        "mma.sync.aligned.m16n8k8.row.col.f32.tf32.tf32.f32 "
        "{%0,%1,%2,%3},{%4,%5,%6,%7},{%8,%9},{%0,%1,%2,%3};"
        : "+f"(c[0]), "+f"(c[1]), "+f"(c[2]), "+f"(c[3])
        : "r"(a[0]), "r"(a[1]), "r"(a[2]), "r"(a[3]), "r"(b[0]), "r"(b[1]));
}

// A-fragment float index, plane-split layout [frag][reg(4)][qx(32)]:
// bank = qx -> full diversity. For c%4==0, AFR2(r,c)+j == element (r,c+j).
__device__ __forceinline__ int AFR2(int r, int c) {
    int kb = c >> 3;
    int frag = (r >> 4) * 16 + kb;
    int reg = ((r >> 3) & 1) + (((c >> 2) & 1) << 1);
    int qx = ((((r & 7) << 2) + (c & 3)) ^ ((kb & 7) << 2));
    return frag * 128 + reg * 32 + qx;
}

// 64x128x128 tile MMA: 8 warps 2(m) x 4(n), warp tile 32x32.
// A from smem plane-split fragments (4x LDS.32, conflict-free); B from gmem wfrag (L1/L2).
__device__ __forceinline__ void mma_tile(const float* sA, const float* __restrict__ gB,
                                         float c[2][4][4]) {
    int tid = threadIdx.x, w = tid >> 5, lane = tid & 31;
    int wm = w >> 2, wn = w & 3;
#pragma unroll
    for (int mt = 0; mt < 2; ++mt)
#pragma unroll
        for (int nt = 0; nt < 4; ++nt)
#pragma unroll
            for (int i = 0; i < 4; ++i) c[mt][nt][i] = 0.f;
#pragma unroll
    for (int kc = 0; kc < 16; ++kc) {
        int sw = (kc & 7) << 2;
        uint32_t a[2][4];
#pragma unroll
        for (int mt = 0; mt < 2; ++mt) {
            int base = ((wm * 2 + mt) * 16 + kc) * 128 + (lane ^ sw);
            a[mt][0] = __float_as_uint(sA[base]);
            a[mt][1] = __float_as_uint(sA[base + 32]);
            a[mt][2] = __float_as_uint(sA[base + 64]);
            a[mt][3] = __float_as_uint(sA[base + 96]);
        }
#pragma unroll
        for (int nt = 0; nt < 4; ++nt) {
            float2 bv = __ldg((const float2*)&gB[(((wn * 4 + nt) * 16 + kc) * 32 + lane) * 2]);
            uint32_t b[2] = {__float_as_uint(bv.x), __float_as_uint(bv.y)};
            mma8(c[0][nt], a[0], b);
            mma8(c[1][nt], a[1], b);
        }
    }
}

#define ROWSTATS(sv, qv, mean, rstd) do { \
    _Pragma("unroll") for (int _mt = 0; _mt < 2; ++_mt) \
    _Pragma("unroll") for (int _h = 0; _h < 2; ++_h) { \
        float _s = (sv)[_mt][_h], _q = (qv)[_mt][_h]; \
        _s += __shfl_xor_sync(0xffffffffu, _s, 1); _q += __shfl_xor_sync(0xffffffffu, _q, 1); \
        _s += __shfl_xor_sync(0xffffffffu, _s, 2); _q += __shfl_xor_sync(0xffffffffu, _q, 2); \
        (sv)[_mt][_h] = _s; (qv)[_mt][_h] = _q; } \
    if ((lane & 3) == 0) { \
        _Pragma("unroll") for (int _mt = 0; _mt < 2; ++_mt) \
        _Pragma("unroll") for (int _h = 0; _h < 2; ++_h) { \
            int _row = wm * 32 + _mt * 16 + g + _h * 8; \
            sm[O_RS + _row * 4 + wn] = (sv)[_mt][_h]; \
            sm[O_RQ + _row * 4 + wn] = (qv)[_mt][_h]; } } \
    __syncthreads(); \
    _Pragma("unroll") for (int _mt = 0; _mt < 2; ++_mt) \
    _Pragma("unroll") for (int _h = 0; _h < 2; ++_h) { \
        int _row = wm * 32 + _mt * 16 + g + _h * 8; \
        float _ts = sm[O_RS + _row * 4] + sm[O_RS + _row * 4 + 1] + sm[O_RS + _row * 4 + 2] + sm[O_RS + _row * 4 + 3]; \
        float _tq = sm[O_RQ + _row * 4] + sm[O_RQ + _row * 4 + 1] + sm[O_RQ + _row * 4 + 2] + sm[O_RQ + _row * 4 + 3]; \
        float _mn = _ts * (1.f / 128.f); \
        (mean)[_mt][_h] = _mn; \
        (rstd)[_mt][_h] = rsqrtf(fmaxf(_tq * (1.f / 128.f) - _mn * _mn, 0.f) + 1e-5f); } \
    __syncthreads(); \
} while (0)

// ---------- weight prep (Wm, We) ----------
__global__ void k_prep(const float* __restrict__ Wm, const float* __restrict__ We) {
    extern __shared__ float ws[];   // [128][129]
    const float* W = blockIdx.x == 0 ? Wm : We;
    int tid = threadIdx.x;
    for (int t = 0; t < 16; ++t) {
        int id = tid + t * 256;
        int k = id >> 5, n4 = (id & 31) << 2;
        float4 v = *(const float4*)&W[k * Dd + n4];
        ws[k * 129 + n4] = v.x; ws[k * 129 + n4 + 1] = v.y;
        ws[k * 129 + n4 + 2] = v.z; ws[k * 129 + n4 + 3] = v.w;
    }
    __syncthreads();
    float* out = wfrag[blockIdx.x];
    for (int t = 0; t < 32; ++t) {
        int id = tid + t * 256;
        int lane = id & 31, kb = (id >> 5) & 15, nb = id >> 9;
        int n = nb * 8 + (lane >> 2), k = kb * 8 + (lane & 3);
        float2 o;
        o.x = tf32f(ws[k * 129 + n]);
        o.y = tf32f(ws[(k + 4) * 129 + n]);
        *(float2*)&out[id * 2] = o;
    }
}

// ---------- S, T, qk ----------
__global__ void k_small(const float* __restrict__ node, const float* __restrict__ Wmem,
                        const float* __restrict__ Wq, const float* __restrict__ bq,
                        const float* __restrict__ Wk) {
    int n = blockIdx.x, c = threadIdx.x;
    __shared__ float ns[Dd], qs[Dd];
    ns[c] = node[n * Dd + c];
    __syncthreads();
    float s = 0.f, t = 0.f, q = 0.f;
#pragma unroll 8
    for (int k = 0; k < Dd; ++k) {
        float nv = ns[k];
        s = fmaf(nv, Wmem[(Dd + k) * Dd + c], s);
        t = fmaf(nv, Wmem[(2 * Dd + k) * Dd + c], t);
        q = fmaf(nv, Wq[k * Dd + c], q);
    }
    sc_S[n * Dd + c] = s; sc_T[n * Dd + c] = t;
    qs[c] = q + bq[c];
    __syncthreads();
    float a[8] = {0,0,0,0,0,0,0,0};
#pragma unroll
    for (int hd = 0; hd < 128; ++hd)
        a[hd >> 4] = fmaf(Wk[c * Dd + hd], qs[hd], a[hd >> 4]);
#pragma unroll
    for (int h = 0; h < 8; ++h)
        sc_qk[n * 1024 + h * 128 + c] = a[h] * 0.25f;
}

// ---------- fused tile kernel: memory (f32 out) + edge_out ----------
__global__ __launch_bounds__(256, 3) void k_fused(
    const float* __restrict__ edge,
    const float* __restrict__ bm, const float* __restrict__ gm, const float* __restrict__ bem,
    const float* __restrict__ beb, const float* __restrict__ g1, const float* __restrict__ be1,
    const float* __restrict__ g2, const float* __restrict__ be2,
    float* __restrict__ oe)
{
    extern __shared__ float sm[];
    const int tid = threadIdx.x, w = tid >> 5, lane = tid & 31;
    const int wm = w >> 2, wn = w & 3, g = lane >> 2, t2 = (lane & 3) << 1;
    const int ib = blockIdx.x >> 3, jn0 = (blockIdx.x & 7) << 6;
    const size_t r0 = (size_t)blockIdx.x * 64;

    // A <- edge (tf32 frags, plane-split layout, vector stores)
#pragma unroll
    for (int t = 0; t < 8; ++t) {
        int id = tid + t * 256;
        int r = id >> 5, c4 = (id & 31) << 2;
        float4 v = *(const float4*)&edge[(r0 + r) * Dd + c4];
        float4 o;
        o.x = tf32f(v.x); o.y = tf32f(v.y); o.z = tf32f(v.z); o.w = tf32f(v.w);
        *(float4*)&sm[O_A + AFR2(r, c4)] = o;
    }
    if (tid < Dd) {
        sm[O_P + tid]  = bm[tid] + sc_T[ib * Dd + tid];
        sm[G_GM + tid] = gm[tid];  sm[G_BEM + tid] = bem[tid];
        sm[G_G1 + tid] = g1[tid];  sm[G_BE1 + tid] = be1[tid];
        sm[G_G2 + tid] = g2[tid];  sm[G_BE2 + tid] = be2[tid];
        sm[G_BEB + tid] = beb[tid];
    }
    __syncthreads();

    float c[2][4][4];
    mma_tile(sm + O_A, wfrag[0], c);        // memory GEMM
    __syncthreads();

    // epilogue1: memory = relu(LN(c + (bm+T) + S)), rewrite A-frags (tf32)
    {
        float sv[2][2] = {{0,0},{0,0}}, qv[2][2] = {{0,0},{0,0}};
#pragma unroll
        for (int mt = 0; mt < 2; ++mt) {
            int rA = wm * 32 + mt * 16 + g;
#pragma unroll
            for (int nt = 0; nt < 4; ++nt) {
                int col = wn * 32 + nt * 8 + t2;
                float p0 = sm[O_P + col], p1 = sm[O_P + col + 1];
                float2 s0 = *(const float2*)&sc_S[(jn0 + rA) * Dd + col];
                float2 s1 = *(const float2*)&sc_S[(jn0 + rA + 8) * Dd + col];
                c[mt][nt][0] += p0 + s0.x; c[mt][nt][1] += p1 + s0.y;
                c[mt][nt][2] += p0 + s1.x; c[mt][nt][3] += p1 + s1.y;
                sv[mt][0] += c[mt][nt][0] + c[mt][nt][1];
                qv[mt][0] += c[mt][nt][0]*c[mt][nt][0] + c[mt][nt][1]*c[mt][nt][1];
                sv[mt][1] += c[mt][nt][2] + c[mt][nt][3];
                qv[mt][1] += c[mt][nt][2]*c[mt][nt][2] + c[mt][nt][3]*c[mt][nt][3];
            }
        }
        float mean[2][2], rstd[2][2];
        ROWSTATS(sv, qv, mean, rstd);
#pragma unroll
        for (int mt = 0; mt < 2; ++mt) {
            int rA = wm * 32 + mt * 16 + g;
#pragma unroll
            for (int nt = 0; nt < 4; ++nt) {
                int col = wn * 32 + nt * 8 + t2;
                float ga0 = sm[G_GM + col], ga1 = sm[G_GM + col + 1];
                float bb0 = sm[G_BEM + col], bb1 = sm[G_BEM + col + 1];
                *(float2*)&sm[O_A + AFR2(rA, col)] = make_float2(
                    tf32f(fmaxf((c[mt][nt][0]-mean[mt][0])*rstd[mt][0]*ga0+bb0, 0.f)),
                    tf32f(fmaxf((c[mt][nt][1]-mean[mt][0])*rstd[mt][0]*ga1+bb1, 0.f)));
                *(float2*)&sm[O_A + AFR2(rA + 8, col)] = make_float2(
                    tf32f(fmaxf((c[mt][nt][2]-mean[mt][1])*rstd[mt][1]*ga0+bb0, 0.f)),
                    tf32f(fmaxf((c[mt][nt][3]-mean[mt][1])*rstd[mt][1]*ga1+bb1, 0.f)));
            }
        }
    }
    __syncthreads();

    mma_tile(sm + O_A, wfrag[1], c);        // edge GEMM

    // write memory f32 [jn][ib][c], coalesced float4 (A-frags read-only now)
#pragma unroll
    for (int t = 0; t < 8; ++t) {
        int id4 = tid + t * 256;
        int r = id4 >> 5, c4 = (id4 & 31) << 2;
        float4 o = *(const float4*)&sm[O_A + AFR2(r, c4)];
        *(float4*)&sc_memf[((size_t)(jn0 + r) * Nn + ib) * Dd + c4] = o;
    }

    // epilogue2: out_edge = LN2(edge + relu(LN1(c + beb)))
    {
        float sv[2][2] = {{0,0},{0,0}}, qv[2][2] = {{0,0},{0,0}};
#pragma unroll
        for (int mt = 0; mt < 2; ++mt)
#pragma unroll
            for (int nt = 0; nt < 4; ++nt) {
                int col = wn * 32 + nt * 8 + t2;
                float b0 = sm[G_BEB + col], b1 = sm[G_BEB + col + 1];
                c[mt][nt][0] += b0; c[mt][nt][1] += b1;
                c[mt][nt][2] += b0; c[mt][nt][3] += b1;
                sv[mt][0] += c[mt][nt][0] + c[mt][nt][1];
                qv[mt][0] += c[mt][nt][0]*c[mt][nt][0] + c[mt][nt][1]*c[mt][nt][1];
                sv[mt][1] += c[mt][nt][2] + c[mt][nt][3];
                qv[mt][1] += c[mt][nt][2]*c[mt][nt][2] + c[mt][nt][3]*c[mt][nt][3];
            }
        float mean[2][2], rstd[2][2];
        ROWSTATS(sv, qv, mean, rstd);
        float sv2[2][2] = {{0,0},{0,0}}, qv2[2][2] = {{0,0},{0,0}};
#pragma unroll
        for (int mt = 0; mt < 2; ++mt) {
            int rA = wm * 32 + mt * 16 + g;
#pragma unroll
            for (int nt = 0; nt < 4; ++nt) {
                int col = wn * 32 + nt * 8 + t2;
                float ga0 = sm[G_G1 + col], ga1 = sm[G_G1 + col + 1];
                float bb0 = sm[G_BE1 + col], bb1 = sm[G_BE1 + col + 1];
                float2 e0 = *(const float2*)&edge[(r0 + rA) * Dd + col];
                float2 e1 = *(const float2*)&edge[(r0 + rA + 8) * Dd + col];
                float w00 = fmaxf((c[mt][nt][0]-mean[mt][0])*rstd[mt][0]*ga0+bb0, 0.f) + e0.x;
                float w01 = fmaxf((c[mt][nt][1]-mean[mt][0])*rstd[mt][0]*ga1+bb1, 0.f) + e0.y;
                float w10 = fmaxf((c[mt][nt][2]-mean[mt][1])*rstd[mt][1]*ga0+bb0, 0.f) + e1.x;
                float w11 = fmaxf((c[mt][nt][3]-mean[mt][1])*rstd[mt][1]*ga1+bb1, 0.f) + e1.y;
                c[mt][nt][0] = w00; c[mt][nt][1] = w01; c[mt][nt][2] = w10; c[mt][nt][3] = w11;
                sv2[mt][0] += w00 + w01; qv2[mt][0] += w00*w00 + w01*w01;
                sv2[mt][1] += w10 + w11; qv2[mt][1] += w10*w10 + w11*w11;
            }
        }
        ROWSTATS(sv2, qv2, mean, rstd);
#pragma unroll
        for (int mt = 0; mt < 2; ++mt) {
            int rA = wm * 32 + mt * 16 + g;
#pragma unroll
            for (int nt = 0; nt < 4; ++nt) {
                int col = wn * 32 + nt * 8 + t2;
                float ga0 = sm[G_G2 + col], ga1 = sm[G_G2 + col + 1];
                float bb0 = sm[G_BE2 + col], bb1 = sm[G_BE2 + col + 1];
                *(float2*)&oe[(r0 + rA) * Dd + col] =
                    make_float2((c[mt][nt][0]-mean[mt][0])*rstd[mt][0]*ga0+bb0,
                                (c[mt][nt][1]-mean[mt][0])*rstd[mt][0]*ga1+bb1);
                *(float2*)&oe[(r0 + rA + 8) * Dd + col] =
                    make_float2((c[mt][nt][2]-mean[mt][1])*rstd[mt][1]*ga0+bb0,
                                (c[mt][nt][3]-mean[mt][1])*rstd[mt][1]*ga1+bb1);
            }
        }
    }
}

// ---------- split-KV attention: partial kernel (one 64-key chunk per block) ----------
// buf: stride 128, float4-slot XOR swizzle (j ^ (m&7)) — conflict-free in all phases
__global__ __launch_bounds__(256, 4) void k_attnp(const unsigned char* __restrict__ mask) {
    __shared__ float qk_s[1024];
    __shared__ float buf[64 * 128];
    __shared__ float scs[512], ps[512];
    const int bid = blockIdx.x, n = bid >> 3, part = bid & 7;
    const int tid = threadIdx.x, w = tid >> 5, lane = tid & 31;
    const uint32_t sbuf = smem_u32(buf);

    for (int i = tid; i < 1024; i += 256) qk_s[i] = sc_qk[n * 1024 + i];

    const float* src = sc_memf + ((size_t)n * Nn + part * 64) * Dd;
#pragma unroll
    for (int t = 0; t < 8; ++t) {
        int id4 = tid + t * 256;
        int m = id4 >> 5, j = id4 & 31;
        cpa16(sbuf + ((m * 128 + ((j ^ (m & 7)) << 2)) << 2), src + (size_t)id4 * 4);
    }
    CPC(); CPW(0);
    __syncthreads();

    // scores: thread -> (m = sm_, heads h0, h0+1)
    {
        const int sm_ = tid & 63, h0 = (tid >> 6) << 1;
        float a0 = 0.f, a1 = 0.f;
        const float* mr = &buf[sm_ * 128];
        const int msw = sm_ & 7;
        const float* qa = &qk_s[h0 * 128];
        const float* qb = &qk_s[(h0 + 1) * 128];
#pragma unroll 8
        for (int j = 0; j < 32; ++j) {
            float4 m4 = *(const float4*)&mr[(j ^ msw) << 2];
            float4 a4 = *(const float4*)&qa[(j ^ msw) << 2];
            float4 b4 = *(const float4*)&qb[(j ^ msw) << 2];
            a0 += m4.x*a4.x + m4.y*a4.y + m4.z*a4.z + m4.w*a4.w;
            a1 += m4.x*b4.x + m4.y*b4.y + m4.z*b4.z + m4.w*b4.w;
        }
        bool mk = mask[n * Nn + part * 64 + sm_] != 0;
        scs[h0 * 64 + sm_]       = mk ? -1e30f : a0;
        scs[(h0 + 1) * 64 + sm_] = mk ? -1e30f : a1;
    }
    __syncthreads();

    float* op = &sc_part[(size_t)bid * 1040];
    // local softmax: warp w = head w (single chunk, no online rescale)
    {
        float s0v = scs[w * 64 + lane], s1v = scs[w * 64 + lane + 32];
        float mx = fmaxf(s0v, s1v);
#pragma unroll
        for (int off = 16; off >= 1; off >>= 1)
            mx = fmaxf(mx, __shfl_xor_sync(0xffffffffu, mx, off));
        float p0 = __expf(s0v - mx), p1 = __expf(s1v - mx);
        ps[w * 64 + lane] = p0; ps[w * 64 + lane + 32] = p1;
        float cs = p0 + p1;
#pragma unroll
        for (int off = 16; off >= 1; off >>= 1)
            cs += __shfl_xor_sync(0xffffffffu, cs, off);
        if (lane == 0) { op[1024 + w] = mx; op[1032 + w] = cs; }
    }
    __syncthreads();

    // unnormalized ctx: thread (h = w, cols lane*4..+3)
    {
        float c0 = 0.f, c1 = 0.f, c2 = 0.f, c3 = 0.f;
        const float* pp = &ps[w * 64];
#pragma unroll 8
        for (int m = 0; m < 64; ++m) {
            float p = pp[m];
            float4 v = *(const float4*)&buf[m * 128 + ((lane ^ (m & 7)) << 2)];
            float vv[4] = {v.x, v.y, v.z, v.w};
            // v is column quad (lane^(m&7))^... slot holds columns 4*(lane) — wait:
            // slot s holds columns of j where (j ^ (m&7)) == s, i.e., j = s ^ (m&7).
            // We read slot (lane ^ (m&7)) -> j = lane -> columns lane*4..+3. Correct.
            c0 = fmaf(p, vv[0], c0); c1 = fmaf(p, vv[1], c1);
            c2 = fmaf(p, vv[2], c2); c3 = fmaf(p, vv[3], c3);
        }
        *(float4*)&op[w * 128 + lane * 4] = make_float4(c0, c1, c2, c3);
    }
}

// ---------- split-KV attention: combine + Wv projection ----------
__global__ __launch_bounds__(256, 4) void k_attnc(const float* __restrict__ Wv,
                                                  const float* __restrict__ bv) {
    __shared__ float ctx_s[1024];
    __shared__ float f_s[64];
    __shared__ float ginv_s[8];
    const int n = blockIdx.x, tid = threadIdx.x;
    const float* base = &sc_part[(size_t)(n * 8) * 1040];

    if (tid < 8) {
        int h = tid;
        float gmax = -1e30f;
#pragma unroll
        for (int p = 0; p < 8; ++p) gmax = fmaxf(gmax, base[(size_t)p * 1040 + 1024 + h]);
        float gsum = 0.f;
#pragma unroll
        for (int p = 0; p < 8; ++p) {
            float f = __expf(base[(size_t)p * 1040 + 1024 + h] - gmax);
            f_s[p * 8 + h] = f;
            gsum = fmaf(f, base[(size_t)p * 1040 + 1032 + h], gsum);
        }
        ginv_s[h] = 1.f / gsum;
    }
    __syncthreads();

    {
        int e0 = tid * 4, h = e0 >> 7;
        float a0 = 0.f, a1 = 0.f, a2 = 0.f, a3 = 0.f;
#pragma unroll
        for (int p = 0; p < 8; ++p) {
            float f = f_s[p * 8 + h];
            float4 v = *(const float4*)&base[(size_t)p * 1040 + e0];
            a0 = fmaf(f, v.x, a0); a1 = fmaf(f, v.y, a1);
            a2 = fmaf(f, v.z, a2); a3 = fmaf(f, v.w, a3);
        }
        float inv = ginv_s[h];
        ctx_s[e0] = a0 * inv; ctx_s[e0 + 1] = a1 * inv;
        ctx_s[e0 + 2] = a2 * inv; ctx_s[e0 + 3] = a3 * inv;
    }
    __syncthreads();

    if (tid < 128) {
        int h = tid >> 4;
        float acc = bv[tid];
#pragma unroll 8
        for (int cc = 0; cc < 128; ++cc)
            acc = fmaf(ctx_s[h * 128 + cc], Wv[cc * Dd + tid], acc);
        sc_o[n * Dd + tid] = acc;
    }
}

// ---------- final: out-proj + LN + FFN + LN ----------
__device__ __forceinline__ float bsum128(float v, float* tmp) {
    int lane = threadIdx.x & 31, wid = threadIdx.x >> 5;
#pragma unroll
    for (int off = 16; off >= 1; off >>= 1) v += __shfl_xor_sync(0xffffffffu, v, off);
    if (lane == 0) tmp[wid] = v;
    __syncthreads();
    float s = tmp[0] + tmp[1] + tmp[2] + tmp[3];
    __syncthreads();
    return s;
}
__global__ void k_final(const float* __restrict__ node,
                        const float* __restrict__ Wo, const float* __restrict__ bo,
                        const float* __restrict__ g2, const float* __restrict__ be2,
                        const float* __restrict__ W1, const float* __restrict__ b1,
                        const float* __restrict__ W2, const float* __restrict__ b2,
                        const float* __restrict__ g3, const float* __restrict__ be3,
                        float* __restrict__ out_x) {
    const int n = blockIdx.x;
    const int c = threadIdx.x;
    __shared__ float os[Dd], xs[Dd], hs[Df], tmp[4];
    os[c] = sc_o[n * Dd + c];
    __syncthreads();
    float t = bo[c];
#pragma unroll 8
    for (int k = 0; k < Dd; ++k) t = fmaf(os[k], Wo[k * Dd + c], t);
    float x = node[n * Dd + c] + t;
    float mean = bsum128(x, tmp) * (1.f / 128.f);
    float d = x - mean;
    float var = bsum128(d * d, tmp) * (1.f / 128.f);
    float xn = d * rsqrtf(var + 1e-5f) * g2[c] + be2[c];
    xs[c] = xn;
    __syncthreads();
    float h0 = b1[c], h1 = b1[c + 128];
#pragma unroll 8
    for (int k = 0; k < Dd; ++k) {
        float xv = xs[k];
        h0 = fmaf(xv, W1[k * Df + c], h0);
        h1 = fmaf(xv, W1[k * Df + c + 128], h1);
    }
    hs[c] = fmaxf(h0, 0.f);
    hs[c + 128] = fmaxf(h1, 0.f);
    __syncthreads();
    float y = b2[c];
#pragma unroll 8
    for (int f = 0; f < Df; ++f) y = fmaf(hs[f], W2[f * Dd + c], y);
    float z = xn + y;
    mean = bsum128(z, tmp) * (1.f / 128.f);
    d = z - mean;
    var = bsum128(d * d, tmp) * (1.f / 128.f);
    out_x[n * Dd + c] = d * rsqrtf(var + 1e-5f) * g3[c] + be3[c];
}

// ---------- host ----------
extern "C" void kernel_launch(void* const* d_in, const int* in_sizes, int n_in,
                              void* d_out, int out_size) {
    const float* node = (const float*)d_in[0];
    const float* edge = (const float*)d_in[1];
    const unsigned char* mask = (const unsigned char*)d_in[2];
    const float* W_mem = (const float*)d_in[3];
    const float* b_mem = (const float*)d_in[4];
    const float* g_mem = (const float*)d_in[5];
    const float* be_mem = (const float*)d_in[6];
    const float* W_e = (const float*)d_in[7];
    const float* b_e = (const float*)d_in[8];
    const float* g_e1 = (const float*)d_in[9];
    const float* be_e1 = (const float*)d_in[10];
    const float* g_e2 = (const float*)d_in[11];
    const float* be_e2 = (const float*)d_in[12];
    const float* Wq = (const float*)d_in[13];
    const float* bq = (const float*)d_in[14];
    const float* Wk = (const float*)d_in[15];
    const float* bk = (const float*)d_in[16]; (void)bk;   // cancels in softmax
    const float* Wv = (const float*)d_in[17];
    const float* bv = (const float*)d_in[18];
    const float* Wo = (const float*)d_in[19];
    const float* bo = (const float*)d_in[20];
    const float* W1 = (const float*)d_in[21];
    const float* b1 = (const float*)d_in[22];
    const float* W2 = (const float*)d_in[23];
    const float* b2 = (const float*)d_in[24];
    const float* g2 = (const float*)d_in[25];
    const float* be2 = (const float*)d_in[26];
    const float* g3 = (const float*)d_in[27];
    const float* be3 = (const float*)d_in[28];

    float* out = (float*)d_out;
    float* out_x = out;
    float* out_edge = out + Nn * Dd;

    static int init = 0;
    if (!init) {
        cudaFuncSetAttribute(k_prep, cudaFuncAttributeMaxDynamicSharedMemorySize, 128 * 129 * 4);
        cudaFuncSetAttribute(k_fused, cudaFuncAttributeMaxDynamicSharedMemorySize, DYN);
        init = 1;
    }

    k_prep<<<2, 256, 128 * 129 * 4>>>(W_mem, W_e);
    k_small<<<Nn, Dd>>>(node, W_mem, Wq, bq, Wk);
    k_fused<<<NT, 256, DYN>>>(edge, b_mem, g_mem, be_mem,
                              b_e, g_e1, be_e1, g_e2, be_e2, out_edge);
    k_attnp<<<4096, 256>>>(mask);
    k_attnc<<<Nn, 256>>>(Wv, bv);
    k_final<<<Nn, 128>>>(node, Wo, bo, g2, be2, W1, b1, W2, b2, g3, be3, out_x);
}

// round 14
// speedup vs baseline: 2.8824x; 1.0195x over previous
#include <cuda_runtime.h>
#include <math.h>
#include <stdint.h>

#define Nn 512
#define Dd 128
#define Df 256
#define Hh 8
#define ROWS (Nn*Nn)
#define NT 4096                   // 64-row tiles

__device__ float sc_S[Nn * Dd];
__device__ float sc_T[Nn * Dd];
__device__ float sc_qk[Nn * Hh * Dd];        // 0.25 * Wk^T q  per (n, h)
__device__ float sc_o[Nn * Dd];
__device__ float wfrag[2][16384];            // Wm_edge, We tf32 frag layout
__device__ float sc_memf[(size_t)ROWS * Dd]; // memory f32 [n][m][c] (134MB)
__device__ float sc_part[(size_t)4096 * 1040]; // split-KV partials (17MB)

// k_fused dynamic smem float offsets
#define O_A  0                    // 8192
#define O_RS 8192                 // 256
#define O_RQ 8448                 // 256
#define O_P  8704                 // 128 (bm + T)
#define O_G  8832                 // 7*128
#define SMF  9728
#define DYN  (SMF * 4)            // 38912 B -> 3 CTA/SM

#define G_GM  (O_G + 0)
#define G_BEM (O_G + 128)
#define G_G1  (O_G + 256)
#define G_BE1 (O_G + 384)
#define G_G2  (O_G + 512)
#define G_BE2 (O_G + 640)
#define G_BEB (O_G + 768)

__device__ __forceinline__ uint32_t tf32c(float x) {
    uint32_t y; asm("cvt.rna.tf32.f32 %0, %1;" : "=r"(y) : "f"(x)); return y;
}
__device__ __forceinline__ float tf32f(float x) { return __uint_as_float(tf32c(x)); }

__device__ __forceinline__ uint32_t smem_u32(const void* p) {
    uint32_t a;
    asm("{ .reg .u64 t; cvta.to.shared.u64 t, %1; cvt.u32.u64 %0, t; }" : "=r"(a) : "l"(p));
    return a;
}
__device__ __forceinline__ void cpa16(uint32_t s, const void* g) {
    asm volatile("cp.async.cg.shared.global [%0], [%1], 16;" :: "r"(s), "l"(g));
}
#define CPC() asm volatile("cp.async.commit_group;" ::: "memory")
#define CPW(n) asm volatile("cp.async.wait_group %0;" :: "n"(n) : "memory")

__device__ __forceinline__ void mma8(float* c, const uint32_t* a, const uint32_t* b) {
    asm volatile(
        "mma.sync.aligned.m16n8k8.row.col.f32.tf32.tf32.f32 "
        "{%0,%1,%2,%3},{%4,%5,%6,%7},{%8,%9},{%0,%1,%2,%3};"
        : "+f"(c[0]), "+f"(c[1]), "+f"(c[2]), "+f"(c[3])
        : "r"(a[0]), "r"(a[1]), "r"(a[2]), "r"(a[3]), "r"(b[0]), "r"(b[1]));
}

// A-fragment float index, plane-split layout [frag][reg(4)][qx(32)]
__device__ __forceinline__ int AFR2(int r, int c) {
    int kb = c >> 3;
    int frag = (r >> 4) * 16 + kb;
    int reg = ((r >> 3) & 1) + (((c >> 2) & 1) << 1);
    int qx = ((((r & 7) << 2) + (c & 3)) ^ ((kb & 7) << 2));
    return frag * 128 + reg * 32 + qx;
}

// 64x128x128 tile MMA: 8 warps 2(m) x 4(n), warp tile 32x32.
__device__ __forceinline__ void mma_tile(const float* sA, const float* __restrict__ gB,
                                         float c[2][4][4]) {
    int tid = threadIdx.x, w = tid >> 5, lane = tid & 31;
    int wm = w >> 2, wn = w & 3;
#pragma unroll
    for (int mt = 0; mt < 2; ++mt)
#pragma unroll
        for (int nt = 0; nt < 4; ++nt)
#pragma unroll
            for (int i = 0; i < 4; ++i) c[mt][nt][i] = 0.f;
#pragma unroll
    for (int kc = 0; kc < 16; ++kc) {
        int sw = (kc & 7) << 2;
        uint32_t a[2][4];
#pragma unroll
        for (int mt = 0; mt < 2; ++mt) {
            int base = ((wm * 2 + mt) * 16 + kc) * 128 + (lane ^ sw);
            a[mt][0] = __float_as_uint(sA[base]);
            a[mt][1] = __float_as_uint(sA[base + 32]);
            a[mt][2] = __float_as_uint(sA[base + 64]);
            a[mt][3] = __float_as_uint(sA[base + 96]);
        }
#pragma unroll
        for (int nt = 0; nt < 4; ++nt) {
            float2 bv = __ldg((const float2*)&gB[(((wn * 4 + nt) * 16 + kc) * 32 + lane) * 2]);
            uint32_t b[2] = {__float_as_uint(bv.x), __float_as_uint(bv.y)};
            mma8(c[0][nt], a[0], b);
            mma8(c[1][nt], a[1], b);
        }
    }
}

#define ROWSTATS(sv, qv, mean, rstd) do { \
    _Pragma("unroll") for (int _mt = 0; _mt < 2; ++_mt) \
    _Pragma("unroll") for (int _h = 0; _h < 2; ++_h) { \
        float _s = (sv)[_mt][_h], _q = (qv)[_mt][_h]; \
        _s += __shfl_xor_sync(0xffffffffu, _s, 1); _q += __shfl_xor_sync(0xffffffffu, _q, 1); \
        _s += __shfl_xor_sync(0xffffffffu, _s, 2); _q += __shfl_xor_sync(0xffffffffu, _q, 2); \
        (sv)[_mt][_h] = _s; (qv)[_mt][_h] = _q; } \
    if ((lane & 3) == 0) { \
        _Pragma("unroll") for (int _mt = 0; _mt < 2; ++_mt) \
        _Pragma("unroll") for (int _h = 0; _h < 2; ++_h) { \
            int _row = wm * 32 + _mt * 16 + g + _h * 8; \
            sm[O_RS + _row * 4 + wn] = (sv)[_mt][_h]; \
            sm[O_RQ + _row * 4 + wn] = (qv)[_mt][_h]; } } \
    __syncthreads(); \
    _Pragma("unroll") for (int _mt = 0; _mt < 2; ++_mt) \
    _Pragma("unroll") for (int _h = 0; _h < 2; ++_h) { \
        int _row = wm * 32 + _mt * 16 + g + _h * 8; \
        float _ts = sm[O_RS + _row * 4] + sm[O_RS + _row * 4 + 1] + sm[O_RS + _row * 4 + 2] + sm[O_RS + _row * 4 + 3]; \
        float _tq = sm[O_RQ + _row * 4] + sm[O_RQ + _row * 4 + 1] + sm[O_RQ + _row * 4 + 2] + sm[O_RQ + _row * 4 + 3]; \
        float _mn = _ts * (1.f / 128.f); \
        (mean)[_mt][_h] = _mn; \
        (rstd)[_mt][_h] = rsqrtf(fmaxf(_tq * (1.f / 128.f) - _mn * _mn, 0.f) + 1e-5f); } \
    __syncthreads(); \
} while (0)

// ---------- weight prep (Wm, We) ----------
__global__ void k_prep(const float* __restrict__ Wm, const float* __restrict__ We) {
    extern __shared__ float ws[];   // [128][129]
    const float* W = blockIdx.x == 0 ? Wm : We;
    int tid = threadIdx.x;
    for (int t = 0; t < 16; ++t) {
        int id = tid + t * 256;
        int k = id >> 5, n4 = (id & 31) << 2;
        float4 v = *(const float4*)&W[k * Dd + n4];
        ws[k * 129 + n4] = v.x; ws[k * 129 + n4 + 1] = v.y;
        ws[k * 129 + n4 + 2] = v.z; ws[k * 129 + n4 + 3] = v.w;
    }
    __syncthreads();
    float* out = wfrag[blockIdx.x];
    for (int t = 0; t < 32; ++t) {
        int id = tid + t * 256;
        int lane = id & 31, kb = (id >> 5) & 15, nb = id >> 9;
        int n = nb * 8 + (lane >> 2), k = kb * 8 + (lane & 3);
        float2 o;
        o.x = tf32f(ws[k * 129 + n]);
        o.y = tf32f(ws[(k + 4) * 129 + n]);
        *(float2*)&out[id * 2] = o;
    }
}

// ---------- S, T, qk ----------
__global__ void k_small(const float* __restrict__ node, const float* __restrict__ Wmem,
                        const float* __restrict__ Wq, const float* __restrict__ bq,
                        const float* __restrict__ Wk) {
    int n = blockIdx.x, c = threadIdx.x;
    __shared__ float ns[Dd], qs[Dd];
    ns[c] = node[n * Dd + c];
    __syncthreads();
    float s = 0.f, t = 0.f, q = 0.f;
#pragma unroll 8
    for (int k = 0; k < Dd; ++k) {
        float nv = ns[k];
        s = fmaf(nv, Wmem[(Dd + k) * Dd + c], s);
        t = fmaf(nv, Wmem[(2 * Dd + k) * Dd + c], t);
        q = fmaf(nv, Wq[k * Dd + c], q);
    }
    sc_S[n * Dd + c] = s; sc_T[n * Dd + c] = t;
    qs[c] = q + bq[c];
    __syncthreads();
    float a[8] = {0,0,0,0,0,0,0,0};
#pragma unroll
    for (int hd = 0; hd < 128; ++hd)
        a[hd >> 4] = fmaf(Wk[c * Dd + hd], qs[hd], a[hd >> 4]);
#pragma unroll
    for (int h = 0; h < 8; ++h)
        sc_qk[n * 1024 + h * 128 + c] = a[h] * 0.25f;
}

// ---------- fused tile kernel: memory (f32 out) + edge_out ----------
__global__ __launch_bounds__(256, 3) void k_fused(
    const float* __restrict__ edge,
    const float* __restrict__ bm, const float* __restrict__ gm, const float* __restrict__ bem,
    const float* __restrict__ beb, const float* __restrict__ g1, const float* __restrict__ be1,
    const float* __restrict__ g2, const float* __restrict__ be2,
    float* __restrict__ oe)
{
    extern __shared__ float sm[];
    const int tid = threadIdx.x, w = tid >> 5, lane = tid & 31;
    const int wm = w >> 2, wn = w & 3, g = lane >> 2, t2 = (lane & 3) << 1;
    const int ib = blockIdx.x >> 3, jn0 = (blockIdx.x & 7) << 6;
    const size_t r0 = (size_t)blockIdx.x * 64;

    // A <- edge (tf32 frags, plane-split layout, vector stores)
#pragma unroll
    for (int t = 0; t < 8; ++t) {
        int id = tid + t * 256;
        int r = id >> 5, c4 = (id & 31) << 2;
        float4 v = *(const float4*)&edge[(r0 + r) * Dd + c4];
        float4 o;
        o.x = tf32f(v.x); o.y = tf32f(v.y); o.z = tf32f(v.z); o.w = tf32f(v.w);
        *(float4*)&sm[O_A + AFR2(r, c4)] = o;
    }
    if (tid < Dd) {
        sm[O_P + tid]  = bm[tid] + sc_T[ib * Dd + tid];
        sm[G_GM + tid] = gm[tid];  sm[G_BEM + tid] = bem[tid];
        sm[G_G1 + tid] = g1[tid];  sm[G_BE1 + tid] = be1[tid];
        sm[G_G2 + tid] = g2[tid];  sm[G_BE2 + tid] = be2[tid];
        sm[G_BEB + tid] = beb[tid];
    }
    __syncthreads();

    float c[2][4][4];
    mma_tile(sm + O_A, wfrag[0], c);        // memory GEMM
    __syncthreads();

    // epilogue1: memory = relu(LN(c + (bm+T) + S)), rewrite A-frags (tf32)
    {
        float sv[2][2] = {{0,0},{0,0}}, qv[2][2] = {{0,0},{0,0}};
#pragma unroll
        for (int mt = 0; mt < 2; ++mt) {
            int rA = wm * 32 + mt * 16 + g;
#pragma unroll
            for (int nt = 0; nt < 4; ++nt) {
                int col = wn * 32 + nt * 8 + t2;
                float p0 = sm[O_P + col], p1 = sm[O_P + col + 1];
                float2 s0 = *(const float2*)&sc_S[(jn0 + rA) * Dd + col];
                float2 s1 = *(const float2*)&sc_S[(jn0 + rA + 8) * Dd + col];
                c[mt][nt][0] += p0 + s0.x; c[mt][nt][1] += p1 + s0.y;
                c[mt][nt][2] += p0 + s1.x; c[mt][nt][3] += p1 + s1.y;
                sv[mt][0] += c[mt][nt][0] + c[mt][nt][1];
                qv[mt][0] += c[mt][nt][0]*c[mt][nt][0] + c[mt][nt][1]*c[mt][nt][1];
                sv[mt][1] += c[mt][nt][2] + c[mt][nt][3];
                qv[mt][1] += c[mt][nt][2]*c[mt][nt][2] + c[mt][nt][3]*c[mt][nt][3];
            }
        }
        float mean[2][2], rstd[2][2];
        ROWSTATS(sv, qv, mean, rstd);
#pragma unroll
        for (int mt = 0; mt < 2; ++mt) {
            int rA = wm * 32 + mt * 16 + g;
#pragma unroll
            for (int nt = 0; nt < 4; ++nt) {
                int col = wn * 32 + nt * 8 + t2;
                float ga0 = sm[G_GM + col], ga1 = sm[G_GM + col + 1];
                float bb0 = sm[G_BEM + col], bb1 = sm[G_BEM + col + 1];
                *(float2*)&sm[O_A + AFR2(rA, col)] = make_float2(
                    tf32f(fmaxf((c[mt][nt][0]-mean[mt][0])*rstd[mt][0]*ga0+bb0, 0.f)),
                    tf32f(fmaxf((c[mt][nt][1]-mean[mt][0])*rstd[mt][0]*ga1+bb1, 0.f)));
                *(float2*)&sm[O_A + AFR2(rA + 8, col)] = make_float2(
                    tf32f(fmaxf((c[mt][nt][2]-mean[mt][1])*rstd[mt][1]*ga0+bb0, 0.f)),
                    tf32f(fmaxf((c[mt][nt][3]-mean[mt][1])*rstd[mt][1]*ga1+bb1, 0.f)));
            }
        }
    }
    __syncthreads();

    mma_tile(sm + O_A, wfrag[1], c);        // edge GEMM

    // write memory f32 [jn][ib][c], coalesced float4
#pragma unroll
    for (int t = 0; t < 8; ++t) {
        int id4 = tid + t * 256;
        int r = id4 >> 5, c4 = (id4 & 31) << 2;
        float4 o = *(const float4*)&sm[O_A + AFR2(r, c4)];
        *(float4*)&sc_memf[((size_t)(jn0 + r) * Nn + ib) * Dd + c4] = o;
    }

    // epilogue2: out_edge = LN2(edge + relu(LN1(c + beb)))
    {
        float sv[2][2] = {{0,0},{0,0}}, qv[2][2] = {{0,0},{0,0}};
#pragma unroll
        for (int mt = 0; mt < 2; ++mt)
#pragma unroll
            for (int nt = 0; nt < 4; ++nt) {
                int col = wn * 32 + nt * 8 + t2;
                float b0 = sm[G_BEB + col], b1 = sm[G_BEB + col + 1];
                c[mt][nt][0] += b0; c[mt][nt][1] += b1;
                c[mt][nt][2] += b0; c[mt][nt][3] += b1;
                sv[mt][0] += c[mt][nt][0] + c[mt][nt][1];
                qv[mt][0] += c[mt][nt][0]*c[mt][nt][0] + c[mt][nt][1]*c[mt][nt][1];
                sv[mt][1] += c[mt][nt][2] + c[mt][nt][3];
                qv[mt][1] += c[mt][nt][2]*c[mt][nt][2] + c[mt][nt][3]*c[mt][nt][3];
            }
        float mean[2][2], rstd[2][2];
        ROWSTATS(sv, qv, mean, rstd);
        float sv2[2][2] = {{0,0},{0,0}}, qv2[2][2] = {{0,0},{0,0}};
#pragma unroll
        for (int mt = 0; mt < 2; ++mt) {
            int rA = wm * 32 + mt * 16 + g;
#pragma unroll
            for (int nt = 0; nt < 4; ++nt) {
                int col = wn * 32 + nt * 8 + t2;
                float ga0 = sm[G_G1 + col], ga1 = sm[G_G1 + col + 1];
                float bb0 = sm[G_BE1 + col], bb1 = sm[G_BE1 + col + 1];
                float2 e0 = *(const float2*)&edge[(r0 + rA) * Dd + col];
                float2 e1 = *(const float2*)&edge[(r0 + rA + 8) * Dd + col];
                float w00 = fmaxf((c[mt][nt][0]-mean[mt][0])*rstd[mt][0]*ga0+bb0, 0.f) + e0.x;
                float w01 = fmaxf((c[mt][nt][1]-mean[mt][0])*rstd[mt][0]*ga1+bb1, 0.f) + e0.y;
                float w10 = fmaxf((c[mt][nt][2]-mean[mt][1])*rstd[mt][1]*ga0+bb0, 0.f) + e1.x;
                float w11 = fmaxf((c[mt][nt][3]-mean[mt][1])*rstd[mt][1]*ga1+bb1, 0.f) + e1.y;
                c[mt][nt][0] = w00; c[mt][nt][1] = w01; c[mt][nt][2] = w10; c[mt][nt][3] = w11;
                sv2[mt][0] += w00 + w01; qv2[mt][0] += w00*w00 + w01*w01;
                sv2[mt][1] += w10 + w11; qv2[mt][1] += w10*w10 + w11*w11;
            }
        }
        ROWSTATS(sv2, qv2, mean, rstd);
#pragma unroll
        for (int mt = 0; mt < 2; ++mt) {
            int rA = wm * 32 + mt * 16 + g;
#pragma unroll
            for (int nt = 0; nt < 4; ++nt) {
                int col = wn * 32 + nt * 8 + t2;
                float ga0 = sm[G_G2 + col], ga1 = sm[G_G2 + col + 1];
                float bb0 = sm[G_BE2 + col], bb1 = sm[G_BE2 + col + 1];
                *(float2*)&oe[(r0 + rA) * Dd + col] =
                    make_float2((c[mt][nt][0]-mean[mt][0])*rstd[mt][0]*ga0+bb0,
                                (c[mt][nt][1]-mean[mt][0])*rstd[mt][0]*ga1+bb1);
                *(float2*)&oe[(r0 + rA + 8) * Dd + col] =
                    make_float2((c[mt][nt][2]-mean[mt][1])*rstd[mt][1]*ga0+bb0,
                                (c[mt][nt][3]-mean[mt][1])*rstd[mt][1]*ga1+bb1);
            }
        }
    }
}

// ---------- split-KV attention: partial kernel (R12 version, stride-132 buffer) ----------
__global__ __launch_bounds__(256, 4) void k_attnp(const unsigned char* __restrict__ mask) {
    __shared__ float qk_s[1024];
    __shared__ float buf[64 * 132];
    __shared__ float scs[512], ps[512];
    const int bid = blockIdx.x, n = bid >> 3, part = bid & 7;
    const int tid = threadIdx.x, w = tid >> 5, lane = tid & 31;
    const uint32_t sbuf = smem_u32(buf);

    for (int i = tid; i < 1024; i += 256) qk_s[i] = sc_qk[n * 1024 + i];

    const float* src = sc_memf + ((size_t)n * Nn + part * 64) * Dd;
#pragma unroll
    for (int t = 0; t < 8; ++t) {
        int id4 = tid + t * 256;
        int m = id4 >> 5, j = id4 & 31;
        cpa16(sbuf + ((m * 132 + j * 4) << 2), src + (size_t)id4 * 4);
    }
    CPC(); CPW(0);
    __syncthreads();

    // scores: thread -> (m = sm_, heads h0, h0+1)
    {
        const int sm_ = tid & 63, h0 = (tid >> 6) << 1;
        float a0 = 0.f, a1 = 0.f;
        const float* mr = &buf[sm_ * 132];
        const float* qa = &qk_s[h0 * 128];
        const float* qb = &qk_s[(h0 + 1) * 128];
#pragma unroll 8
        for (int j = 0; j < 32; ++j) {
            float4 m4 = *(const float4*)&mr[j * 4];
            float4 a4 = *(const float4*)&qa[j * 4];
            float4 b4 = *(const float4*)&qb[j * 4];
            a0 += m4.x*a4.x + m4.y*a4.y + m4.z*a4.z + m4.w*a4.w;
            a1 += m4.x*b4.x + m4.y*b4.y + m4.z*b4.z + m4.w*b4.w;
        }
        bool mk = mask[n * Nn + part * 64 + sm_] != 0;
        scs[h0 * 64 + sm_]       = mk ? -1e30f : a0;
        scs[(h0 + 1) * 64 + sm_] = mk ? -1e30f : a1;
    }
    __syncthreads();

    float* op = &sc_part[(size_t)bid * 1040];
    // local softmax: warp w = head w (single chunk, no online rescale)
    {
        float s0v = scs[w * 64 + lane], s1v = scs[w * 64 + lane + 32];
        float mx = fmaxf(s0v, s1v);
#pragma unroll
        for (int off = 16; off >= 1; off >>= 1)
            mx = fmaxf(mx, __shfl_xor_sync(0xffffffffu, mx, off));
        float p0 = __expf(s0v - mx), p1 = __expf(s1v - mx);
        ps[w * 64 + lane] = p0; ps[w * 64 + lane + 32] = p1;
        float cs = p0 + p1;
#pragma unroll
        for (int off = 16; off >= 1; off >>= 1)
            cs += __shfl_xor_sync(0xffffffffu, cs, off);
        if (lane == 0) { op[1024 + w] = mx; op[1032 + w] = cs; }
    }
    __syncthreads();

    // unnormalized ctx: thread (h = w, cols lane*4..+3)
    {
        float c0 = 0.f, c1 = 0.f, c2 = 0.f, c3 = 0.f;
        const float* pp = &ps[w * 64];
#pragma unroll 8
        for (int m = 0; m < 64; ++m) {
            float p = pp[m];
            float4 v = *(const float4*)&buf[m * 132 + lane * 4];
            c0 = fmaf(p, v.x, c0); c1 = fmaf(p, v.y, c1);
            c2 = fmaf(p, v.z, c2); c3 = fmaf(p, v.w, c3);
        }
        *(float4*)&op[w * 128 + lane * 4] = make_float4(c0, c1, c2, c3);
    }
}

// ---------- split-KV attention: combine + Wv projection ----------
__global__ __launch_bounds__(256, 4) void k_attnc(const float* __restrict__ Wv,
                                                  const float* __restrict__ bv) {
    __shared__ float ctx_s[1024];
    __shared__ float f_s[64];
    __shared__ float ginv_s[8];
    const int n = blockIdx.x, tid = threadIdx.x;
    const float* base = &sc_part[(size_t)(n * 8) * 1040];

    if (tid < 8) {
        int h = tid;
        float gmax = -1e30f;
#pragma unroll
        for (int p = 0; p < 8; ++p) gmax = fmaxf(gmax, base[(size_t)p * 1040 + 1024 + h]);
        float gsum = 0.f;
#pragma unroll
        for (int p = 0; p < 8; ++p) {
            float f = __expf(base[(size_t)p * 1040 + 1024 + h] - gmax);
            f_s[p * 8 + h] = f;
            gsum = fmaf(f, base[(size_t)p * 1040 + 1032 + h], gsum);
        }
        ginv_s[h] = 1.f / gsum;
    }
    __syncthreads();

    {
        int e0 = tid * 4, h = e0 >> 7;
        float a0 = 0.f, a1 = 0.f, a2 = 0.f, a3 = 0.f;
#pragma unroll
        for (int p = 0; p < 8; ++p) {
            float f = f_s[p * 8 + h];
            float4 v = *(const float4*)&base[(size_t)p * 1040 + e0];
            a0 = fmaf(f, v.x, a0); a1 = fmaf(f, v.y, a1);
            a2 = fmaf(f, v.z, a2); a3 = fmaf(f, v.w, a3);
        }
        float inv = ginv_s[h];
        ctx_s[e0] = a0 * inv; ctx_s[e0 + 1] = a1 * inv;
        ctx_s[e0 + 2] = a2 * inv; ctx_s[e0 + 3] = a3 * inv;
    }
    __syncthreads();

    if (tid < 128) {
        int h = tid >> 4;
        float acc = bv[tid];
#pragma unroll 8
        for (int cc = 0; cc < 128; ++cc)
            acc = fmaf(ctx_s[h * 128 + cc], Wv[cc * Dd + tid], acc);
        sc_o[n * Dd + tid] = acc;
    }
}

// ---------- final: out-proj + LN + FFN + LN ----------
__device__ __forceinline__ float bsum128(float v, float* tmp) {
    int lane = threadIdx.x & 31, wid = threadIdx.x >> 5;
#pragma unroll
    for (int off = 16; off >= 1; off >>= 1) v += __shfl_xor_sync(0xffffffffu, v, off);
    if (lane == 0) tmp[wid] = v;
    __syncthreads();
    float s = tmp[0] + tmp[1] + tmp[2] + tmp[3];
    __syncthreads();
    return s;
}
__global__ void k_final(const float* __restrict__ node,
                        const float* __restrict__ Wo, const float* __restrict__ bo,
                        const float* __restrict__ g2, const float* __restrict__ be2,
                        const float* __restrict__ W1, const float* __restrict__ b1,
                        const float* __restrict__ W2, const float* __restrict__ b2,
                        const float* __restrict__ g3, const float* __restrict__ be3,
                        float* __restrict__ out_x) {
    const int n = blockIdx.x;
    const int c = threadIdx.x;
    __shared__ float os[Dd], xs[Dd], hs[Df], tmp[4];
    os[c] = sc_o[n * Dd + c];
    __syncthreads();
    float t = bo[c];
#pragma unroll 8
    for (int k = 0; k < Dd; ++k) t = fmaf(os[k], Wo[k * Dd + c], t);
    float x = node[n * Dd + c] + t;
    float mean = bsum128(x, tmp) * (1.f / 128.f);
    float d = x - mean;
    float var = bsum128(d * d, tmp) * (1.f / 128.f);
    float xn = d * rsqrtf(var + 1e-5f) * g2[c] + be2[c];
    xs[c] = xn;
    __syncthreads();
    float h0 = b1[c], h1 = b1[c + 128];
#pragma unroll 8
    for (int k = 0; k < Dd; ++k) {
        float xv = xs[k];
        h0 = fmaf(xv, W1[k * Df + c], h0);
        h1 = fmaf(xv, W1[k * Df + c + 128], h1);
    }
    hs[c] = fmaxf(h0, 0.f);
    hs[c + 128] = fmaxf(h1, 0.f);
    __syncthreads();
    float y = b2[c];
#pragma unroll 8
    for (int f = 0; f < Df; ++f) y = fmaf(hs[f], W2[f * Dd + c], y);
    float z = xn + y;
    mean = bsum128(z, tmp) * (1.f / 128.f);
    d = z - mean;
    var = bsum128(d * d, tmp) * (1.f / 128.f);
    out_x[n * Dd + c] = d * rsqrtf(var + 1e-5f) * g3[c] + be3[c];
}

// ---------- host ----------
extern "C" void kernel_launch(void* const* d_in, const int* in_sizes, int n_in,
                              void* d_out, int out_size) {
    const float* node = (const float*)d_in[0];
    const float* edge = (const float*)d_in[1];
    const unsigned char* mask = (const unsigned char*)d_in[2];
    const float* W_mem = (const float*)d_in[3];
    const float* b_mem = (const float*)d_in[4];
    const float* g_mem = (const float*)d_in[5];
    const float* be_mem = (const float*)d_in[6];
    const float* W_e = (const float*)d_in[7];
    const float* b_e = (const float*)d_in[8];
    const float* g_e1 = (const float*)d_in[9];
    const float* be_e1 = (const float*)d_in[10];
    const float* g_e2 = (const float*)d_in[11];
    const float* be_e2 = (const float*)d_in[12];
    const float* Wq = (const float*)d_in[13];
    const float* bq = (const float*)d_in[14];
    const float* Wk = (const float*)d_in[15];
    const float* bk = (const float*)d_in[16]; (void)bk;   // cancels in softmax
    const float* Wv = (const float*)d_in[17];
    const float* bv = (const float*)d_in[18];
    const float* Wo = (const float*)d_in[19];
    const float* bo = (const float*)d_in[20];
    const float* W1 = (const float*)d_in[21];
    const float* b1 = (const float*)d_in[22];
    const float* W2 = (const float*)d_in[23];
    const float* b2 = (const float*)d_in[24];
    const float* g2 = (const float*)d_in[25];
    const float* be2 = (const float*)d_in[26];
    const float* g3 = (const float*)d_in[27];
    const float* be3 = (const float*)d_in[28];

    float* out = (float*)d_out;
    float* out_x = out;
    float* out_edge = out + Nn * Dd;

    static int init = 0;
    if (!init) {
        cudaFuncSetAttribute(k_prep, cudaFuncAttributeMaxDynamicSharedMemorySize, 128 * 129 * 4);
        cudaFuncSetAttribute(k_fused, cudaFuncAttributeMaxDynamicSharedMemorySize, DYN);
        init = 1;
    }

    k_prep<<<2, 256, 128 * 129 * 4>>>(W_mem, W_e);
    k_small<<<Nn, Dd>>>(node, W_mem, Wq, bq, Wk);
    k_fused<<<NT, 256, DYN>>>(edge, b_mem, g_mem, be_mem,
                              b_e, g_e1, be_e1, g_e2, be_e2, out_edge);
    k_attnp<<<4096, 256>>>(mask);
    k_attnc<<<Nn, 256>>>(Wv, bv);
    k_final<<<Nn, 128>>>(node, Wo, bo, g2, be2, W1, b1, W2, b2, g3, be3, out_x);
}

// round 15
// speedup vs baseline: 2.9866x; 1.0361x over previous
#include <cuda_runtime.h>
#include <math.h>
#include <stdint.h>

#define Nn 512
#define Dd 128
#define Df 256
#define Hh 8
#define ROWS (Nn*Nn)
#define NT 4096                   // 64-row tiles

__device__ float sc_S[Nn * Dd];
__device__ float sc_T[Nn * Dd];
__device__ float sc_qk[Nn * Hh * Dd];        // 0.25 * Wk^T q  per (n, h)
__device__ float sc_o[Nn * Dd];
__device__ float wfrag[2][16384];            // Wm_edge, We tf32 frag layout
__device__ float sc_memf[(size_t)ROWS * Dd]; // memory f32 [n][m][c] (134MB)
__device__ float sc_part[(size_t)4096 * 1040]; // split-KV partials (17MB)

// k_fused dynamic smem float offsets
#define O_A  0                    // 8192
#define O_RS 8192                 // 256
#define O_RQ 8448                 // 256
#define O_P  8704                 // 128 (bm + T)
#define O_G  8832                 // 7*128
#define SMF  9728
#define DYN  (SMF * 4)            // 38912 B -> 3 CTA/SM

#define G_GM  (O_G + 0)
#define G_BEM (O_G + 128)
#define G_G1  (O_G + 256)
#define G_BE1 (O_G + 384)
#define G_G2  (O_G + 512)
#define G_BE2 (O_G + 640)
#define G_BEB (O_G + 768)

__device__ __forceinline__ uint32_t tf32c(float x) {
    uint32_t y; asm("cvt.rna.tf32.f32 %0, %1;" : "=r"(y) : "f"(x)); return y;
}
__device__ __forceinline__ float tf32f(float x) { return __uint_as_float(tf32c(x)); }

__device__ __forceinline__ uint32_t smem_u32(const void* p) {
    uint32_t a;
    asm("{ .reg .u64 t; cvta.to.shared.u64 t, %1; cvt.u32.u64 %0, t; }" : "=r"(a) : "l"(p));
    return a;
}
__device__ __forceinline__ void cpa16(uint32_t s, const void* g) {
    asm volatile("cp.async.cg.shared.global [%0], [%1], 16;" :: "r"(s), "l"(g));
}
#define CPC() asm volatile("cp.async.commit_group;" ::: "memory")
#define CPW(n) asm volatile("cp.async.wait_group %0;" :: "n"(n) : "memory")

__device__ __forceinline__ void mma8(float* c, const uint32_t* a, const uint32_t* b) {
    asm volatile(
        "mma.sync.aligned.m16n8k8.row.col.f32.tf32.tf32.f32 "
        "{%0,%1,%2,%3},{%4,%5,%6,%7},{%8,%9},{%0,%1,%2,%3};"
        : "+f"(c[0]), "+f"(c[1]), "+f"(c[2]), "+f"(c[3])
        : "r"(a[0]), "r"(a[1]), "r"(a[2]), "r"(a[3]), "r"(b[0]), "r"(b[1]));
}

// A-fragment float index, plane-split layout [frag][reg(4)][qx(32)]
__device__ __forceinline__ int AFR2(int r, int c) {
    int kb = c >> 3;
    int frag = (r >> 4) * 16 + kb;
    int reg = ((r >> 3) & 1) + (((c >> 2) & 1) << 1);
    int qx = ((((r & 7) << 2) + (c & 3)) ^ ((kb & 7) << 2));
    return frag * 128 + reg * 32 + qx;
}

// 64x128x128 tile MMA: 8 warps 2(m) x 4(n), warp tile 32x32.
__device__ __forceinline__ void mma_tile(const float* sA, const float* __restrict__ gB,
                                         float c[2][4][4]) {
    int tid = threadIdx.x, w = tid >> 5, lane = tid & 31;
    int wm = w >> 2, wn = w & 3;
#pragma unroll
    for (int mt = 0; mt < 2; ++mt)
#pragma unroll
        for (int nt = 0; nt < 4; ++nt)
#pragma unroll
            for (int i = 0; i < 4; ++i) c[mt][nt][i] = 0.f;
#pragma unroll
    for (int kc = 0; kc < 16; ++kc) {
        int sw = (kc & 7) << 2;
        uint32_t a[2][4];
#pragma unroll
        for (int mt = 0; mt < 2; ++mt) {
            int base = ((wm * 2 + mt) * 16 + kc) * 128 + (lane ^ sw);
            a[mt][0] = __float_as_uint(sA[base]);
            a[mt][1] = __float_as_uint(sA[base + 32]);
            a[mt][2] = __float_as_uint(sA[base + 64]);
            a[mt][3] = __float_as_uint(sA[base + 96]);
        }
#pragma unroll
        for (int nt = 0; nt < 4; ++nt) {
            float2 bv = __ldg((const float2*)&gB[(((wn * 4 + nt) * 16 + kc) * 32 + lane) * 2]);
            uint32_t b[2] = {__float_as_uint(bv.x), __float_as_uint(bv.y)};
            mma8(c[0][nt], a[0], b);
            mma8(c[1][nt], a[1], b);
        }
    }
}

#define ROWSTATS(sv, qv, mean, rstd) do { \
    _Pragma("unroll") for (int _mt = 0; _mt < 2; ++_mt) \
    _Pragma("unroll") for (int _h = 0; _h < 2; ++_h) { \
        float _s = (sv)[_mt][_h], _q = (qv)[_mt][_h]; \
        _s += __shfl_xor_sync(0xffffffffu, _s, 1); _q += __shfl_xor_sync(0xffffffffu, _q, 1); \
        _s += __shfl_xor_sync(0xffffffffu, _s, 2); _q += __shfl_xor_sync(0xffffffffu, _q, 2); \
        (sv)[_mt][_h] = _s; (qv)[_mt][_h] = _q; } \
    if ((lane & 3) == 0) { \
        _Pragma("unroll") for (int _mt = 0; _mt < 2; ++_mt) \
        _Pragma("unroll") for (int _h = 0; _h < 2; ++_h) { \
            int _row = wm * 32 + _mt * 16 + g + _h * 8; \
            sm[O_RS + _row * 4 + wn] = (sv)[_mt][_h]; \
            sm[O_RQ + _row * 4 + wn] = (qv)[_mt][_h]; } } \
    __syncthreads(); \
    _Pragma("unroll") for (int _mt = 0; _mt < 2; ++_mt) \
    _Pragma("unroll") for (int _h = 0; _h < 2; ++_h) { \
        int _row = wm * 32 + _mt * 16 + g + _h * 8; \
        float _ts = sm[O_RS + _row * 4] + sm[O_RS + _row * 4 + 1] + sm[O_RS + _row * 4 + 2] + sm[O_RS + _row * 4 + 3]; \
        float _tq = sm[O_RQ + _row * 4] + sm[O_RQ + _row * 4 + 1] + sm[O_RQ + _row * 4 + 2] + sm[O_RQ + _row * 4 + 3]; \
        float _mn = _ts * (1.f / 128.f); \
        (mean)[_mt][_h] = _mn; \
        (rstd)[_mt][_h] = rsqrtf(fmaxf(_tq * (1.f / 128.f) - _mn * _mn, 0.f) + 1e-5f); } \
    __syncthreads(); \
} while (0)

// ---------- weight prep (Wm, We) ----------
__global__ void k_prep(const float* __restrict__ Wm, const float* __restrict__ We) {
    extern __shared__ float ws[];   // [128][129]
    const float* W = blockIdx.x == 0 ? Wm : We;
    int tid = threadIdx.x;
    for (int t = 0; t < 16; ++t) {
        int id = tid + t * 256;
        int k = id >> 5, n4 = (id & 31) << 2;
        float4 v = *(const float4*)&W[k * Dd + n4];
        ws[k * 129 + n4] = v.x; ws[k * 129 + n4 + 1] = v.y;
        ws[k * 129 + n4 + 2] = v.z; ws[k * 129 + n4 + 3] = v.w;
    }
    __syncthreads();
    float* out = wfrag[blockIdx.x];
    for (int t = 0; t < 32; ++t) {
        int id = tid + t * 256;
        int lane = id & 31, kb = (id >> 5) & 15, nb = id >> 9;
        int n = nb * 8 + (lane >> 2), k = kb * 8 + (lane & 3);
        float2 o;
        o.x = tf32f(ws[k * 129 + n]);
        o.y = tf32f(ws[(k + 4) * 129 + n]);
        *(float2*)&out[id * 2] = o;
    }
}

// ---------- S, T, qk ----------
__global__ void k_small(const float* __restrict__ node, const float* __restrict__ Wmem,
                        const float* __restrict__ Wq, const float* __restrict__ bq,
                        const float* __restrict__ Wk) {
    int n = blockIdx.x, c = threadIdx.x;
    __shared__ float ns[Dd], qs[Dd];
    ns[c] = node[n * Dd + c];
    __syncthreads();
    float s = 0.f, t = 0.f, q = 0.f;
#pragma unroll 8
    for (int k = 0; k < Dd; ++k) {
        float nv = ns[k];
        s = fmaf(nv, Wmem[(Dd + k) * Dd + c], s);
        t = fmaf(nv, Wmem[(2 * Dd + k) * Dd + c], t);
        q = fmaf(nv, Wq[k * Dd + c], q);
    }
    sc_S[n * Dd + c] = s; sc_T[n * Dd + c] = t;
    qs[c] = q + bq[c];
    __syncthreads();
    float a[8] = {0,0,0,0,0,0,0,0};
#pragma unroll
    for (int hd = 0; hd < 128; ++hd)
        a[hd >> 4] = fmaf(Wk[c * Dd + hd], qs[hd], a[hd >> 4]);
#pragma unroll
    for (int h = 0; h < 8; ++h)
        sc_qk[n * 1024 + h * 128 + c] = a[h] * 0.25f;
}

// ---------- fused tile kernel: memory (f32 out) + edge_out ----------
__global__ __launch_bounds__(256, 3) void k_fused(
    const float* __restrict__ edge,
    const float* __restrict__ bm, const float* __restrict__ gm, const float* __restrict__ bem,
    const float* __restrict__ beb, const float* __restrict__ g1, const float* __restrict__ be1,
    const float* __restrict__ g2, const float* __restrict__ be2,
    float* __restrict__ oe)
{
    extern __shared__ float sm[];
    const int tid = threadIdx.x, w = tid >> 5, lane = tid & 31;
    const int wm = w >> 2, wn = w & 3, g = lane >> 2, t2 = (lane & 3) << 1;
    const int ib = blockIdx.x >> 3, jn0 = (blockIdx.x & 7) << 6;
    const size_t r0 = (size_t)blockIdx.x * 64;

    // A <- edge (tf32 frags, plane-split layout, vector stores)
#pragma unroll
    for (int t = 0; t < 8; ++t) {
        int id = tid + t * 256;
        int r = id >> 5, c4 = (id & 31) << 2;
        float4 v = *(const float4*)&edge[(r0 + r) * Dd + c4];
        float4 o;
        o.x = tf32f(v.x); o.y = tf32f(v.y); o.z = tf32f(v.z); o.w = tf32f(v.w);
        *(float4*)&sm[O_A + AFR2(r, c4)] = o;
    }
    if (tid < Dd) {
        sm[O_P + tid]  = bm[tid] + sc_T[ib * Dd + tid];
        sm[G_GM + tid] = gm[tid];  sm[G_BEM + tid] = bem[tid];
        sm[G_G1 + tid] = g1[tid];  sm[G_BE1 + tid] = be1[tid];
        sm[G_G2 + tid] = g2[tid];  sm[G_BE2 + tid] = be2[tid];
        sm[G_BEB + tid] = beb[tid];
    }
    __syncthreads();

    float c[2][4][4];
    mma_tile(sm + O_A, wfrag[0], c);        // memory GEMM
    __syncthreads();

    // epilogue1: memory = relu(LN(c + (bm+T) + S)), rewrite A-frags (tf32)
    {
        float sv[2][2] = {{0,0},{0,0}}, qv[2][2] = {{0,0},{0,0}};
#pragma unroll
        for (int mt = 0; mt < 2; ++mt) {
            int rA = wm * 32 + mt * 16 + g;
#pragma unroll
            for (int nt = 0; nt < 4; ++nt) {
                int col = wn * 32 + nt * 8 + t2;
                float p0 = sm[O_P + col], p1 = sm[O_P + col + 1];
                float2 s0 = *(const float2*)&sc_S[(jn0 + rA) * Dd + col];
                float2 s1 = *(const float2*)&sc_S[(jn0 + rA + 8) * Dd + col];
                c[mt][nt][0] += p0 + s0.x; c[mt][nt][1] += p1 + s0.y;
                c[mt][nt][2] += p0 + s1.x; c[mt][nt][3] += p1 + s1.y;
                sv[mt][0] += c[mt][nt][0] + c[mt][nt][1];
                qv[mt][0] += c[mt][nt][0]*c[mt][nt][0] + c[mt][nt][1]*c[mt][nt][1];
                sv[mt][1] += c[mt][nt][2] + c[mt][nt][3];
                qv[mt][1] += c[mt][nt][2]*c[mt][nt][2] + c[mt][nt][3]*c[mt][nt][3];
            }
        }
        float mean[2][2], rstd[2][2];
        ROWSTATS(sv, qv, mean, rstd);
#pragma unroll
        for (int mt = 0; mt < 2; ++mt) {
            int rA = wm * 32 + mt * 16 + g;
#pragma unroll
            for (int nt = 0; nt < 4; ++nt) {
                int col = wn * 32 + nt * 8 + t2;
                float ga0 = sm[G_GM + col], ga1 = sm[G_GM + col + 1];
                float bb0 = sm[G_BEM + col], bb1 = sm[G_BEM + col + 1];
                *(float2*)&sm[O_A + AFR2(rA, col)] = make_float2(
                    tf32f(fmaxf((c[mt][nt][0]-mean[mt][0])*rstd[mt][0]*ga0+bb0, 0.f)),
                    tf32f(fmaxf((c[mt][nt][1]-mean[mt][0])*rstd[mt][0]*ga1+bb1, 0.f)));
                *(float2*)&sm[O_A + AFR2(rA + 8, col)] = make_float2(
                    tf32f(fmaxf((c[mt][nt][2]-mean[mt][1])*rstd[mt][1]*ga0+bb0, 0.f)),
                    tf32f(fmaxf((c[mt][nt][3]-mean[mt][1])*rstd[mt][1]*ga1+bb1, 0.f)));
            }
        }
    }
    __syncthreads();

    mma_tile(sm + O_A, wfrag[1], c);        // edge GEMM

    // write memory f32 [jn][ib][c], coalesced float4
#pragma unroll
    for (int t = 0; t < 8; ++t) {
        int id4 = tid + t * 256;
        int r = id4 >> 5, c4 = (id4 & 31) << 2;
        float4 o = *(const float4*)&sm[O_A + AFR2(r, c4)];
        *(float4*)&sc_memf[((size_t)(jn0 + r) * Nn + ib) * Dd + c4] = o;
    }

    // epilogue2: out_edge = LN2(edge + relu(LN1(c + beb)))
    {
        float sv[2][2] = {{0,0},{0,0}}, qv[2][2] = {{0,0},{0,0}};
#pragma unroll
        for (int mt = 0; mt < 2; ++mt)
#pragma unroll
            for (int nt = 0; nt < 4; ++nt) {
                int col = wn * 32 + nt * 8 + t2;
                float b0 = sm[G_BEB + col], b1 = sm[G_BEB + col + 1];
                c[mt][nt][0] += b0; c[mt][nt][1] += b1;
                c[mt][nt][2] += b0; c[mt][nt][3] += b1;
                sv[mt][0] += c[mt][nt][0] + c[mt][nt][1];
                qv[mt][0] += c[mt][nt][0]*c[mt][nt][0] + c[mt][nt][1]*c[mt][nt][1];
                sv[mt][1] += c[mt][nt][2] + c[mt][nt][3];
                qv[mt][1] += c[mt][nt][2]*c[mt][nt][2] + c[mt][nt][3]*c[mt][nt][3];
            }
        float mean[2][2], rstd[2][2];
        ROWSTATS(sv, qv, mean, rstd);
        float sv2[2][2] = {{0,0},{0,0}}, qv2[2][2] = {{0,0},{0,0}};
#pragma unroll
        for (int mt = 0; mt < 2; ++mt) {
            int rA = wm * 32 + mt * 16 + g;
#pragma unroll
            for (int nt = 0; nt < 4; ++nt) {
                int col = wn * 32 + nt * 8 + t2;
                float ga0 = sm[G_G1 + col], ga1 = sm[G_G1 + col + 1];
                float bb0 = sm[G_BE1 + col], bb1 = sm[G_BE1 + col + 1];
                float2 e0 = *(const float2*)&edge[(r0 + rA) * Dd + col];
                float2 e1 = *(const float2*)&edge[(r0 + rA + 8) * Dd + col];
                float w00 = fmaxf((c[mt][nt][0]-mean[mt][0])*rstd[mt][0]*ga0+bb0, 0.f) + e0.x;
                float w01 = fmaxf((c[mt][nt][1]-mean[mt][0])*rstd[mt][0]*ga1+bb1, 0.f) + e0.y;
                float w10 = fmaxf((c[mt][nt][2]-mean[mt][1])*rstd[mt][1]*ga0+bb0, 0.f) + e1.x;
                float w11 = fmaxf((c[mt][nt][3]-mean[mt][1])*rstd[mt][1]*ga1+bb1, 0.f) + e1.y;
                c[mt][nt][0] = w00; c[mt][nt][1] = w01; c[mt][nt][2] = w10; c[mt][nt][3] = w11;
                sv2[mt][0] += w00 + w01; qv2[mt][0] += w00*w00 + w01*w01;
                sv2[mt][1] += w10 + w11; qv2[mt][1] += w10*w10 + w11*w11;
            }
        }
        ROWSTATS(sv2, qv2, mean, rstd);
#pragma unroll
        for (int mt = 0; mt < 2; ++mt) {
            int rA = wm * 32 + mt * 16 + g;
#pragma unroll
            for (int nt = 0; nt < 4; ++nt) {
                int col = wn * 32 + nt * 8 + t2;
                float ga0 = sm[G_G2 + col], ga1 = sm[G_G2 + col + 1];
                float bb0 = sm[G_BE2 + col], bb1 = sm[G_BE2 + col + 1];
                *(float2*)&oe[(r0 + rA) * Dd + col] =
                    make_float2((c[mt][nt][0]-mean[mt][0])*rstd[mt][0]*ga0+bb0,
                                (c[mt][nt][1]-mean[mt][0])*rstd[mt][0]*ga1+bb1);
                *(float2*)&oe[(r0 + rA + 8) * Dd + col] =
                    make_float2((c[mt][nt][2]-mean[mt][1])*rstd[mt][1]*ga0+bb0,
                                (c[mt][nt][3]-mean[mt][1])*rstd[mt][1]*ga1+bb1);
            }
        }
    }
}

// ---------- split-KV attention: partial kernel (one 64-key chunk per block) ----------
// ctx phase remapped: warp = (head-pair, m-half) so each buf read feeds 2 heads.
__global__ __launch_bounds__(256, 4) void k_attnp(const unsigned char* __restrict__ mask) {
    __shared__ float qk_s[1024];     // reused as ctx partials after scores
    __shared__ float buf[64 * 132];
    __shared__ float scs[512], ps[512];
    const int bid = blockIdx.x, n = bid >> 3, part = bid & 7;
    const int tid = threadIdx.x, w = tid >> 5, lane = tid & 31;
    const uint32_t sbuf = smem_u32(buf);

    for (int i = tid; i < 1024; i += 256) qk_s[i] = sc_qk[n * 1024 + i];

    const float* src = sc_memf + ((size_t)n * Nn + part * 64) * Dd;
#pragma unroll
    for (int t = 0; t < 8; ++t) {
        int id4 = tid + t * 256;
        int m = id4 >> 5, j = id4 & 31;
        cpa16(sbuf + ((m * 132 + j * 4) << 2), src + (size_t)id4 * 4);
    }
    CPC(); CPW(0);
    __syncthreads();

    // scores: thread -> (m = sm_, heads h0, h0+1)
    {
        const int sm_ = tid & 63, h0 = (tid >> 6) << 1;
        float a0 = 0.f, a1 = 0.f;
        const float* mr = &buf[sm_ * 132];
        const float* qa = &qk_s[h0 * 128];
        const float* qb = &qk_s[(h0 + 1) * 128];
#pragma unroll 8
        for (int j = 0; j < 32; ++j) {
            float4 m4 = *(const float4*)&mr[j * 4];
            float4 a4 = *(const float4*)&qa[j * 4];
            float4 b4 = *(const float4*)&qb[j * 4];
            a0 += m4.x*a4.x + m4.y*a4.y + m4.z*a4.z + m4.w*a4.w;
            a1 += m4.x*b4.x + m4.y*b4.y + m4.z*b4.z + m4.w*b4.w;
        }
        bool mk = mask[n * Nn + part * 64 + sm_] != 0;
        scs[h0 * 64 + sm_]       = mk ? -1e30f : a0;
        scs[(h0 + 1) * 64 + sm_] = mk ? -1e30f : a1;
    }
    __syncthreads();

    float* op = &sc_part[(size_t)bid * 1040];
    // local softmax: warp w = head w (single chunk, no online rescale)
    {
        float s0v = scs[w * 64 + lane], s1v = scs[w * 64 + lane + 32];
        float mx = fmaxf(s0v, s1v);
#pragma unroll
        for (int off = 16; off >= 1; off >>= 1)
            mx = fmaxf(mx, __shfl_xor_sync(0xffffffffu, mx, off));
        float p0 = __expf(s0v - mx), p1 = __expf(s1v - mx);
        ps[w * 64 + lane] = p0; ps[w * 64 + lane + 32] = p1;
        float cs = p0 + p1;
#pragma unroll
        for (int off = 16; off >= 1; off >>= 1)
            cs += __shfl_xor_sync(0xffffffffu, cs, off);
        if (lane == 0) { op[1024 + w] = mx; op[1032 + w] = cs; }
    }
    __syncthreads();

    // unnormalized ctx: warp = (hp = w&3 -> heads 2hp,2hp+1; mh = w>>2 -> m-half)
    // lane = column quad q. Each buf float4 feeds BOTH heads (8 FMA / 16B read).
    {
        const int hp = w & 3, mh = w >> 2;
        float a00 = 0.f, a01 = 0.f, a02 = 0.f, a03 = 0.f;
        float a10 = 0.f, a11 = 0.f, a12 = 0.f, a13 = 0.f;
        const float* pp0 = &ps[(2 * hp) * 64 + mh * 32];
        const float* pp1 = &ps[(2 * hp + 1) * 64 + mh * 32];
        const float* bp = &buf[mh * 32 * 132 + lane * 4];
#pragma unroll 8
        for (int m = 0; m < 32; ++m) {
            float p0 = pp0[m], p1 = pp1[m];
            float4 v = *(const float4*)&bp[m * 132];
            a00 = fmaf(p0, v.x, a00); a01 = fmaf(p0, v.y, a01);
            a02 = fmaf(p0, v.z, a02); a03 = fmaf(p0, v.w, a03);
            a10 = fmaf(p1, v.x, a10); a11 = fmaf(p1, v.y, a11);
            a12 = fmaf(p1, v.z, a12); a13 = fmaf(p1, v.w, a13);
        }
        __syncthreads();   // qk_s dead; safe to reuse as partial store
        if (mh == 1) {
            float* pt = &qk_s[hp * 256 + lane * 8];
            *(float4*)&pt[0] = make_float4(a00, a01, a02, a03);
            *(float4*)&pt[4] = make_float4(a10, a11, a12, a13);
        }
        __syncthreads();
        if (mh == 0) {
            const float* pt = &qk_s[hp * 256 + lane * 8];
            float4 b0 = *(const float4*)&pt[0];
            float4 b1 = *(const float4*)&pt[4];
            *(float4*)&op[(2 * hp) * 128 + lane * 4] =
                make_float4(a00 + b0.x, a01 + b0.y, a02 + b0.z, a03 + b0.w);
            *(float4*)&op[(2 * hp + 1) * 128 + lane * 4] =
                make_float4(a10 + b1.x, a11 + b1.y, a12 + b1.z, a13 + b1.w);
        }
    }
}

// ---------- split-KV attention: combine + Wv projection ----------
__global__ __launch_bounds__(256, 4) void k_attnc(const float* __restrict__ Wv,
                                                  const float* __restrict__ bv) {
    __shared__ float ctx_s[1024];
    __shared__ float f_s[64];
    __shared__ float ginv_s[8];
    const int n = blockIdx.x, tid = threadIdx.x;
    const float* base = &sc_part[(size_t)(n * 8) * 1040];

    if (tid < 8) {
        int h = tid;
        float gmax = -1e30f;
#pragma unroll
        for (int p = 0; p < 8; ++p) gmax = fmaxf(gmax, base[(size_t)p * 1040 + 1024 + h]);
        float gsum = 0.f;
#pragma unroll
        for (int p = 0; p < 8; ++p) {
            float f = __expf(base[(size_t)p * 1040 + 1024 + h] - gmax);
            f_s[p * 8 + h] = f;
            gsum = fmaf(f, base[(size_t)p * 1040 + 1032 + h], gsum);
        }
        ginv_s[h] = 1.f / gsum;
    }
    __syncthreads();

    {
        int e0 = tid * 4, h = e0 >> 7;
        float a0 = 0.f, a1 = 0.f, a2 = 0.f, a3 = 0.f;
#pragma unroll
        for (int p = 0; p < 8; ++p) {
            float f = f_s[p * 8 + h];
            float4 v = *(const float4*)&base[(size_t)p * 1040 + e0];
            a0 = fmaf(f, v.x, a0); a1 = fmaf(f, v.y, a1);
            a2 = fmaf(f, v.z, a2); a3 = fmaf(f, v.w, a3);
        }
        float inv = ginv_s[h];
        ctx_s[e0] = a0 * inv; ctx_s[e0 + 1] = a1 * inv;
        ctx_s[e0 + 2] = a2 * inv; ctx_s[e0 + 3] = a3 * inv;
    }
    __syncthreads();

    if (tid < 128) {
        int h = tid >> 4;
        float acc = bv[tid];
#pragma unroll 8
        for (int cc = 0; cc < 128; ++cc)
            acc = fmaf(ctx_s[h * 128 + cc], Wv[cc * Dd + tid], acc);
        sc_o[n * Dd + tid] = acc;
    }
}

// ---------- final: out-proj + LN + FFN + LN ----------
__device__ __forceinline__ float bsum128(float v, float* tmp) {
    int lane = threadIdx.x & 31, wid = threadIdx.x >> 5;
#pragma unroll
    for (int off = 16; off >= 1; off >>= 1) v += __shfl_xor_sync(0xffffffffu, v, off);
    if (lane == 0) tmp[wid] = v;
    __syncthreads();
    float s = tmp[0] + tmp[1] + tmp[2] + tmp[3];
    __syncthreads();
    return s;
}
__global__ void k_final(const float* __restrict__ node,
                        const float* __restrict__ Wo, const float* __restrict__ bo,
                        const float* __restrict__ g2, const float* __restrict__ be2,
                        const float* __restrict__ W1, const float* __restrict__ b1,
                        const float* __restrict__ W2, const float* __restrict__ b2,
                        const float* __restrict__ g3, const float* __restrict__ be3,
                        float* __restrict__ out_x) {
    const int n = blockIdx.x;
    const int c = threadIdx.x;
    __shared__ float os[Dd], xs[Dd], hs[Df], tmp[4];
    os[c] = sc_o[n * Dd + c];
    __syncthreads();
    float t = bo[c];
#pragma unroll 8
    for (int k = 0; k < Dd; ++k) t = fmaf(os[k], Wo[k * Dd + c], t);
    float x = node[n * Dd + c] + t;
    float mean = bsum128(x, tmp) * (1.f / 128.f);
    float d = x - mean;
    float var = bsum128(d * d, tmp) * (1.f / 128.f);
    float xn = d * rsqrtf(var + 1e-5f) * g2[c] + be2[c];
    xs[c] = xn;
    __syncthreads();
    float h0 = b1[c], h1 = b1[c + 128];
#pragma unroll 8
    for (int k = 0; k < Dd; ++k) {
        float xv = xs[k];
        h0 = fmaf(xv, W1[k * Df + c], h0);
        h1 = fmaf(xv, W1[k * Df + c + 128], h1);
    }
    hs[c] = fmaxf(h0, 0.f);
    hs[c + 128] = fmaxf(h1, 0.f);
    __syncthreads();
    float y = b2[c];
#pragma unroll 8
    for (int f = 0; f < Df; ++f) y = fmaf(hs[f], W2[f * Dd + c], y);
    float z = xn + y;
    mean = bsum128(z, tmp) * (1.f / 128.f);
    d = z - mean;
    var = bsum128(d * d, tmp) * (1.f / 128.f);
    out_x[n * Dd + c] = d * rsqrtf(var + 1e-5f) * g3[c] + be3[c];
}

// ---------- host ----------
extern "C" void kernel_launch(void* const* d_in, const int* in_sizes, int n_in,
                              void* d_out, int out_size) {
    const float* node = (const float*)d_in[0];
    const float* edge = (const float*)d_in[1];
    const unsigned char* mask = (const unsigned char*)d_in[2];
    const float* W_mem = (const float*)d_in[3];
    const float* b_mem = (const float*)d_in[4];
    const float* g_mem = (const float*)d_in[5];
    const float* be_mem = (const float*)d_in[6];
    const float* W_e = (const float*)d_in[7];
    const float* b_e = (const float*)d_in[8];
    const float* g_e1 = (const float*)d_in[9];
    const float* be_e1 = (const float*)d_in[10];
    const float* g_e2 = (const float*)d_in[11];
    const float* be_e2 = (const float*)d_in[12];
    const float* Wq = (const float*)d_in[13];
    const float* bq = (const float*)d_in[14];
    const float* Wk = (const float*)d_in[15];
    const float* bk = (const float*)d_in[16]; (void)bk;   // cancels in softmax
    const float* Wv = (const float*)d_in[17];
    const float* bv = (const float*)d_in[18];
    const float* Wo = (const float*)d_in[19];
    const float* bo = (const float*)d_in[20];
    const float* W1 = (const float*)d_in[21];
    const float* b1 = (const float*)d_in[22];
    const float* W2 = (const float*)d_in[23];
    const float* b2 = (const float*)d_in[24];
    const float* g2 = (const float*)d_in[25];
    const float* be2 = (const float*)d_in[26];
    const float* g3 = (const float*)d_in[27];
    const float* be3 = (const float*)d_in[28];

    float* out = (float*)d_out;
    float* out_x = out;
    float* out_edge = out + Nn * Dd;

    static int init = 0;
    if (!init) {
        cudaFuncSetAttribute(k_prep, cudaFuncAttributeMaxDynamicSharedMemorySize, 128 * 129 * 4);
        cudaFuncSetAttribute(k_fused, cudaFuncAttributeMaxDynamicSharedMemorySize, DYN);
        init = 1;
    }

    k_prep<<<2, 256, 128 * 129 * 4>>>(W_mem, W_e);
    k_small<<<Nn, Dd>>>(node, W_mem, Wq, bq, Wk);
    k_fused<<<NT, 256, DYN>>>(edge, b_mem, g_mem, be_mem,
                              b_e, g_e1, be_e1, g_e2, be_e2, out_edge);
    k_attnp<<<4096, 256>>>(mask);
    k_attnc<<<Nn, 256>>>(Wv, bv);
    k_final<<<Nn, 128>>>(node, Wo, bo, g2, be2, W1, b1, W2, b2, g3, be3, out_x);
}